// round 5
// baseline (speedup 1.0000x reference)
#include <cuda_runtime.h>

#define N_NODES 2048
#define F 256
#define H 8
#define DK 32
#define ALPHA 0.2f
#define LN_EPS 1e-5f

typedef unsigned long long ull;

// ---------------- scratch (no allocations allowed) ----------------
__device__ float d_hbuf[N_NODES * F];
__device__ float d_Q[H * N_NODES * DK];
__device__ float d_K[H * N_NODES * DK];
__device__ float d_V[H * N_NODES * DK];
__device__ float2 d_V2[H * (N_NODES / 2) * DK];  // (v[2jp][d], v[2jp+1][d]) pairs
__device__ float d_bq[H * N_NODES];
__device__ float d_bk[H * N_NODES];
__device__ float d_af[H * DK];                   // a' = (1-a)*scale*log2e * a
__device__ unsigned d_adjb[N_NODES * (N_NODES / 32)];
__device__ float d_ao[N_NODES * F];

// ---------------- helpers ----------------
__device__ __forceinline__ float ex2f(float x) {
    float r; asm("ex2.approx.f32 %0, %1;" : "=f"(r) : "f"(x)); return r;
}
__device__ __forceinline__ ull pk2(float lo, float hi) {
    ull r; asm("mov.b64 %0, {%1, %2};" : "=l"(r) : "f"(lo), "f"(hi)); return r;
}
__device__ __forceinline__ void upk2(ull v, float& lo, float& hi) {
    asm("mov.b64 {%0, %1}, %2;" : "=f"(lo), "=f"(hi) : "l"(v));
}
__device__ __forceinline__ ull fma2v(ull a, ull b, ull c) {
    ull r;
    asm("fma.rn.f32x2 %0, %1, %2, %3;" : "=l"(r) : "l"(a), "l"(b), "l"(c));
    return r;
}
// acc += a2 * max(q2 + k2, 0)   (packed f32x2; relu per 32-bit half)
__device__ __forceinline__ void term2(ull q2, ull k2, ull a2, ull& acc) {
    asm("{\n\t"
        ".reg .b64 s64;\n\t"
        ".reg .f32 tlo, thi;\n\t"
        "add.rn.f32x2 s64, %1, %2;\n\t"
        "mov.b64 {tlo, thi}, s64;\n\t"
        "max.f32 tlo, tlo, 0f00000000;\n\t"
        "max.f32 thi, thi, 0f00000000;\n\t"
        "mov.b64 s64, {tlo, thi};\n\t"
        "fma.rn.f32x2 %0, %3, s64, %0;\n\t"
        "}\n"
        : "+l"(acc)
        : "l"(q2), "l"(k2), "l"(a2));
}

// ---------------- K1: pack adjacency into bitmask (4 words/warp) ----------------
__global__ void __launch_bounds__(256) pack_adj(const int* __restrict__ adj) {
    int t = blockIdx.x * 256 + threadIdx.x;
    int warp = t >> 5, lane = t & 31;
    int base = warp * 128;
    unsigned m0 = __ballot_sync(0xffffffffu, adj[base + lane] != 0);
    unsigned m1 = __ballot_sync(0xffffffffu, adj[base + 32 + lane] != 0);
    unsigned m2 = __ballot_sync(0xffffffffu, adj[base + 64 + lane] != 0);
    unsigned m3 = __ballot_sync(0xffffffffu, adj[base + 96 + lane] != 0);
    if (lane == 0) *(uint4*)&d_adjb[warp * 4] = make_uint4(m0, m1, m2, m3);
}

// ---------------- K2: LayerNorm ----------------
__global__ void __launch_bounds__(256) ln_kernel(const float* __restrict__ x,
                                                 const float* __restrict__ gamma,
                                                 const float* __restrict__ beta) {
    int row = blockIdx.x;
    int t = threadIdx.x;
    float v = x[row * F + t];
    float s = v, s2 = v * v;
    #pragma unroll
    for (int m = 16; m > 0; m >>= 1) {
        s  += __shfl_xor_sync(0xffffffffu, s, m);
        s2 += __shfl_xor_sync(0xffffffffu, s2, m);
    }
    __shared__ float ws[8], ws2[8];
    if ((t & 31) == 0) { ws[t >> 5] = s; ws2[t >> 5] = s2; }
    __syncthreads();
    float tot = 0.f, tot2 = 0.f;
    #pragma unroll
    for (int w = 0; w < 8; ++w) { tot += ws[w]; tot2 += ws2[w]; }
    float mu = tot * (1.0f / F);
    float var = tot2 * (1.0f / F) - mu * mu;
    float inv = rsqrtf(var + LN_EPS);
    d_hbuf[row * F + t] = (v - mu) * inv * gamma[t] + beta[t];
}

// ---------------- K3: QKV projection GEMM ----------------
__global__ void __launch_bounds__(256) qkv_gemm(const float* __restrict__ Wq,
                                                const float* __restrict__ Wk,
                                                const float* __restrict__ Wv) {
    __shared__ float sAT[32][132];
    __shared__ float sB[32][36];
    int tid = threadIdx.x;
    int bm0 = blockIdx.x * 128;
    int by = blockIdx.y;
    int which = by >> 3, hh = by & 7;
    const float* W = (which == 0) ? Wq : (which == 1) ? Wk : Wv;
    W += hh * (F * DK);
    float* outb = (which == 0) ? d_Q : (which == 1) ? d_K : d_V;
    outb += hh * (N_NODES * DK);
    int tm = tid >> 3, tn = tid & 7;
    float acc[4][4];
    #pragma unroll
    for (int i = 0; i < 4; ++i)
        #pragma unroll
        for (int j = 0; j < 4; ++j) acc[i][j] = 0.f;

    for (int k0 = 0; k0 < F; k0 += 32) {
        #pragma unroll
        for (int it = 0; it < 4; ++it) {
            int idx = it * 256 + tid;
            int row = idx >> 3, f4 = idx & 7;
            float4 av = *(const float4*)&d_hbuf[(bm0 + row) * F + k0 + 4 * f4];
            sAT[4 * f4 + 0][row] = av.x;
            sAT[4 * f4 + 1][row] = av.y;
            sAT[4 * f4 + 2][row] = av.z;
            sAT[4 * f4 + 3][row] = av.w;
        }
        {
            int kk = tid >> 3, d4 = tid & 7;
            *(float4*)&sB[kk][4 * d4] = *(const float4*)&W[(k0 + kk) * DK + 4 * d4];
        }
        __syncthreads();
        #pragma unroll
        for (int kk = 0; kk < 32; ++kk) {
            float4 a4 = *(const float4*)&sAT[kk][4 * tm];
            float4 b4 = *(const float4*)&sB[kk][4 * tn];
            float av[4] = {a4.x, a4.y, a4.z, a4.w};
            float bv[4] = {b4.x, b4.y, b4.z, b4.w};
            #pragma unroll
            for (int i = 0; i < 4; ++i)
                #pragma unroll
                for (int j = 0; j < 4; ++j) acc[i][j] += av[i] * bv[j];
        }
        __syncthreads();
    }
    #pragma unroll
    for (int i = 0; i < 4; ++i) {
        float4 o = make_float4(acc[i][0], acc[i][1], acc[i][2], acc[i][3]);
        *(float4*)&outb[(bm0 + 4 * tm + i) * DK + 4 * tn] = o;
    }
}

// ---------------- K3b: fold constants (rank-1 bases + scaled a) ----------------
__global__ void __launch_bounds__(256) fold_kernel(const float* __restrict__ a) {
    const float SCALE = 0.17677669529663687f;  // 1/sqrt(32)
    const float L2E = 1.4426950408889634f;
    int t = blockIdx.x * 256 + threadIdx.x;    // h*2048 + n
    int hh = t >> 11;
    const float* av = a + hh * DK;
    const float* qp = d_Q + t * DK;
    const float* kp = d_K + t * DK;
    float sq = 0.f, sk = 0.f;
    #pragma unroll
    for (int d4 = 0; d4 < 8; ++d4) {
        float4 qv = *(const float4*)&qp[4 * d4];
        float4 kv = *(const float4*)&kp[4 * d4];
        float4 avv = *(const float4*)&av[4 * d4];
        sq += avv.x * qv.x + avv.y * qv.y + avv.z * qv.z + avv.w * qv.w;
        sk += avv.x * kv.x + avv.y * kv.y + avv.z * kv.z + avv.w * kv.w;
    }
    d_bq[t] = (ALPHA * SCALE * L2E) * sq;
    d_bk[t] = (ALPHA * SCALE * L2E) * sk;
    if (t < H * DK) d_af[t] = ((1.0f - ALPHA) * SCALE * L2E) * a[t];
}

// ---------------- K3c: V pair-interleave prep ----------------
__global__ void __launch_bounds__(256) v_prep() {
    int idx = blockIdx.x * 256 + threadIdx.x;   // [0, H*1024*8)
    int jg = idx >> 3;                          // global jpair (incl. head)
    int q = idx & 7;                            // 4-d chunk
    const float* r0 = d_V + (jg * 2) * DK + 4 * q;
    float4 va = *(const float4*)r0;
    float4 vb = *(const float4*)(r0 + DK);
    float2* dst = d_V2 + jg * DK + 4 * q;
    dst[0] = make_float2(va.x, vb.x);
    dst[1] = make_float2(va.y, vb.y);
    dst[2] = make_float2(va.z, vb.z);
    dst[3] = make_float2(va.w, vb.w);
}

// ---------------- K4: fused GAT attention (f32x2 logits + PV) ----------------
#define BI 32
#define BJ 128
#define NJT (N_NODES / BJ)

struct AttnSmem {
    float2  sVp[BJ / 2][34];    // [jpair][d] interleaved (v_even, v_odd) - 17.4KB
    float   sK[BJ][34];         // [j][d] natural - 17.4KB
    float   sQ[BI][34];         // [i][d] natural - 4.3KB
    float   sP[BI][BJ + 2];     // exp'd probs - 16.6KB
    unsigned sAdj[BI][64];      // 8KB
    float   sA[DK];             // a'
    float   sBq[BI];
    float   sBk[BJ];
    float   sL[BI];
};

__global__ void __launch_bounds__(256, 3) attn_kernel() {
    extern __shared__ char smem_raw[];
    AttnSmem& sm = *reinterpret_cast<AttnSmem*>(smem_raw);
    int tid = threadIdx.x;
    int h = blockIdx.y;
    int i0 = blockIdx.x * BI;
    int hN = h * N_NODES;
    const float* Qh = d_Q + hN * DK;
    const float* Kh = d_K + hN * DK;
    const float2* V2h = d_V2 + h * (N_NODES / 2) * DK;

    // ---- prologue: Q tile, adjacency, row bases, a' ----
    {
        int i = tid >> 3, dq = tid & 7;
        float4 qv = *(const float4*)&Qh[(i0 + i) * DK + 4 * dq];
        *(float2*)&sm.sQ[i][4 * dq] = make_float2(qv.x, qv.y);
        *(float2*)&sm.sQ[i][4 * dq + 2] = make_float2(qv.z, qv.w);
    }
    if (tid < BI) sm.sBq[tid] = d_bq[hN + i0 + tid];
    if (tid < DK) sm.sA[tid] = d_af[h * DK + tid];
    for (int idx = tid; idx < BI * 64; idx += 256)
        sm.sAdj[idx >> 6][idx & 63] = d_adjb[(i0 + (idx >> 6)) * 64 + (idx & 63)];

    int r = tid >> 5;           // logits: warp -> 4-row group; PV: warp -> d-group
    int c = tid & 31;           // logits: lane -> col (strided 32); PV: lane -> row

    const ull ONE2 = pk2(1.0f, 1.0f);
    ull oacc[4] = {0ull, 0ull, 0ull, 0ull};
    ull lsum = 0ull;

    for (int jt = 0; jt < NJT; ++jt) {
        int j0 = jt * BJ;
        __syncthreads();  // previous PV done before overwriting K/V tiles

        // ---- fill K tile [j][d] (straight copy) ----
        #pragma unroll
        for (int it = 0; it < 4; ++it) {
            int idx = it * 256 + tid;            // 1024 chunks of 4 floats
            int j = idx >> 3, dq = idx & 7;
            float4 kv = *(const float4*)&Kh[(j0 + j) * DK + 4 * dq];
            *(float2*)&sm.sK[j][4 * dq] = make_float2(kv.x, kv.y);
            *(float2*)&sm.sK[j][4 * dq + 2] = make_float2(kv.z, kv.w);
        }
        // ---- fill V tile [jp][d] (straight copy of pre-interleaved) ----
        #pragma unroll
        for (int it = 0; it < 4; ++it) {
            int idx = it * 256 + tid;            // 1024 chunks of 2 float2
            int jp = idx >> 4, q = idx & 15;
            *(float4*)&sm.sVp[jp][2 * q] =
                *(const float4*)&V2h[(jt * 64 + jp) * DK + 2 * q];
        }
        if (tid < BJ) sm.sBk[tid] = d_bk[hN + j0 + tid];
        __syncthreads();

        // ---- logits: f32x2 over d-pairs; 4 rows x 4 strided cols / thread ----
        ull acc[4][4];
        #pragma unroll
        for (int ii = 0; ii < 4; ++ii)
            #pragma unroll
            for (int jj = 0; jj < 4; ++jj) acc[ii][jj] = 0ull;

        #pragma unroll
        for (int d2 = 0; d2 < 16; ++d2) {
            ull a2 = *(const ull*)&sm.sA[2 * d2];
            ull q2[4], k2[4];
            #pragma unroll
            for (int ii = 0; ii < 4; ++ii)
                q2[ii] = *(const ull*)&sm.sQ[4 * r + ii][2 * d2];
            #pragma unroll
            for (int jj = 0; jj < 4; ++jj)
                k2[jj] = *(const ull*)&sm.sK[c + 32 * jj][2 * d2];
            #pragma unroll
            for (int ii = 0; ii < 4; ++ii)
                #pragma unroll
                for (int jj = 0; jj < 4; ++jj) term2(q2[ii], k2[jj], a2, acc[ii][jj]);
        }

        // ---- epilogue: bias, adjacency mask, exp2, store probs ----
        #pragma unroll
        for (int ii = 0; ii < 4; ++ii) {
            int i = 4 * r + ii;
            float bq = sm.sBq[i];
            #pragma unroll
            for (int jj = 0; jj < 4; ++jj) {
                int j = c + 32 * jj;
                float lo, hi;
                upk2(acc[ii][jj], lo, hi);
                float lg = lo + hi + bq + sm.sBk[j];
                unsigned bit = (sm.sAdj[i][jt * 4 + jj] >> c) & 1u;
                sm.sP[i][j] = bit ? ex2f(lg) : 0.0f;
            }
        }
        __syncthreads();

        // ---- PV: f32x2 over j-pairs; warp r owns d-group, lane c owns row ----
        #pragma unroll 8
        for (int jp = 0; jp < BJ / 2; ++jp) {
            ull p2u = *(const ull*)&sm.sP[c][2 * jp];
            ulonglong2 va = *(const ulonglong2*)&sm.sVp[jp][4 * r];      // dd=4r,4r+1
            ulonglong2 vb = *(const ulonglong2*)&sm.sVp[jp][4 * r + 2];  // dd=4r+2,4r+3
            oacc[0] = fma2v(p2u, va.x, oacc[0]);
            oacc[1] = fma2v(p2u, va.y, oacc[1]);
            oacc[2] = fma2v(p2u, vb.x, oacc[2]);
            oacc[3] = fma2v(p2u, vb.y, oacc[3]);
            if (r == 0) lsum = fma2v(p2u, ONE2, lsum);
        }
    }

    if (r == 0) {
        float lo, hi; upk2(lsum, lo, hi);
        sm.sL[c] = lo + hi;
    }
    __syncthreads();
    float inv = 1.0f / sm.sL[c];
    float o[4];
    #pragma unroll
    for (int t = 0; t < 4; ++t) {
        float lo, hi; upk2(oacc[t], lo, hi);
        o[t] = (lo + hi) * inv;
    }
    *(float4*)&d_ao[(i0 + c) * F + h * DK + r * 4] = make_float4(o[0], o[1], o[2], o[3]);
}

// ---------------- K5: output projection + bias + residual ----------------
__global__ void __launch_bounds__(256) out_gemm(const float* __restrict__ Wo,
                                                const float* __restrict__ bo,
                                                const float* __restrict__ x,
                                                float* __restrict__ out) {
    __shared__ float sAT[32][132];
    __shared__ float sB[32][36];
    int tid = threadIdx.x;
    int bm0 = blockIdx.x * 128;
    int c0 = blockIdx.y * 32;
    int tm = tid >> 3, tn = tid & 7;
    float acc[4][4];
    #pragma unroll
    for (int i = 0; i < 4; ++i)
        #pragma unroll
        for (int j = 0; j < 4; ++j) acc[i][j] = 0.f;

    for (int k0 = 0; k0 < F; k0 += 32) {
        #pragma unroll
        for (int it = 0; it < 4; ++it) {
            int idx = it * 256 + tid;
            int row = idx >> 3, f4 = idx & 7;
            float4 av = *(const float4*)&d_ao[(bm0 + row) * F + k0 + 4 * f4];
            sAT[4 * f4 + 0][row] = av.x;
            sAT[4 * f4 + 1][row] = av.y;
            sAT[4 * f4 + 2][row] = av.z;
            sAT[4 * f4 + 3][row] = av.w;
        }
        {
            int kk = tid >> 3, d4 = tid & 7;
            *(float4*)&sB[kk][4 * d4] = *(const float4*)&Wo[(k0 + kk) * F + c0 + 4 * d4];
        }
        __syncthreads();
        #pragma unroll
        for (int kk = 0; kk < 32; ++kk) {
            float4 a4 = *(const float4*)&sAT[kk][4 * tm];
            float4 b4 = *(const float4*)&sB[kk][4 * tn];
            float av[4] = {a4.x, a4.y, a4.z, a4.w};
            float bv[4] = {b4.x, b4.y, b4.z, b4.w};
            #pragma unroll
            for (int i = 0; i < 4; ++i)
                #pragma unroll
                for (int j = 0; j < 4; ++j) acc[i][j] += av[i] * bv[j];
        }
        __syncthreads();
    }
    float4 bv4 = *(const float4*)&bo[c0 + 4 * tn];
    #pragma unroll
    for (int i = 0; i < 4; ++i) {
        int n = bm0 + 4 * tm + i;
        float4 xv = *(const float4*)&x[n * F + c0 + 4 * tn];
        float4 o = make_float4(acc[i][0] + bv4.x + xv.x, acc[i][1] + bv4.y + xv.y,
                               acc[i][2] + bv4.z + xv.z, acc[i][3] + bv4.w + xv.w);
        *(float4*)&out[n * F + c0 + 4 * tn] = o;
    }
}

// ---------------- launch ----------------
extern "C" void kernel_launch(void* const* d_in, const int* in_sizes, int n_in,
                              void* d_out, int out_size) {
    const float* x     = (const float*)d_in[0];
    const int*   adj   = (const int*)d_in[1];
    const float* Wq    = (const float*)d_in[2];
    const float* Wk    = (const float*)d_in[3];
    const float* Wv    = (const float*)d_in[4];
    const float* a     = (const float*)d_in[5];
    const float* Wo    = (const float*)d_in[6];
    const float* bo    = (const float*)d_in[7];
    const float* gamma = (const float*)d_in[8];
    const float* beta  = (const float*)d_in[9];
    float* out = (float*)d_out;

    cudaFuncSetAttribute(attn_kernel, cudaFuncAttributeMaxDynamicSharedMemorySize,
                         (int)sizeof(AttnSmem));

    pack_adj<<<(N_NODES * N_NODES / 4) / 256, 256>>>(adj);
    ln_kernel<<<N_NODES, 256>>>(x, gamma, beta);
    qkv_gemm<<<dim3(N_NODES / 128, 24), 256>>>(Wq, Wk, Wv);
    fold_kernel<<<(H * N_NODES) / 256, 256>>>(a);
    v_prep<<<(H * (N_NODES / 2) * 8) / 256, 256>>>();
    attn_kernel<<<dim3(N_NODES / BI, H), 256, sizeof(AttnSmem)>>>();
    out_gemm<<<dim3(N_NODES / 128, F / 32), 256>>>(Wo, bo, x, out);
}

// round 6
// speedup vs baseline: 1.1257x; 1.1257x over previous
#include <cuda_runtime.h>
#include <cuda_fp16.h>

#define N_NODES 2048
#define F 256
#define H 8
#define DK 32
#define ALPHA 0.2f
#define LN_EPS 1e-5f

typedef unsigned long long ull;

// ---------------- scratch (no allocations allowed) ----------------
__device__ float d_hbuf[N_NODES * F];
__device__ __half2 d_Qh2[H * N_NODES * (DK / 2)];   // fp16 Q, d-pairs
__device__ __half2 d_Kh2[H * N_NODES * (DK / 2)];   // fp16 K, d-pairs
__device__ float2 d_V2[H * (N_NODES / 2) * DK];     // (v[2jp][d], v[2jp+1][d]) pairs
__device__ float d_bq[H * N_NODES];
__device__ float d_bk[H * N_NODES];
__device__ __half2 d_afh2[H * (DK / 2)];            // a' d-pairs, a' = (1-α)·scale·log2e·a
__device__ unsigned d_adjb[N_NODES * (N_NODES / 32)];
__device__ float d_ao[N_NODES * F];

// ---------------- helpers ----------------
__device__ __forceinline__ float ex2f(float x) {
    float r; asm("ex2.approx.f32 %0, %1;" : "=f"(r) : "f"(x)); return r;
}
__device__ __forceinline__ ull pk2(float lo, float hi) {
    ull r; asm("mov.b64 %0, {%1, %2};" : "=l"(r) : "f"(lo), "f"(hi)); return r;
}
__device__ __forceinline__ void upk2(ull v, float& lo, float& hi) {
    asm("mov.b64 {%0, %1}, %2;" : "=f"(lo), "=f"(hi) : "l"(v));
}
__device__ __forceinline__ ull fma2v(ull a, ull b, ull c) {
    ull r;
    asm("fma.rn.f32x2 %0, %1, %2, %3;" : "=l"(r) : "l"(a), "l"(b), "l"(c));
    return r;
}

// ---------------- K1: pack adjacency (4 words/warp) + a' fold ----------------
__global__ void __launch_bounds__(256) pack_adj(const int* __restrict__ adj,
                                                const float* __restrict__ a) {
    int t = blockIdx.x * 256 + threadIdx.x;
    int warp = t >> 5, lane = t & 31;
    int base = warp * 128;
    unsigned m0 = __ballot_sync(0xffffffffu, adj[base + lane] != 0);
    unsigned m1 = __ballot_sync(0xffffffffu, adj[base + 32 + lane] != 0);
    unsigned m2 = __ballot_sync(0xffffffffu, adj[base + 64 + lane] != 0);
    unsigned m3 = __ballot_sync(0xffffffffu, adj[base + 96 + lane] != 0);
    if (lane == 0) *(uint4*)&d_adjb[warp * 4] = make_uint4(m0, m1, m2, m3);
    if (blockIdx.x == 0 && threadIdx.x < H * (DK / 2)) {
        const float C = (1.0f - ALPHA) * 0.17677669529663687f * 1.4426950408889634f;
        float2 av = *(const float2*)&a[2 * threadIdx.x];
        d_afh2[threadIdx.x] = __floats2half2_rn(C * av.x, C * av.y);
    }
}

// ---------------- K2: LayerNorm ----------------
__global__ void __launch_bounds__(256) ln_kernel(const float* __restrict__ x,
                                                 const float* __restrict__ gamma,
                                                 const float* __restrict__ beta) {
    int row = blockIdx.x;
    int t = threadIdx.x;
    float v = x[row * F + t];
    float s = v, s2 = v * v;
    #pragma unroll
    for (int m = 16; m > 0; m >>= 1) {
        s  += __shfl_xor_sync(0xffffffffu, s, m);
        s2 += __shfl_xor_sync(0xffffffffu, s2, m);
    }
    __shared__ float ws[8], ws2[8];
    if ((t & 31) == 0) { ws[t >> 5] = s; ws2[t >> 5] = s2; }
    __syncthreads();
    float tot = 0.f, tot2 = 0.f;
    #pragma unroll
    for (int w = 0; w < 8; ++w) { tot += ws[w]; tot2 += ws2[w]; }
    float mu = tot * (1.0f / F);
    float var = tot2 * (1.0f / F) - mu * mu;
    float inv = rsqrtf(var + LN_EPS);
    d_hbuf[row * F + t] = (v - mu) * inv * gamma[t] + beta[t];
}

// ---------------- K3: QKV GEMM with fused epilogue ----------------
// which==0/1: write fp16 Q/K (d-pairs) + rank-1 bias bq/bk via shfl reduce.
// which==2:  write pair-interleaved V2 directly (no fp32 V buffer at all).
__global__ void __launch_bounds__(256) qkv_gemm(const float* __restrict__ Wq,
                                                const float* __restrict__ Wk,
                                                const float* __restrict__ Wv,
                                                const float* __restrict__ a) {
    __shared__ float sAT[32][132];
    __shared__ float sB[32][36];
    int tid = threadIdx.x;
    int bm0 = blockIdx.x * 128;
    int by = blockIdx.y;
    int which = by >> 3, hh = by & 7;
    const float* W = (which == 0) ? Wq : (which == 1) ? Wk : Wv;
    W += hh * (F * DK);
    int tm = tid >> 3, tn = tid & 7;
    float acc[4][4];
    #pragma unroll
    for (int i = 0; i < 4; ++i)
        #pragma unroll
        for (int j = 0; j < 4; ++j) acc[i][j] = 0.f;

    for (int k0 = 0; k0 < F; k0 += 32) {
        #pragma unroll
        for (int it = 0; it < 4; ++it) {
            int idx = it * 256 + tid;
            int row = idx >> 3, f4 = idx & 7;
            float4 av = *(const float4*)&d_hbuf[(bm0 + row) * F + k0 + 4 * f4];
            sAT[4 * f4 + 0][row] = av.x;
            sAT[4 * f4 + 1][row] = av.y;
            sAT[4 * f4 + 2][row] = av.z;
            sAT[4 * f4 + 3][row] = av.w;
        }
        {
            int kk = tid >> 3, d4 = tid & 7;
            *(float4*)&sB[kk][4 * d4] = *(const float4*)&W[(k0 + kk) * DK + 4 * d4];
        }
        __syncthreads();
        #pragma unroll
        for (int kk = 0; kk < 32; ++kk) {
            float4 a4 = *(const float4*)&sAT[kk][4 * tm];
            float4 b4 = *(const float4*)&sB[kk][4 * tn];
            float av[4] = {a4.x, a4.y, a4.z, a4.w};
            float bv[4] = {b4.x, b4.y, b4.z, b4.w};
            #pragma unroll
            for (int i = 0; i < 4; ++i)
                #pragma unroll
                for (int j = 0; j < 4; ++j) acc[i][j] += av[i] * bv[j];
        }
        __syncthreads();
    }

    if (which == 2) {
        // V2: rows (4tm, 4tm+1) and (4tm+2, 4tm+3) interleave into jg pairs
        float2* base = d_V2 + (hh * (N_NODES / 2) + (bm0 >> 1) + 2 * tm) * DK + 4 * tn;
        #pragma unroll
        for (int p = 0; p < 2; ++p) {
            float2* dst = base + p * DK;
            *(float4*)&dst[0] = make_float4(acc[2 * p][0], acc[2 * p + 1][0],
                                            acc[2 * p][1], acc[2 * p + 1][1]);
            *(float4*)&dst[2] = make_float4(acc[2 * p][2], acc[2 * p + 1][2],
                                            acc[2 * p][3], acc[2 * p + 1][3]);
        }
    } else {
        const float C = ALPHA * 0.17677669529663687f * 1.4426950408889634f;
        __half2* dstH = ((which == 0) ? d_Qh2 : d_Kh2) + hh * N_NODES * 16;
        float* dstB = ((which == 0) ? d_bq : d_bk) + hh * N_NODES;
        float4 av = *(const float4*)&a[hh * DK + 4 * tn];
        #pragma unroll
        for (int i = 0; i < 4; ++i) {
            int row = bm0 + 4 * tm + i;
            __half2 h0 = __floats2half2_rn(acc[i][0], acc[i][1]);
            __half2 h1 = __floats2half2_rn(acc[i][2], acc[i][3]);
            uint2 pk;
            pk.x = *(unsigned*)&h0;
            pk.y = *(unsigned*)&h1;
            *(uint2*)&dstH[row * 16 + 2 * tn] = pk;
            float part = av.x * acc[i][0] + av.y * acc[i][1] +
                         av.z * acc[i][2] + av.w * acc[i][3];
            part += __shfl_xor_sync(0xffffffffu, part, 1);
            part += __shfl_xor_sync(0xffffffffu, part, 2);
            part += __shfl_xor_sync(0xffffffffu, part, 4);
            if (tn == 0) dstB[row] = C * part;
        }
    }
}

// ---------------- K4: fused GAT attention (half2 logits + blocked f32 drain) ----------------
#define BI 32
#define BJ 128
#define NJT (N_NODES / BJ)
#define QP 17   // half2 pitch for Q/K tiles (conflict-free reads)

struct AttnSmem {
    float2  sVp[BJ / 2][34];    // [jpair][d] interleaved - 17.4KB
    __half2 sKh[BJ][QP];        // [j][d2] - 8.7KB
    __half2 sQh[BI][QP];        // [i][d2] - 2.2KB
    float   sP[BI][BJ + 2];     // exp'd probs - 16.6KB
    unsigned sAdj[BI][64];      // 8KB
    __half2 sA2[16];            // a' d-pairs
    float   sBq[BI];
    float   sBk[BJ];
    float   sL[BI];
};

__global__ void __launch_bounds__(256, 3) attn_kernel() {
    extern __shared__ char smem_raw[];
    AttnSmem& sm = *reinterpret_cast<AttnSmem*>(smem_raw);
    int tid = threadIdx.x;
    int h = blockIdx.y;
    int i0 = blockIdx.x * BI;
    int hN = h * N_NODES;
    const __half2* Qh2 = d_Qh2 + hN * 16;
    const __half2* Kh2 = d_Kh2 + hN * 16;
    const float2* V2h = d_V2 + h * (N_NODES / 2) * DK;

    // ---- prologue: Q tile, adjacency, bases, a' ----
    if (tid < 128) {                      // 128 int4 chunks = 32 rows x 16 half2
        int i = tid >> 2, q4 = (tid & 3) * 4;
        uint4 qv = *(const uint4*)&Qh2[(i0 + i) * 16 + q4];
        sm.sQh[i][q4 + 0] = *(__half2*)&qv.x;
        sm.sQh[i][q4 + 1] = *(__half2*)&qv.y;
        sm.sQh[i][q4 + 2] = *(__half2*)&qv.z;
        sm.sQh[i][q4 + 3] = *(__half2*)&qv.w;
    }
    if (tid < BI) sm.sBq[tid] = d_bq[hN + i0 + tid];
    if (tid < 16) sm.sA2[tid] = d_afh2[h * 16 + tid];
    for (int idx = tid; idx < BI * 64; idx += 256)
        sm.sAdj[idx >> 6][idx & 63] = d_adjb[(i0 + (idx >> 6)) * 64 + (idx & 63)];

    int r = tid >> 5;           // logits: warp -> 4-row group; PV: warp -> d-group
    int c = tid & 31;           // logits: lane -> col (strided 32); PV: lane -> row

    const ull ONE2 = pk2(1.0f, 1.0f);
    const __half2 h2z = __float2half2_rn(0.0f);
    ull oacc[4] = {0ull, 0ull, 0ull, 0ull};
    ull lsum = 0ull;

    for (int jt = 0; jt < NJT; ++jt) {
        int j0 = jt * BJ;
        __syncthreads();  // previous PV done before overwriting K/V tiles

        // ---- fill K tile [j][d2] ----
        #pragma unroll
        for (int it = 0; it < 2; ++it) {
            int chunk = it * 256 + tid;          // 512 chunks of 4 half2
            int j = chunk >> 2, q4 = (chunk & 3) * 4;
            uint4 kv = *(const uint4*)&Kh2[(j0 + j) * 16 + q4];
            sm.sKh[j][q4 + 0] = *(__half2*)&kv.x;
            sm.sKh[j][q4 + 1] = *(__half2*)&kv.y;
            sm.sKh[j][q4 + 2] = *(__half2*)&kv.z;
            sm.sKh[j][q4 + 3] = *(__half2*)&kv.w;
        }
        // ---- fill V tile [jp][d] (straight copy, pre-interleaved) ----
        #pragma unroll
        for (int it = 0; it < 4; ++it) {
            int idx = it * 256 + tid;            // 1024 chunks of 2 float2
            int jp = idx >> 4, q = idx & 15;
            *(float4*)&sm.sVp[jp][2 * q] =
                *(const float4*)&V2h[(jt * 64 + jp) * DK + 2 * q];
        }
        if (tid < BJ) sm.sBk[tid] = d_bk[hN + j0 + tid];
        __syncthreads();

        // ---- logits: half2 over d-pairs, fp32 drain every 8 pairs ----
        float facc[4][4];
        #pragma unroll
        for (int ii = 0; ii < 4; ++ii)
            #pragma unroll
            for (int jj = 0; jj < 4; ++jj) facc[ii][jj] = 0.f;

        #pragma unroll
        for (int blk = 0; blk < 2; ++blk) {
            __half2 hacc[4][4];
            #pragma unroll
            for (int ii = 0; ii < 4; ++ii)
                #pragma unroll
                for (int jj = 0; jj < 4; ++jj) hacc[ii][jj] = h2z;
            #pragma unroll
            for (int dd = 0; dd < 8; ++dd) {
                int d2 = blk * 8 + dd;
                __half2 a2 = sm.sA2[d2];
                __half2 q2[4], k2[4];
                #pragma unroll
                for (int ii = 0; ii < 4; ++ii) q2[ii] = sm.sQh[4 * r + ii][d2];
                #pragma unroll
                for (int jj = 0; jj < 4; ++jj) k2[jj] = sm.sKh[c + 32 * jj][d2];
                #pragma unroll
                for (int ii = 0; ii < 4; ++ii)
                    #pragma unroll
                    for (int jj = 0; jj < 4; ++jj)
                        hacc[ii][jj] = __hfma2(a2,
                            __hmax2(__hadd2(q2[ii], k2[jj]), h2z), hacc[ii][jj]);
            }
            #pragma unroll
            for (int ii = 0; ii < 4; ++ii)
                #pragma unroll
                for (int jj = 0; jj < 4; ++jj) {
                    float2 f = __half22float2(hacc[ii][jj]);
                    facc[ii][jj] += f.x + f.y;
                }
        }

        // ---- epilogue: bias, adjacency mask, exp2, store probs ----
        #pragma unroll
        for (int ii = 0; ii < 4; ++ii) {
            int i = 4 * r + ii;
            float bq = sm.sBq[i];
            #pragma unroll
            for (int jj = 0; jj < 4; ++jj) {
                int j = c + 32 * jj;
                float lg = facc[ii][jj] + bq + sm.sBk[j];
                unsigned bit = (sm.sAdj[i][jt * 4 + jj] >> c) & 1u;
                sm.sP[i][j] = bit ? ex2f(lg) : 0.0f;
            }
        }
        __syncthreads();

        // ---- PV: f32x2 over j-pairs; warp r owns d-group, lane c owns row ----
        #pragma unroll 8
        for (int jp = 0; jp < BJ / 2; ++jp) {
            ull p2u = *(const ull*)&sm.sP[c][2 * jp];
            ulonglong2 va = *(const ulonglong2*)&sm.sVp[jp][4 * r];
            ulonglong2 vb = *(const ulonglong2*)&sm.sVp[jp][4 * r + 2];
            oacc[0] = fma2v(p2u, va.x, oacc[0]);
            oacc[1] = fma2v(p2u, va.y, oacc[1]);
            oacc[2] = fma2v(p2u, vb.x, oacc[2]);
            oacc[3] = fma2v(p2u, vb.y, oacc[3]);
            if (r == 0) lsum = fma2v(p2u, ONE2, lsum);
        }
    }

    if (r == 0) {
        float lo, hi; upk2(lsum, lo, hi);
        sm.sL[c] = lo + hi;
    }
    __syncthreads();
    float inv = 1.0f / sm.sL[c];
    float o[4];
    #pragma unroll
    for (int t = 0; t < 4; ++t) {
        float lo, hi; upk2(oacc[t], lo, hi);
        o[t] = (lo + hi) * inv;
    }
    *(float4*)&d_ao[(i0 + c) * F + h * DK + r * 4] = make_float4(o[0], o[1], o[2], o[3]);
}

// ---------------- K5: output projection + bias + residual ----------------
__global__ void __launch_bounds__(256) out_gemm(const float* __restrict__ Wo,
                                                const float* __restrict__ bo,
                                                const float* __restrict__ x,
                                                float* __restrict__ out) {
    __shared__ float sAT[32][132];
    __shared__ float sB[32][36];
    int tid = threadIdx.x;
    int bm0 = blockIdx.x * 128;
    int c0 = blockIdx.y * 32;
    int tm = tid >> 3, tn = tid & 7;
    float acc[4][4];
    #pragma unroll
    for (int i = 0; i < 4; ++i)
        #pragma unroll
        for (int j = 0; j < 4; ++j) acc[i][j] = 0.f;

    for (int k0 = 0; k0 < F; k0 += 32) {
        #pragma unroll
        for (int it = 0; it < 4; ++it) {
            int idx = it * 256 + tid;
            int row = idx >> 3, f4 = idx & 7;
            float4 av = *(const float4*)&d_ao[(bm0 + row) * F + k0 + 4 * f4];
            sAT[4 * f4 + 0][row] = av.x;
            sAT[4 * f4 + 1][row] = av.y;
            sAT[4 * f4 + 2][row] = av.z;
            sAT[4 * f4 + 3][row] = av.w;
        }
        {
            int kk = tid >> 3, d4 = tid & 7;
            *(float4*)&sB[kk][4 * d4] = *(const float4*)&Wo[(k0 + kk) * F + c0 + 4 * d4];
        }
        __syncthreads();
        #pragma unroll
        for (int kk = 0; kk < 32; ++kk) {
            float4 a4 = *(const float4*)&sAT[kk][4 * tm];
            float4 b4 = *(const float4*)&sB[kk][4 * tn];
            float av[4] = {a4.x, a4.y, a4.z, a4.w};
            float bv[4] = {b4.x, b4.y, b4.z, b4.w};
            #pragma unroll
            for (int i = 0; i < 4; ++i)
                #pragma unroll
                for (int j = 0; j < 4; ++j) acc[i][j] += av[i] * bv[j];
        }
        __syncthreads();
    }
    float4 bv4 = *(const float4*)&bo[c0 + 4 * tn];
    #pragma unroll
    for (int i = 0; i < 4; ++i) {
        int n = bm0 + 4 * tm + i;
        float4 xv = *(const float4*)&x[n * F + c0 + 4 * tn];
        float4 o = make_float4(acc[i][0] + bv4.x + xv.x, acc[i][1] + bv4.y + xv.y,
                               acc[i][2] + bv4.z + xv.z, acc[i][3] + bv4.w + xv.w);
        *(float4*)&out[n * F + c0 + 4 * tn] = o;
    }
}

// ---------------- launch ----------------
extern "C" void kernel_launch(void* const* d_in, const int* in_sizes, int n_in,
                              void* d_out, int out_size) {
    const float* x     = (const float*)d_in[0];
    const int*   adj   = (const int*)d_in[1];
    const float* Wq    = (const float*)d_in[2];
    const float* Wk    = (const float*)d_in[3];
    const float* Wv    = (const float*)d_in[4];
    const float* a     = (const float*)d_in[5];
    const float* Wo    = (const float*)d_in[6];
    const float* bo    = (const float*)d_in[7];
    const float* gamma = (const float*)d_in[8];
    const float* beta  = (const float*)d_in[9];
    float* out = (float*)d_out;

    cudaFuncSetAttribute(attn_kernel, cudaFuncAttributeMaxDynamicSharedMemorySize,
                         (int)sizeof(AttnSmem));

    pack_adj<<<(N_NODES * N_NODES / 4) / 256, 256>>>(adj, a);
    ln_kernel<<<N_NODES, 256>>>(x, gamma, beta);
    qkv_gemm<<<dim3(N_NODES / 128, 24), 256>>>(Wq, Wk, Wv, a);
    attn_kernel<<<dim3(N_NODES / BI, H), 256, sizeof(AttnSmem)>>>();
    out_gemm<<<dim3(N_NODES / 128, F / 32), 256>>>(Wo, bo, x, out);
}

// round 8
// speedup vs baseline: 1.1522x; 1.0235x over previous
#include <cuda_runtime.h>
#include <cuda_fp16.h>

#define N_NODES 2048
#define F 256
#define H 8
#define DK 32
#define ALPHA 0.2f
#define LN_EPS 1e-5f

typedef unsigned long long ull;

// ---------------- scratch (no allocations allowed) ----------------
__device__ float d_hbuf[N_NODES * F];
__device__ __half2 d_Qh2[H * N_NODES * (DK / 2)];   // fp16 Q, d-pairs
__device__ __half2 d_Kh2[H * N_NODES * (DK / 2)];   // fp16 K, d-pairs
__device__ float2 d_V2[H * (N_NODES / 2) * DK];     // (v[2jp][d], v[2jp+1][d]) pairs
__device__ float d_bq[H * N_NODES];
__device__ float d_bk[H * N_NODES];
__device__ __half2 d_afh2[H * (DK / 2)];            // a' d-pairs, a' = (1-α)·scale·log2e·a
__device__ unsigned d_adjb[N_NODES * (N_NODES / 32)];
__device__ float d_ao[N_NODES * F];

// ---------------- helpers ----------------
__device__ __forceinline__ float ex2f(float x) {
    float r; asm("ex2.approx.f32 %0, %1;" : "=f"(r) : "f"(x)); return r;
}
__device__ __forceinline__ ull pk2(float lo, float hi) {
    ull r; asm("mov.b64 %0, {%1, %2};" : "=l"(r) : "f"(lo), "f"(hi)); return r;
}
__device__ __forceinline__ void upk2(ull v, float& lo, float& hi) {
    asm("mov.b64 {%0, %1}, %2;" : "=f"(lo), "=f"(hi) : "l"(v));
}
__device__ __forceinline__ ull fma2v(ull a, ull b, ull c) {
    ull r;
    asm("fma.rn.f32x2 %0, %1, %2, %3;" : "=l"(r) : "l"(a), "l"(b), "l"(c));
    return r;
}
// fused relu(q + k) on half2 via fma.rn.relu.f16x2 (sm_80+) — single issue slot
__device__ __forceinline__ __half2 hadd2_relu(__half2 q, __half2 k, __half2 one2) {
    unsigned d;
    asm("fma.rn.relu.f16x2 %0, %1, %2, %3;"
        : "=r"(d)
        : "r"(*(unsigned*)&q), "r"(*(unsigned*)&one2), "r"(*(unsigned*)&k));
    return *(__half2*)&d;
}

// ---------------- K1: pack adjacency (4 words/warp) + a' fold ----------------
__global__ void __launch_bounds__(256) pack_adj(const int* __restrict__ adj,
                                                const float* __restrict__ a) {
    int t = blockIdx.x * 256 + threadIdx.x;
    int warp = t >> 5, lane = t & 31;
    int base = warp * 128;
    unsigned m0 = __ballot_sync(0xffffffffu, adj[base + lane] != 0);
    unsigned m1 = __ballot_sync(0xffffffffu, adj[base + 32 + lane] != 0);
    unsigned m2 = __ballot_sync(0xffffffffu, adj[base + 64 + lane] != 0);
    unsigned m3 = __ballot_sync(0xffffffffu, adj[base + 96 + lane] != 0);
    if (lane == 0) *(uint4*)&d_adjb[warp * 4] = make_uint4(m0, m1, m2, m3);
    if (blockIdx.x == 0 && threadIdx.x < H * (DK / 2)) {
        const float C = (1.0f - ALPHA) * 0.17677669529663687f * 1.4426950408889634f;
        float2 av = *(const float2*)&a[2 * threadIdx.x];
        d_afh2[threadIdx.x] = __floats2half2_rn(C * av.x, C * av.y);
    }
}

// ---------------- K2: LayerNorm ----------------
__global__ void __launch_bounds__(256) ln_kernel(const float* __restrict__ x,
                                                 const float* __restrict__ gamma,
                                                 const float* __restrict__ beta) {
    int row = blockIdx.x;
    int t = threadIdx.x;
    float v = x[row * F + t];
    float s = v, s2 = v * v;
    #pragma unroll
    for (int m = 16; m > 0; m >>= 1) {
        s  += __shfl_xor_sync(0xffffffffu, s, m);
        s2 += __shfl_xor_sync(0xffffffffu, s2, m);
    }
    __shared__ float ws[8], ws2[8];
    if ((t & 31) == 0) { ws[t >> 5] = s; ws2[t >> 5] = s2; }
    __syncthreads();
    float tot = 0.f, tot2 = 0.f;
    #pragma unroll
    for (int w = 0; w < 8; ++w) { tot += ws[w]; tot2 += ws2[w]; }
    float mu = tot * (1.0f / F);
    float var = tot2 * (1.0f / F) - mu * mu;
    float inv = rsqrtf(var + LN_EPS);
    d_hbuf[row * F + t] = (v - mu) * inv * gamma[t] + beta[t];
}

// ---------------- K3: QKV GEMM with fused epilogue ----------------
__global__ void __launch_bounds__(256) qkv_gemm(const float* __restrict__ Wq,
                                                const float* __restrict__ Wk,
                                                const float* __restrict__ Wv,
                                                const float* __restrict__ a) {
    __shared__ float sAT[32][132];
    __shared__ float sB[32][36];
    int tid = threadIdx.x;
    int bm0 = blockIdx.x * 128;
    int by = blockIdx.y;
    int which = by >> 3, hh = by & 7;
    const float* W = (which == 0) ? Wq : (which == 1) ? Wk : Wv;
    W += hh * (F * DK);
    int tm = tid >> 3, tn = tid & 7;
    float acc[4][4];
    #pragma unroll
    for (int i = 0; i < 4; ++i)
        #pragma unroll
        for (int j = 0; j < 4; ++j) acc[i][j] = 0.f;

    for (int k0 = 0; k0 < F; k0 += 32) {
        #pragma unroll
        for (int it = 0; it < 4; ++it) {
            int idx = it * 256 + tid;
            int row = idx >> 3, f4 = idx & 7;
            float4 av = *(const float4*)&d_hbuf[(bm0 + row) * F + k0 + 4 * f4];
            sAT[4 * f4 + 0][row] = av.x;
            sAT[4 * f4 + 1][row] = av.y;
            sAT[4 * f4 + 2][row] = av.z;
            sAT[4 * f4 + 3][row] = av.w;
        }
        {
            int kk = tid >> 3, d4 = tid & 7;
            *(float4*)&sB[kk][4 * d4] = *(const float4*)&W[(k0 + kk) * DK + 4 * d4];
        }
        __syncthreads();
        #pragma unroll
        for (int kk = 0; kk < 32; ++kk) {
            float4 a4 = *(const float4*)&sAT[kk][4 * tm];
            float4 b4 = *(const float4*)&sB[kk][4 * tn];
            float av[4] = {a4.x, a4.y, a4.z, a4.w};
            float bv[4] = {b4.x, b4.y, b4.z, b4.w};
            #pragma unroll
            for (int i = 0; i < 4; ++i)
                #pragma unroll
                for (int j = 0; j < 4; ++j) acc[i][j] += av[i] * bv[j];
        }
        __syncthreads();
    }

    if (which == 2) {
        float2* base = d_V2 + (hh * (N_NODES / 2) + (bm0 >> 1) + 2 * tm) * DK + 4 * tn;
        #pragma unroll
        for (int p = 0; p < 2; ++p) {
            float2* dst = base + p * DK;
            *(float4*)&dst[0] = make_float4(acc[2 * p][0], acc[2 * p + 1][0],
                                            acc[2 * p][1], acc[2 * p + 1][1]);
            *(float4*)&dst[2] = make_float4(acc[2 * p][2], acc[2 * p + 1][2],
                                            acc[2 * p][3], acc[2 * p + 1][3]);
        }
    } else {
        const float C = ALPHA * 0.17677669529663687f * 1.4426950408889634f;
        __half2* dstH = ((which == 0) ? d_Qh2 : d_Kh2) + hh * N_NODES * 16;
        float* dstB = ((which == 0) ? d_bq : d_bk) + hh * N_NODES;
        float4 av = *(const float4*)&a[hh * DK + 4 * tn];
        #pragma unroll
        for (int i = 0; i < 4; ++i) {
            int row = bm0 + 4 * tm + i;
            __half2 h0 = __floats2half2_rn(acc[i][0], acc[i][1]);
            __half2 h1 = __floats2half2_rn(acc[i][2], acc[i][3]);
            uint2 pk;
            pk.x = *(unsigned*)&h0;
            pk.y = *(unsigned*)&h1;
            *(uint2*)&dstH[row * 16 + 2 * tn] = pk;
            float part = av.x * acc[i][0] + av.y * acc[i][1] +
                         av.z * acc[i][2] + av.w * acc[i][3];
            part += __shfl_xor_sync(0xffffffffu, part, 1);
            part += __shfl_xor_sync(0xffffffffu, part, 2);
            part += __shfl_xor_sync(0xffffffffu, part, 4);
            if (tn == 0) dstB[row] = C * part;
        }
    }
}

// ---------------- K4: fused GAT attention (fma.relu logits) ----------------
#define BI 32
#define BJ 128
#define NJT (N_NODES / BJ)
#define QP 17   // half2 pitch for Q/K tiles (conflict-free reads)

struct AttnSmem {
    float2  sVp[BJ / 2][34];    // [jpair][d] interleaved - 17.4KB
    __half2 sKh[BJ][QP];        // [j][d2] - 8.7KB
    __half2 sQh[BI][QP];        // [i][d2] - 2.2KB
    float   sP[BI][BJ + 2];     // exp'd probs - 16.6KB
    unsigned sAdj[BI][64];      // 8KB
    __half2 sA2[16];            // a' d-pairs
    float   sBq[BI];
    float   sBk[BJ];
    float   sL[BI];
};

__global__ void __launch_bounds__(256, 3) attn_kernel() {
    extern __shared__ char smem_raw[];
    AttnSmem& sm = *reinterpret_cast<AttnSmem*>(smem_raw);
    int tid = threadIdx.x;
    int h = blockIdx.y;
    int i0 = blockIdx.x * BI;
    int hN = h * N_NODES;
    const __half2* Qh2 = d_Qh2 + hN * 16;
    const __half2* Kh2 = d_Kh2 + hN * 16;
    const float2* V2h = d_V2 + h * (N_NODES / 2) * DK;

    // ---- prologue: Q tile, adjacency, bases, a' ----
    if (tid < 128) {                      // 128 int4 chunks = 32 rows x 16 half2
        int i = tid >> 2, q4 = (tid & 3) * 4;
        uint4 qv = *(const uint4*)&Qh2[(i0 + i) * 16 + q4];
        sm.sQh[i][q4 + 0] = *(__half2*)&qv.x;
        sm.sQh[i][q4 + 1] = *(__half2*)&qv.y;
        sm.sQh[i][q4 + 2] = *(__half2*)&qv.z;
        sm.sQh[i][q4 + 3] = *(__half2*)&qv.w;
    }
    if (tid < BI) sm.sBq[tid] = d_bq[hN + i0 + tid];
    if (tid < 16) sm.sA2[tid] = d_afh2[h * 16 + tid];
    for (int idx = tid; idx < BI * 64; idx += 256)
        sm.sAdj[idx >> 6][idx & 63] = d_adjb[(i0 + (idx >> 6)) * 64 + (idx & 63)];

    int r = tid >> 5;           // logits: warp -> 4-row group; PV: warp -> d-group
    int c = tid & 31;           // logits: lane -> col (strided 32); PV: lane -> row

    const ull ONE2 = pk2(1.0f, 1.0f);
    const __half2 h2z = __float2half2_rn(0.0f);
    const __half2 h2one = __float2half2_rn(1.0f);
    ull oacc[4] = {0ull, 0ull, 0ull, 0ull};
    ull lsum = 0ull;

    for (int jt = 0; jt < NJT; ++jt) {
        int j0 = jt * BJ;
        __syncthreads();  // previous PV done before overwriting K/V tiles

        // ---- fill K tile [j][d2] ----
        #pragma unroll
        for (int it = 0; it < 2; ++it) {
            int chunk = it * 256 + tid;          // 512 chunks of 4 half2
            int j = chunk >> 2, q4 = (chunk & 3) * 4;
            uint4 kv = *(const uint4*)&Kh2[(j0 + j) * 16 + q4];
            sm.sKh[j][q4 + 0] = *(__half2*)&kv.x;
            sm.sKh[j][q4 + 1] = *(__half2*)&kv.y;
            sm.sKh[j][q4 + 2] = *(__half2*)&kv.z;
            sm.sKh[j][q4 + 3] = *(__half2*)&kv.w;
        }
        // ---- fill V tile [jp][d] (straight copy, pre-interleaved) ----
        #pragma unroll
        for (int it = 0; it < 4; ++it) {
            int idx = it * 256 + tid;            // 1024 chunks of 2 float2
            int jp = idx >> 4, q = idx & 15;
            *(float4*)&sm.sVp[jp][2 * q] =
                *(const float4*)&V2h[(jt * 64 + jp) * DK + 2 * q];
        }
        if (tid < BJ) sm.sBk[tid] = d_bk[hN + j0 + tid];
        __syncthreads();

        // ---- logits: fma.relu + hfma2, fp32 drain every 8 d-pairs ----
        float facc[4][4];
        #pragma unroll
        for (int ii = 0; ii < 4; ++ii)
            #pragma unroll
            for (int jj = 0; jj < 4; ++jj) facc[ii][jj] = 0.f;

        #pragma unroll
        for (int blk = 0; blk < 2; ++blk) {
            __half2 hacc[4][4];
            #pragma unroll
            for (int ii = 0; ii < 4; ++ii)
                #pragma unroll
                for (int jj = 0; jj < 4; ++jj) hacc[ii][jj] = h2z;
            #pragma unroll
            for (int dd = 0; dd < 8; ++dd) {
                int d2 = blk * 8 + dd;
                __half2 a2 = sm.sA2[d2];
                __half2 q2[4], k2[4];
                #pragma unroll
                for (int ii = 0; ii < 4; ++ii) q2[ii] = sm.sQh[4 * r + ii][d2];
                #pragma unroll
                for (int jj = 0; jj < 4; ++jj) k2[jj] = sm.sKh[c + 32 * jj][d2];
                #pragma unroll
                for (int ii = 0; ii < 4; ++ii)
                    #pragma unroll
                    for (int jj = 0; jj < 4; ++jj)
                        hacc[ii][jj] = __hfma2(a2,
                            hadd2_relu(q2[ii], k2[jj], h2one), hacc[ii][jj]);
            }
            #pragma unroll
            for (int ii = 0; ii < 4; ++ii)
                #pragma unroll
                for (int jj = 0; jj < 4; ++jj) {
                    float2 f = __half22float2(hacc[ii][jj]);
                    facc[ii][jj] += f.x + f.y;
                }
        }

        // ---- epilogue: bias, adjacency mask, exp2, store probs ----
        #pragma unroll
        for (int ii = 0; ii < 4; ++ii) {
            int i = 4 * r + ii;
            float bq = sm.sBq[i];
            #pragma unroll
            for (int jj = 0; jj < 4; ++jj) {
                int j = c + 32 * jj;
                float lg = facc[ii][jj] + bq + sm.sBk[j];
                unsigned bit = (sm.sAdj[i][jt * 4 + jj] >> c) & 1u;
                sm.sP[i][j] = bit ? ex2f(lg) : 0.0f;
            }
        }
        __syncthreads();

        // ---- PV: f32x2 over j-pairs; warp r owns d-group, lane c owns row ----
        #pragma unroll 8
        for (int jp = 0; jp < BJ / 2; ++jp) {
            ull p2u = *(const ull*)&sm.sP[c][2 * jp];
            ulonglong2 va = *(const ulonglong2*)&sm.sVp[jp][4 * r];
            ulonglong2 vb = *(const ulonglong2*)&sm.sVp[jp][4 * r + 2];
            oacc[0] = fma2v(p2u, va.x, oacc[0]);
            oacc[1] = fma2v(p2u, va.y, oacc[1]);
            oacc[2] = fma2v(p2u, vb.x, oacc[2]);
            oacc[3] = fma2v(p2u, vb.y, oacc[3]);
            if (r == 0) lsum = fma2v(p2u, ONE2, lsum);
        }
    }

    if (r == 0) {
        float lo, hi; upk2(lsum, lo, hi);
        sm.sL[c] = lo + hi;
    }
    __syncthreads();
    float inv = 1.0f / sm.sL[c];
    float o[4];
    #pragma unroll
    for (int t = 0; t < 4; ++t) {
        float lo, hi; upk2(oacc[t], lo, hi);
        o[t] = (lo + hi) * inv;
    }
    *(float4*)&d_ao[(i0 + c) * F + h * DK + r * 4] = make_float4(o[0], o[1], o[2], o[3]);
}

// ---------------- K5: output projection + bias + residual ----------------
__global__ void __launch_bounds__(256) out_gemm(const float* __restrict__ Wo,
                                                const float* __restrict__ bo,
                                                const float* __restrict__ x,
                                                float* __restrict__ out) {
    __shared__ float sAT[32][132];
    __shared__ float sB[32][36];
    int tid = threadIdx.x;
    int bm0 = blockIdx.x * 128;
    int c0 = blockIdx.y * 32;
    int tm = tid >> 3, tn = tid & 7;
    float acc[4][4];
    #pragma unroll
    for (int i = 0; i < 4; ++i)
        #pragma unroll
        for (int j = 0; j < 4; ++j) acc[i][j] = 0.f;

    for (int k0 = 0; k0 < F; k0 += 32) {
        #pragma unroll
        for (int it = 0; it < 4; ++it) {
            int idx = it * 256 + tid;
            int row = idx >> 3, f4 = idx & 7;
            float4 av = *(const float4*)&d_ao[(bm0 + row) * F + k0 + 4 * f4];
            sAT[4 * f4 + 0][row] = av.x;
            sAT[4 * f4 + 1][row] = av.y;
            sAT[4 * f4 + 2][row] = av.z;
            sAT[4 * f4 + 3][row] = av.w;
        }
        {
            int kk = tid >> 3, d4 = tid & 7;
            *(float4*)&sB[kk][4 * d4] = *(const float4*)&Wo[(k0 + kk) * F + c0 + 4 * d4];
        }
        __syncthreads();
        #pragma unroll
        for (int kk = 0; kk < 32; ++kk) {
            float4 a4 = *(const float4*)&sAT[kk][4 * tm];
            float4 b4 = *(const float4*)&sB[kk][4 * tn];
            float av[4] = {a4.x, a4.y, a4.z, a4.w};
            float bv[4] = {b4.x, b4.y, b4.z, b4.w};
            #pragma unroll
            for (int i = 0; i < 4; ++i)
                #pragma unroll
                for (int j = 0; j < 4; ++j) acc[i][j] += av[i] * bv[j];
        }
        __syncthreads();
    }
    float4 bv4 = *(const float4*)&bo[c0 + 4 * tn];
    #pragma unroll
    for (int i = 0; i < 4; ++i) {
        int n = bm0 + 4 * tm + i;
        float4 xv = *(const float4*)&x[n * F + c0 + 4 * tn];
        float4 o = make_float4(acc[i][0] + bv4.x + xv.x, acc[i][1] + bv4.y + xv.y,
                               acc[i][2] + bv4.z + xv.z, acc[i][3] + bv4.w + xv.w);
        *(float4*)&out[n * F + c0 + 4 * tn] = o;
    }
}

// ---------------- launch ----------------
extern "C" void kernel_launch(void* const* d_in, const int* in_sizes, int n_in,
                              void* d_out, int out_size) {
    const float* x     = (const float*)d_in[0];
    const int*   adj   = (const int*)d_in[1];
    const float* Wq    = (const float*)d_in[2];
    const float* Wk    = (const float*)d_in[3];
    const float* Wv    = (const float*)d_in[4];
    const float* a     = (const float*)d_in[5];
    const float* Wo    = (const float*)d_in[6];
    const float* bo    = (const float*)d_in[7];
    const float* gamma = (const float*)d_in[8];
    const float* beta  = (const float*)d_in[9];
    float* out = (float*)d_out;

    cudaFuncSetAttribute(attn_kernel, cudaFuncAttributeMaxDynamicSharedMemorySize,
                         (int)sizeof(AttnSmem));

    pack_adj<<<(N_NODES * N_NODES / 4) / 256, 256>>>(adj, a);
    ln_kernel<<<N_NODES, 256>>>(x, gamma, beta);
    qkv_gemm<<<dim3(N_NODES / 128, 24), 256>>>(Wq, Wk, Wv, a);
    attn_kernel<<<dim3(N_NODES / BI, H), 256, sizeof(AttnSmem)>>>();
    out_gemm<<<dim3(N_NODES / 128, F / 32), 256>>>(Wo, bo, x, out);
}

// round 9
// speedup vs baseline: 1.5360x; 1.3331x over previous
#include <cuda_runtime.h>
#include <cuda_fp16.h>

#define N_NODES 2048
#define F 256
#define H 8
#define DK 32
#define ALPHA 0.2f
#define LN_EPS 1e-5f

typedef unsigned long long ull;

// ---------------- scratch (no allocations allowed) ----------------
__device__ float d_hbuf[N_NODES * F];
__device__ __half2 d_Qh2[H * N_NODES * (DK / 2)];   // fp16 Q, d-pairs
__device__ __half2 d_Kh2[H * N_NODES * (DK / 2)];   // fp16 K, d-pairs
__device__ __half  d_Vh[H * N_NODES * DK];          // fp16 V, [node][d]
__device__ float d_bq[H * N_NODES];
__device__ float d_bk[H * N_NODES];
__device__ __half2 d_afh2[H * (DK / 2)];            // a' d-pairs, a' = (1-α)·scale·log2e·a
__device__ unsigned d_adjb[N_NODES * (N_NODES / 32)];
__device__ float d_ao[N_NODES * F];

// ---------------- helpers ----------------
__device__ __forceinline__ float ex2f(float x) {
    float r; asm("ex2.approx.f32 %0, %1;" : "=f"(r) : "f"(x)); return r;
}
// fused relu(q + k) on half2 via fma.rn.relu.f16x2 (sm_80+) — single issue slot
__device__ __forceinline__ __half2 hadd2_relu(__half2 q, __half2 k, __half2 one2) {
    unsigned d;
    asm("fma.rn.relu.f16x2 %0, %1, %2, %3;"
        : "=r"(d)
        : "r"(*(unsigned*)&q), "r"(*(unsigned*)&one2), "r"(*(unsigned*)&k));
    return *(__half2*)&d;
}
__device__ __forceinline__ void ldm_x4(unsigned& a0, unsigned& a1, unsigned& a2,
                                       unsigned& a3, unsigned addr) {
    asm volatile("ldmatrix.sync.aligned.m8n8.x4.shared.b16 {%0,%1,%2,%3}, [%4];"
                 : "=r"(a0), "=r"(a1), "=r"(a2), "=r"(a3) : "r"(addr));
}
__device__ __forceinline__ void ldm_x2t(unsigned& b0, unsigned& b1, unsigned addr) {
    asm volatile("ldmatrix.sync.aligned.m8n8.x2.trans.shared.b16 {%0,%1}, [%2];"
                 : "=r"(b0), "=r"(b1) : "r"(addr));
}
__device__ __forceinline__ void mma16816(float& c0, float& c1, float& c2, float& c3,
                                         unsigned a0, unsigned a1, unsigned a2,
                                         unsigned a3, unsigned b0, unsigned b1) {
    asm volatile("mma.sync.aligned.m16n8k16.row.col.f32.f16.f16.f32 "
                 "{%0,%1,%2,%3}, {%4,%5,%6,%7}, {%8,%9}, {%0,%1,%2,%3};"
                 : "+f"(c0), "+f"(c1), "+f"(c2), "+f"(c3)
                 : "r"(a0), "r"(a1), "r"(a2), "r"(a3), "r"(b0), "r"(b1));
}

// ---------------- K1: pack adjacency (4 words/warp) + a' fold ----------------
__global__ void __launch_bounds__(256) pack_adj(const int* __restrict__ adj,
                                                const float* __restrict__ a) {
    int t = blockIdx.x * 256 + threadIdx.x;
    int warp = t >> 5, lane = t & 31;
    int base = warp * 128;
    unsigned m0 = __ballot_sync(0xffffffffu, adj[base + lane] != 0);
    unsigned m1 = __ballot_sync(0xffffffffu, adj[base + 32 + lane] != 0);
    unsigned m2 = __ballot_sync(0xffffffffu, adj[base + 64 + lane] != 0);
    unsigned m3 = __ballot_sync(0xffffffffu, adj[base + 96 + lane] != 0);
    if (lane == 0) *(uint4*)&d_adjb[warp * 4] = make_uint4(m0, m1, m2, m3);
    if (blockIdx.x == 0 && threadIdx.x < H * (DK / 2)) {
        const float C = (1.0f - ALPHA) * 0.17677669529663687f * 1.4426950408889634f;
        float2 av = *(const float2*)&a[2 * threadIdx.x];
        d_afh2[threadIdx.x] = __floats2half2_rn(C * av.x, C * av.y);
    }
}

// ---------------- K2: LayerNorm ----------------
__global__ void __launch_bounds__(256) ln_kernel(const float* __restrict__ x,
                                                 const float* __restrict__ gamma,
                                                 const float* __restrict__ beta) {
    int row = blockIdx.x;
    int t = threadIdx.x;
    float v = x[row * F + t];
    float s = v, s2 = v * v;
    #pragma unroll
    for (int m = 16; m > 0; m >>= 1) {
        s  += __shfl_xor_sync(0xffffffffu, s, m);
        s2 += __shfl_xor_sync(0xffffffffu, s2, m);
    }
    __shared__ float ws[8], ws2[8];
    if ((t & 31) == 0) { ws[t >> 5] = s; ws2[t >> 5] = s2; }
    __syncthreads();
    float tot = 0.f, tot2 = 0.f;
    #pragma unroll
    for (int w = 0; w < 8; ++w) { tot += ws[w]; tot2 += ws2[w]; }
    float mu = tot * (1.0f / F);
    float var = tot2 * (1.0f / F) - mu * mu;
    float inv = rsqrtf(var + LN_EPS);
    d_hbuf[row * F + t] = (v - mu) * inv * gamma[t] + beta[t];
}

// ---------------- K3: QKV GEMM with fused epilogue ----------------
__global__ void __launch_bounds__(256) qkv_gemm(const float* __restrict__ Wq,
                                                const float* __restrict__ Wk,
                                                const float* __restrict__ Wv,
                                                const float* __restrict__ a) {
    __shared__ float sAT[32][132];
    __shared__ float sB[32][36];
    int tid = threadIdx.x;
    int bm0 = blockIdx.x * 128;
    int by = blockIdx.y;
    int which = by >> 3, hh = by & 7;
    const float* W = (which == 0) ? Wq : (which == 1) ? Wk : Wv;
    W += hh * (F * DK);
    int tm = tid >> 3, tn = tid & 7;
    float acc[4][4];
    #pragma unroll
    for (int i = 0; i < 4; ++i)
        #pragma unroll
        for (int j = 0; j < 4; ++j) acc[i][j] = 0.f;

    for (int k0 = 0; k0 < F; k0 += 32) {
        #pragma unroll
        for (int it = 0; it < 4; ++it) {
            int idx = it * 256 + tid;
            int row = idx >> 3, f4 = idx & 7;
            float4 av = *(const float4*)&d_hbuf[(bm0 + row) * F + k0 + 4 * f4];
            sAT[4 * f4 + 0][row] = av.x;
            sAT[4 * f4 + 1][row] = av.y;
            sAT[4 * f4 + 2][row] = av.z;
            sAT[4 * f4 + 3][row] = av.w;
        }
        {
            int kk = tid >> 3, d4 = tid & 7;
            *(float4*)&sB[kk][4 * d4] = *(const float4*)&W[(k0 + kk) * DK + 4 * d4];
        }
        __syncthreads();
        #pragma unroll
        for (int kk = 0; kk < 32; ++kk) {
            float4 a4 = *(const float4*)&sAT[kk][4 * tm];
            float4 b4 = *(const float4*)&sB[kk][4 * tn];
            float av[4] = {a4.x, a4.y, a4.z, a4.w};
            float bv[4] = {b4.x, b4.y, b4.z, b4.w};
            #pragma unroll
            for (int i = 0; i < 4; ++i)
                #pragma unroll
                for (int j = 0; j < 4; ++j) acc[i][j] += av[i] * bv[j];
        }
        __syncthreads();
    }

    if (which == 2) {
        __half* dstV = d_Vh + hh * N_NODES * DK;
        #pragma unroll
        for (int i = 0; i < 4; ++i) {
            int row = bm0 + 4 * tm + i;
            __half2 h0 = __floats2half2_rn(acc[i][0], acc[i][1]);
            __half2 h1 = __floats2half2_rn(acc[i][2], acc[i][3]);
            uint2 pk;
            pk.x = *(unsigned*)&h0;
            pk.y = *(unsigned*)&h1;
            *(uint2*)&dstV[row * DK + 4 * tn] = pk;
        }
    } else {
        const float C = ALPHA * 0.17677669529663687f * 1.4426950408889634f;
        __half2* dstH = ((which == 0) ? d_Qh2 : d_Kh2) + hh * N_NODES * 16;
        float* dstB = ((which == 0) ? d_bq : d_bk) + hh * N_NODES;
        float4 av = *(const float4*)&a[hh * DK + 4 * tn];
        #pragma unroll
        for (int i = 0; i < 4; ++i) {
            int row = bm0 + 4 * tm + i;
            __half2 h0 = __floats2half2_rn(acc[i][0], acc[i][1]);
            __half2 h1 = __floats2half2_rn(acc[i][2], acc[i][3]);
            uint2 pk;
            pk.x = *(unsigned*)&h0;
            pk.y = *(unsigned*)&h1;
            *(uint2*)&dstH[row * 16 + 2 * tn] = pk;
            float part = av.x * acc[i][0] + av.y * acc[i][1] +
                         av.z * acc[i][2] + av.w * acc[i][3];
            part += __shfl_xor_sync(0xffffffffu, part, 1);
            part += __shfl_xor_sync(0xffffffffu, part, 2);
            part += __shfl_xor_sync(0xffffffffu, part, 4);
            if (tn == 0) dstB[row] = C * part;
        }
    }
}

// ---------------- K4: fused GAT attention (half2 logits + mma PV) ----------------
#define BI 32
#define BJ 128
#define NJT (N_NODES / BJ)

struct AttnSmem {
    __half  sPh[BI][136];      // P fp16, pitch 136 halves (272B) - 8.5KB
    __half  sVh[BJ][40];       // V fp16 [j][d], pitch 40 halves (80B) - 10KB
    __half2 sKT[16][136];      // K [d2][j] half2, pitch 136 - 8.5KB
    __half2 sQh[BI][17];       // Q [i][d2] - 2.1KB
    unsigned sAdj[BI][64];     // 8KB
    __half2 sA2[16];           // a' d-pairs
    float   sBq[BI];
    float   sBk[BJ];
    float   sL[BI];
};

__global__ void __launch_bounds__(256, 4) attn_kernel() {
    extern __shared__ char smem_raw[];
    AttnSmem& sm = *reinterpret_cast<AttnSmem*>(smem_raw);
    int tid = threadIdx.x;
    int h = blockIdx.y;
    int i0 = blockIdx.x * BI;
    int hN = h * N_NODES;
    const __half2* Qh2 = d_Qh2 + hN * 16;
    const __half2* Kh2 = d_Kh2 + hN * 16;
    const __half*  Vh  = d_Vh + hN * DK;

    // ---- prologue: Q tile, adjacency, bases, a' ----
    if (tid < 128) {
        int i = tid >> 2, q4 = (tid & 3) * 4;
        uint4 qv = *(const uint4*)&Qh2[(i0 + i) * 16 + q4];
        sm.sQh[i][q4 + 0] = *(__half2*)&qv.x;
        sm.sQh[i][q4 + 1] = *(__half2*)&qv.y;
        sm.sQh[i][q4 + 2] = *(__half2*)&qv.z;
        sm.sQh[i][q4 + 3] = *(__half2*)&qv.w;
    }
    if (tid < BI) sm.sBq[tid] = d_bq[hN + i0 + tid];
    if (tid < 16) sm.sA2[tid] = d_afh2[h * 16 + tid];
    for (int idx = tid; idx < BI * 64; idx += 256)
        sm.sAdj[idx >> 6][idx & 63] = d_adjb[(i0 + (idx >> 6)) * 64 + (idx & 63)];

    int r = tid >> 5;           // warp id
    int c = tid & 31;           // lane
    int mh = r >> 2;            // mma: m-half (rows 16mh..16mh+15)
    int nq = r & 3;             // mma: n-quarter (cols 8nq..8nq+7)

    // ldmatrix base addresses (per-lane)
    unsigned aAddrBase = (unsigned)__cvta_generic_to_shared(
        &sm.sPh[mh * 16 + (c & 15)][(c >> 4) * 8]);
    unsigned bAddrBase = (unsigned)__cvta_generic_to_shared(
        &sm.sVh[c & 15][nq * 8]);

    const __half2 h2one = __float2half2_rn(1.0f);
    float psum[4] = {0.f, 0.f, 0.f, 0.f};
    float cacc0 = 0.f, cacc1 = 0.f, cacc2 = 0.f, cacc3 = 0.f;

    for (int jt = 0; jt < NJT; ++jt) {
        int j0 = jt * BJ;
        __syncthreads();  // prev tile's mma/logits reads done before refill

        // ---- fill K tile transposed [d2][j] ----
        #pragma unroll
        for (int it = 0; it < 2; ++it) {
            int chunk = it * 256 + tid;          // 512 chunks of 4 half2
            int j = chunk >> 2, q4 = (chunk & 3) * 4;
            uint4 kv = *(const uint4*)&Kh2[(j0 + j) * 16 + q4];
            sm.sKT[q4 + 0][j] = *(__half2*)&kv.x;
            sm.sKT[q4 + 1][j] = *(__half2*)&kv.y;
            sm.sKT[q4 + 2][j] = *(__half2*)&kv.z;
            sm.sKT[q4 + 3][j] = *(__half2*)&kv.w;
        }
        // ---- fill V tile [j][d] fp16 ----
        #pragma unroll
        for (int it = 0; it < 2; ++it) {
            int chunk = it * 256 + tid;          // 512 chunks of 8 halves
            int j = chunk >> 2, q8 = (chunk & 3) * 8;
            *(uint4*)&sm.sVh[j][q8] = *(const uint4*)&Vh[(j0 + j) * DK + q8];
        }
        if (tid < BJ) sm.sBk[tid] = d_bk[hN + j0 + tid];
        __syncthreads();

        // ---- logits: 4 rows x 4 cols (2c,2c+1,2c+64,2c+65) per thread ----
        float facc[4][4];
        #pragma unroll
        for (int ii = 0; ii < 4; ++ii)
            #pragma unroll
            for (int jj = 0; jj < 4; ++jj) facc[ii][jj] = 0.f;

        #pragma unroll
        for (int blk = 0; blk < 2; ++blk) {
            __half2 hacc[4][4];
            #pragma unroll
            for (int ii = 0; ii < 4; ++ii)
                #pragma unroll
                for (int jj = 0; jj < 4; ++jj) hacc[ii][jj] = __float2half2_rn(0.f);
            #pragma unroll
            for (int dd = 0; dd < 8; ++dd) {
                int d2 = blk * 8 + dd;
                __half2 a2 = sm.sA2[d2];
                __half2 q2[4], k2[4];
                #pragma unroll
                for (int ii = 0; ii < 4; ++ii) q2[ii] = sm.sQh[4 * r + ii][d2];
                {
                    uint2 kk0 = *(const uint2*)&sm.sKT[d2][2 * c];
                    uint2 kk1 = *(const uint2*)&sm.sKT[d2][2 * c + 64];
                    k2[0] = *(__half2*)&kk0.x;
                    k2[1] = *(__half2*)&kk0.y;
                    k2[2] = *(__half2*)&kk1.x;
                    k2[3] = *(__half2*)&kk1.y;
                }
                #pragma unroll
                for (int ii = 0; ii < 4; ++ii)
                    #pragma unroll
                    for (int jj = 0; jj < 4; ++jj)
                        hacc[ii][jj] = __hfma2(a2,
                            hadd2_relu(q2[ii], k2[jj], h2one), hacc[ii][jj]);
            }
            #pragma unroll
            for (int ii = 0; ii < 4; ++ii)
                #pragma unroll
                for (int jj = 0; jj < 4; ++jj) {
                    float2 f = __half22float2(hacc[ii][jj]);
                    facc[ii][jj] += f.x + f.y;
                }
        }

        // ---- epilogue: bias, adjacency mask, exp2, fp16 P store, row partials ----
        {
            int wi = jt * 4 + (c >> 4);
            int b0 = (2 * c) & 31;
            float2 bk0 = *(const float2*)&sm.sBk[2 * c];
            float2 bk1 = *(const float2*)&sm.sBk[2 * c + 64];
            #pragma unroll
            for (int ii = 0; ii < 4; ++ii) {
                int i = 4 * r + ii;
                float bq = sm.sBq[i];
                unsigned w0 = sm.sAdj[i][wi];
                unsigned w1 = sm.sAdj[i][wi + 2];
                float p00 = ((w0 >> b0) & 1u)       ? ex2f(facc[ii][0] + bq + bk0.x) : 0.f;
                float p01 = ((w0 >> (b0 + 1)) & 1u) ? ex2f(facc[ii][1] + bq + bk0.y) : 0.f;
                float p10 = ((w1 >> b0) & 1u)       ? ex2f(facc[ii][2] + bq + bk1.x) : 0.f;
                float p11 = ((w1 >> (b0 + 1)) & 1u) ? ex2f(facc[ii][3] + bq + bk1.y) : 0.f;
                psum[ii] += (p00 + p01) + (p10 + p11);
                *(__half2*)&sm.sPh[i][2 * c]      = __floats2half2_rn(p00, p01);
                *(__half2*)&sm.sPh[i][2 * c + 64] = __floats2half2_rn(p10, p11);
            }
        }
        __syncthreads();  // P tile complete

        // ---- PV via tensor cores: one m16n8 output tile per warp ----
        #pragma unroll
        for (int ks = 0; ks < 8; ++ks) {
            unsigned a0, a1, a2r, a3, b0r, b1r;
            ldm_x4(a0, a1, a2r, a3, aAddrBase + ks * 32);        // +16 halves per ks
            ldm_x2t(b0r, b1r, bAddrBase + ks * 16 * 80);         // +16 rows per ks
            mma16816(cacc0, cacc1, cacc2, cacc3, a0, a1, a2r, a3, b0r, b1r);
        }
    }

    // ---- row-sum reduction across lanes ----
    #pragma unroll
    for (int ii = 0; ii < 4; ++ii) {
        float v = psum[ii];
        v += __shfl_xor_sync(0xffffffffu, v, 16);
        v += __shfl_xor_sync(0xffffffffu, v, 8);
        v += __shfl_xor_sync(0xffffffffu, v, 4);
        v += __shfl_xor_sync(0xffffffffu, v, 2);
        v += __shfl_xor_sync(0xffffffffu, v, 1);
        if (c == 0) sm.sL[4 * r + ii] = v;
    }
    __syncthreads();

    // ---- normalize + store (c-fragment layout) ----
    {
        int row0 = mh * 16 + (c >> 2);
        int col0 = nq * 8 + 2 * (c & 3);
        float inv0 = 1.0f / sm.sL[row0];
        float inv1 = 1.0f / sm.sL[row0 + 8];
        *(float2*)&d_ao[(i0 + row0) * F + h * DK + col0] =
            make_float2(cacc0 * inv0, cacc1 * inv0);
        *(float2*)&d_ao[(i0 + row0 + 8) * F + h * DK + col0] =
            make_float2(cacc2 * inv1, cacc3 * inv1);
    }
}

// ---------------- K5: output projection + bias + residual ----------------
__global__ void __launch_bounds__(256) out_gemm(const float* __restrict__ Wo,
                                                const float* __restrict__ bo,
                                                const float* __restrict__ x,
                                                float* __restrict__ out) {
    __shared__ float sAT[32][132];
    __shared__ float sB[32][36];
    int tid = threadIdx.x;
    int bm0 = blockIdx.x * 128;
    int c0 = blockIdx.y * 32;
    int tm = tid >> 3, tn = tid & 7;
    float acc[4][4];
    #pragma unroll
    for (int i = 0; i < 4; ++i)
        #pragma unroll
        for (int j = 0; j < 4; ++j) acc[i][j] = 0.f;

    for (int k0 = 0; k0 < F; k0 += 32) {
        #pragma unroll
        for (int it = 0; it < 4; ++it) {
            int idx = it * 256 + tid;
            int row = idx >> 3, f4 = idx & 7;
            float4 av = *(const float4*)&d_ao[(bm0 + row) * F + k0 + 4 * f4];
            sAT[4 * f4 + 0][row] = av.x;
            sAT[4 * f4 + 1][row] = av.y;
            sAT[4 * f4 + 2][row] = av.z;
            sAT[4 * f4 + 3][row] = av.w;
        }
        {
            int kk = tid >> 3, d4 = tid & 7;
            *(float4*)&sB[kk][4 * d4] = *(const float4*)&Wo[(k0 + kk) * F + c0 + 4 * d4];
        }
        __syncthreads();
        #pragma unroll
        for (int kk = 0; kk < 32; ++kk) {
            float4 a4 = *(const float4*)&sAT[kk][4 * tm];
            float4 b4 = *(const float4*)&sB[kk][4 * tn];
            float av[4] = {a4.x, a4.y, a4.z, a4.w};
            float bv[4] = {b4.x, b4.y, b4.z, b4.w};
            #pragma unroll
            for (int i = 0; i < 4; ++i)
                #pragma unroll
                for (int j = 0; j < 4; ++j) acc[i][j] += av[i] * bv[j];
        }
        __syncthreads();
    }
    float4 bv4 = *(const float4*)&bo[c0 + 4 * tn];
    #pragma unroll
    for (int i = 0; i < 4; ++i) {
        int n = bm0 + 4 * tm + i;
        float4 xv = *(const float4*)&x[n * F + c0 + 4 * tn];
        float4 o = make_float4(acc[i][0] + bv4.x + xv.x, acc[i][1] + bv4.y + xv.y,
                               acc[i][2] + bv4.z + xv.z, acc[i][3] + bv4.w + xv.w);
        *(float4*)&out[n * F + c0 + 4 * tn] = o;
    }
}

// ---------------- launch ----------------
extern "C" void kernel_launch(void* const* d_in, const int* in_sizes, int n_in,
                              void* d_out, int out_size) {
    const float* x     = (const float*)d_in[0];
    const int*   adj   = (const int*)d_in[1];
    const float* Wq    = (const float*)d_in[2];
    const float* Wk    = (const float*)d_in[3];
    const float* Wv    = (const float*)d_in[4];
    const float* a     = (const float*)d_in[5];
    const float* Wo    = (const float*)d_in[6];
    const float* bo    = (const float*)d_in[7];
    const float* gamma = (const float*)d_in[8];
    const float* beta  = (const float*)d_in[9];
    float* out = (float*)d_out;

    cudaFuncSetAttribute(attn_kernel, cudaFuncAttributeMaxDynamicSharedMemorySize,
                         (int)sizeof(AttnSmem));

    pack_adj<<<(N_NODES * N_NODES / 4) / 256, 256>>>(adj, a);
    ln_kernel<<<N_NODES, 256>>>(x, gamma, beta);
    qkv_gemm<<<dim3(N_NODES / 128, 24), 256>>>(Wq, Wk, Wv, a);
    attn_kernel<<<dim3(N_NODES / BI, H), 256, sizeof(AttnSmem)>>>();
    out_gemm<<<dim3(N_NODES / 128, F / 32), 256>>>(Wo, bo, x, out);
}

// round 10
// speedup vs baseline: 1.6525x; 1.0758x over previous
#include <cuda_runtime.h>
#include <cuda_fp16.h>

#define N_NODES 2048
#define F 256
#define H 8
#define DK 32
#define ALPHA 0.2f
#define LN_EPS 1e-5f

typedef unsigned long long ull;

// ---------------- scratch (no allocations allowed) ----------------
__device__ float d_hbuf[N_NODES * F];
__device__ __half2 d_Qh2[H * N_NODES * (DK / 2)];   // fp16 Q, d-pairs
__device__ __half2 d_Kh2[H * N_NODES * (DK / 2)];   // fp16 K, d-pairs
__device__ __half  d_Vh[H * N_NODES * DK];          // fp16 V, [node][d]
__device__ float d_bq[H * N_NODES];
__device__ float d_bk[H * N_NODES];
__device__ __half2 d_afh2[H * (DK / 2)];            // a' d-pairs, a' = (1-α)·scale·log2e·a
__device__ unsigned d_adjb[N_NODES * (N_NODES / 32)];
__device__ float d_ao[N_NODES * F];

// ---------------- helpers ----------------
__device__ __forceinline__ float ex2f(float x) {
    float r; asm("ex2.approx.f32 %0, %1;" : "=f"(r) : "f"(x)); return r;
}
// fused relu(k + q) on half2 via fma.rn.relu.f16x2 (k*1 + q)
__device__ __forceinline__ unsigned hrelu_add(unsigned k, unsigned q, unsigned one2) {
    unsigned d;
    asm("fma.rn.relu.f16x2 %0, %1, %2, %3;"
        : "=r"(d) : "r"(k), "r"(one2), "r"(q));
    return d;
}
__device__ __forceinline__ void ldm_x2(unsigned& r0, unsigned& r1, unsigned addr) {
    asm volatile("ldmatrix.sync.aligned.m8n8.x2.shared.b16 {%0,%1}, [%2];"
                 : "=r"(r0), "=r"(r1) : "r"(addr));
}
__device__ __forceinline__ void ldm_x4(unsigned& a0, unsigned& a1, unsigned& a2,
                                       unsigned& a3, unsigned addr) {
    asm volatile("ldmatrix.sync.aligned.m8n8.x4.shared.b16 {%0,%1,%2,%3}, [%4];"
                 : "=r"(a0), "=r"(a1), "=r"(a2), "=r"(a3) : "r"(addr));
}
__device__ __forceinline__ void ldm_x2t(unsigned& b0, unsigned& b1, unsigned addr) {
    asm volatile("ldmatrix.sync.aligned.m8n8.x2.trans.shared.b16 {%0,%1}, [%2];"
                 : "=r"(b0), "=r"(b1) : "r"(addr));
}
__device__ __forceinline__ void mma16816(float& c0, float& c1, float& c2, float& c3,
                                         unsigned a0, unsigned a1, unsigned a2,
                                         unsigned a3, unsigned b0, unsigned b1) {
    asm volatile("mma.sync.aligned.m16n8k16.row.col.f32.f16.f16.f32 "
                 "{%0,%1,%2,%3}, {%4,%5,%6,%7}, {%8,%9}, {%0,%1,%2,%3};"
                 : "+f"(c0), "+f"(c1), "+f"(c2), "+f"(c3)
                 : "r"(a0), "r"(a1), "r"(a2), "r"(a3), "r"(b0), "r"(b1));
}

// ---------------- K1: pack adjacency (4 words/warp) + a' fold ----------------
__global__ void __launch_bounds__(256) pack_adj(const int* __restrict__ adj,
                                                const float* __restrict__ a) {
    int t = blockIdx.x * 256 + threadIdx.x;
    int warp = t >> 5, lane = t & 31;
    int base = warp * 128;
    unsigned m0 = __ballot_sync(0xffffffffu, adj[base + lane] != 0);
    unsigned m1 = __ballot_sync(0xffffffffu, adj[base + 32 + lane] != 0);
    unsigned m2 = __ballot_sync(0xffffffffu, adj[base + 64 + lane] != 0);
    unsigned m3 = __ballot_sync(0xffffffffu, adj[base + 96 + lane] != 0);
    if (lane == 0) *(uint4*)&d_adjb[warp * 4] = make_uint4(m0, m1, m2, m3);
    if (blockIdx.x == 0 && threadIdx.x < H * (DK / 2)) {
        const float C = (1.0f - ALPHA) * 0.17677669529663687f * 1.4426950408889634f;
        float2 av = *(const float2*)&a[2 * threadIdx.x];
        d_afh2[threadIdx.x] = __floats2half2_rn(C * av.x, C * av.y);
    }
}

// ---------------- K2: LayerNorm ----------------
__global__ void __launch_bounds__(256) ln_kernel(const float* __restrict__ x,
                                                 const float* __restrict__ gamma,
                                                 const float* __restrict__ beta) {
    int row = blockIdx.x;
    int t = threadIdx.x;
    float v = x[row * F + t];
    float s = v, s2 = v * v;
    #pragma unroll
    for (int m = 16; m > 0; m >>= 1) {
        s  += __shfl_xor_sync(0xffffffffu, s, m);
        s2 += __shfl_xor_sync(0xffffffffu, s2, m);
    }
    __shared__ float ws[8], ws2[8];
    if ((t & 31) == 0) { ws[t >> 5] = s; ws2[t >> 5] = s2; }
    __syncthreads();
    float tot = 0.f, tot2 = 0.f;
    #pragma unroll
    for (int w = 0; w < 8; ++w) { tot += ws[w]; tot2 += ws2[w]; }
    float mu = tot * (1.0f / F);
    float var = tot2 * (1.0f / F) - mu * mu;
    float inv = rsqrtf(var + LN_EPS);
    d_hbuf[row * F + t] = (v - mu) * inv * gamma[t] + beta[t];
}

// ---------------- K3: QKV GEMM with fused epilogue ----------------
__global__ void __launch_bounds__(256) qkv_gemm(const float* __restrict__ Wq,
                                                const float* __restrict__ Wk,
                                                const float* __restrict__ Wv,
                                                const float* __restrict__ a) {
    __shared__ float sAT[32][132];
    __shared__ float sB[32][36];
    int tid = threadIdx.x;
    int bm0 = blockIdx.x * 128;
    int by = blockIdx.y;
    int which = by >> 3, hh = by & 7;
    const float* W = (which == 0) ? Wq : (which == 1) ? Wk : Wv;
    W += hh * (F * DK);
    int tm = tid >> 3, tn = tid & 7;
    float acc[4][4];
    #pragma unroll
    for (int i = 0; i < 4; ++i)
        #pragma unroll
        for (int j = 0; j < 4; ++j) acc[i][j] = 0.f;

    for (int k0 = 0; k0 < F; k0 += 32) {
        #pragma unroll
        for (int it = 0; it < 4; ++it) {
            int idx = it * 256 + tid;
            int row = idx >> 3, f4 = idx & 7;
            float4 av = *(const float4*)&d_hbuf[(bm0 + row) * F + k0 + 4 * f4];
            sAT[4 * f4 + 0][row] = av.x;
            sAT[4 * f4 + 1][row] = av.y;
            sAT[4 * f4 + 2][row] = av.z;
            sAT[4 * f4 + 3][row] = av.w;
        }
        {
            int kk = tid >> 3, d4 = tid & 7;
            *(float4*)&sB[kk][4 * d4] = *(const float4*)&W[(k0 + kk) * DK + 4 * d4];
        }
        __syncthreads();
        #pragma unroll
        for (int kk = 0; kk < 32; ++kk) {
            float4 a4 = *(const float4*)&sAT[kk][4 * tm];
            float4 b4 = *(const float4*)&sB[kk][4 * tn];
            float av[4] = {a4.x, a4.y, a4.z, a4.w};
            float bv[4] = {b4.x, b4.y, b4.z, b4.w};
            #pragma unroll
            for (int i = 0; i < 4; ++i)
                #pragma unroll
                for (int j = 0; j < 4; ++j) acc[i][j] += av[i] * bv[j];
        }
        __syncthreads();
    }

    if (which == 2) {
        __half* dstV = d_Vh + hh * N_NODES * DK;
        #pragma unroll
        for (int i = 0; i < 4; ++i) {
            int row = bm0 + 4 * tm + i;
            __half2 h0 = __floats2half2_rn(acc[i][0], acc[i][1]);
            __half2 h1 = __floats2half2_rn(acc[i][2], acc[i][3]);
            uint2 pk;
            pk.x = *(unsigned*)&h0;
            pk.y = *(unsigned*)&h1;
            *(uint2*)&dstV[row * DK + 4 * tn] = pk;
        }
    } else {
        const float C = ALPHA * 0.17677669529663687f * 1.4426950408889634f;
        __half2* dstH = ((which == 0) ? d_Qh2 : d_Kh2) + hh * N_NODES * 16;
        float* dstB = ((which == 0) ? d_bq : d_bk) + hh * N_NODES;
        float4 av = *(const float4*)&a[hh * DK + 4 * tn];
        #pragma unroll
        for (int i = 0; i < 4; ++i) {
            int row = bm0 + 4 * tm + i;
            __half2 h0 = __floats2half2_rn(acc[i][0], acc[i][1]);
            __half2 h1 = __floats2half2_rn(acc[i][2], acc[i][3]);
            uint2 pk;
            pk.x = *(unsigned*)&h0;
            pk.y = *(unsigned*)&h1;
            *(uint2*)&dstH[row * 16 + 2 * tn] = pk;
            float part = av.x * acc[i][0] + av.y * acc[i][1] +
                         av.z * acc[i][2] + av.w * acc[i][3];
            part += __shfl_xor_sync(0xffffffffu, part, 1);
            part += __shfl_xor_sync(0xffffffffu, part, 2);
            part += __shfl_xor_sync(0xffffffffu, part, 4);
            if (tn == 0) dstB[row] = C * part;
        }
    }
}

// ---------------- K4: fused GAT attention (mma logits + mma PV) ----------------
#define BI 32
#define BJ 128
#define NJT (N_NODES / BJ)

struct AttnSmem {
    __half  sPh[BI][136];      // P fp16 - 8.5KB
    __half  sVh[BJ][40];       // V fp16 [j][d] - 10KB
    __half  sKh[BJ][40];       // K fp16 [j][d] - 10KB
    float   sLog[BI][128];     // fp32 logits (pre-bias) - 16KB
    __half2 sQh[BI][17];       // Q [i][d2] - 2.2KB
    unsigned sAdj[BI][64];     // 8KB
    float   sBq[BI];
    float   sBk[BJ];
    float   sL[BI];
};

__global__ void __launch_bounds__(256, 4) attn_kernel() {
    extern __shared__ char smem_raw[];
    AttnSmem& sm = *reinterpret_cast<AttnSmem*>(smem_raw);
    int tid = threadIdx.x;
    int h = blockIdx.y;
    int i0 = blockIdx.x * BI;
    int hN = h * N_NODES;
    const __half2* Qh2 = d_Qh2 + hN * 16;
    const __half2* Kh2 = d_Kh2 + hN * 16;
    const __half*  Vh  = d_Vh + hN * DK;

    // ---- prologue: Q tile, adjacency, bases ----
    if (tid < 128) {
        int i = tid >> 2, q4 = (tid & 3) * 4;
        uint4 qv = *(const uint4*)&Qh2[(i0 + i) * 16 + q4];
        sm.sQh[i][q4 + 0] = *(__half2*)&qv.x;
        sm.sQh[i][q4 + 1] = *(__half2*)&qv.y;
        sm.sQh[i][q4 + 2] = *(__half2*)&qv.z;
        sm.sQh[i][q4 + 3] = *(__half2*)&qv.w;
    }
    if (tid < BI) sm.sBq[tid] = d_bq[hN + i0 + tid];
    for (int idx = tid; idx < BI * 64; idx += 256)
        sm.sAdj[idx >> 6][idx & 63] = d_adjb[(i0 + (idx >> 6)) * 64 + (idx & 63)];
    __syncthreads();

    int r = tid >> 5;           // warp id (owns i-rows 4r..4r+3)
    int c = tid & 31;           // lane
    int mh = r >> 2;            // PV mma: m-half
    int nq = r & 3;             // PV mma: n-quarter
    int l4 = c & 3;             // lane % 4

    // ---- kernel-lifetime register operands for logits mma ----
    unsigned qE[2][2], qEh[2][2], qO[2][2], qOh[2][2];  // [ig][slab]
    #pragma unroll
    for (int ig = 0; ig < 2; ++ig) {
        int iE = 4 * r + 2 * ig, iO = iE + 1;
        #pragma unroll
        for (int s = 0; s < 2; ++s) {
            qE[ig][s]  = *(unsigned*)&sm.sQh[iE][s * 8 + l4];
            qEh[ig][s] = *(unsigned*)&sm.sQh[iE][s * 8 + 4 + l4];
            qO[ig][s]  = *(unsigned*)&sm.sQh[iO][s * 8 + l4];
            qOh[ig][s] = *(unsigned*)&sm.sQh[iO][s * 8 + 4 + l4];
        }
    }
    unsigned bLo[2], bHi[2];
    #pragma unroll
    for (int s = 0; s < 2; ++s) {
        bLo[s] = *(const unsigned*)&d_afh2[h * 16 + s * 8 + l4];
        bHi[s] = *(const unsigned*)&d_afh2[h * 16 + s * 8 + 4 + l4];
    }
    unsigned kBase = (unsigned)__cvta_generic_to_shared(
        &sm.sKh[c & 7][((c & 15) >> 3) * 8]);
    unsigned aAddrBase = (unsigned)__cvta_generic_to_shared(
        &sm.sPh[mh * 16 + (c & 15)][(c >> 4) * 8]);
    unsigned bAddrBase = (unsigned)__cvta_generic_to_shared(
        &sm.sVh[c & 15][nq * 8]);
    const unsigned one2 = 0x3c003c00u;  // (1.0h, 1.0h)

    float psum[4] = {0.f, 0.f, 0.f, 0.f};
    float cacc0 = 0.f, cacc1 = 0.f, cacc2 = 0.f, cacc3 = 0.f;

    for (int jt = 0; jt < NJT; ++jt) {
        int j0 = jt * BJ;
        __syncthreads();  // prev tile fully consumed

        // ---- fill K tile [j][d] fp16 ----
        #pragma unroll
        for (int it = 0; it < 2; ++it) {
            int chunk = it * 256 + tid;
            int j = chunk >> 2, q8 = (chunk & 3) * 8;
            *(uint4*)&sm.sKh[j][q8] = *(const uint4*)&Kh2[(j0 + j) * 16 + (chunk & 3) * 4];
        }
        // ---- fill V tile [j][d] fp16 ----
        #pragma unroll
        for (int it = 0; it < 2; ++it) {
            int chunk = it * 256 + tid;
            int j = chunk >> 2, q8 = (chunk & 3) * 8;
            *(uint4*)&sm.sVh[j][q8] = *(const uint4*)&Vh[(j0 + j) * DK + q8];
        }
        if (tid < BJ) sm.sBk[tid] = d_bk[hN + j0 + tid];
        __syncthreads();

        // ---- logits: r = relu(k+q) fragments -> mma d-reduction (fp32) ----
        #pragma unroll 2
        for (int jg = 0; jg < 16; ++jg) {
            unsigned addr = kBase + jg * 640;
            unsigned kaL0, kaH0, kaL1, kaH1;
            ldm_x2(kaL0, kaH0, addr);
            ldm_x2(kaL1, kaH1, addr + 32);
            #pragma unroll
            for (int ig = 0; ig < 2; ++ig) {
                float c0 = 0.f, c1 = 0.f, c2v = 0.f, c3 = 0.f;
                // slab 0 (d 0..15)
                mma16816(c0, c1, c2v, c3,
                         hrelu_add(kaL0, qE[ig][0], one2),
                         hrelu_add(kaL0, qO[ig][0], one2),
                         hrelu_add(kaH0, qEh[ig][0], one2),
                         hrelu_add(kaH0, qOh[ig][0], one2),
                         bLo[0], bHi[0]);
                // slab 1 (d 16..31)
                mma16816(c0, c1, c2v, c3,
                         hrelu_add(kaL1, qE[ig][1], one2),
                         hrelu_add(kaL1, qO[ig][1], one2),
                         hrelu_add(kaH1, qEh[ig][1], one2),
                         hrelu_add(kaH1, qOh[ig][1], one2),
                         bLo[1], bHi[1]);
                int i0r = 4 * r + 2 * ig;
                int jj = jg * 8 + (c >> 2);
                if (l4 == 0) sm.sLog[i0r][jj] = c0;
                if (l4 == 1) sm.sLog[i0r + 1][jj] = c2v;
            }
        }
        __syncwarp();

        // ---- epilogue: bias, adjacency mask, exp2, fp16 P store, row partials ----
        {
            int wi = jt * 4 + (c >> 4);
            int b0 = (2 * c) & 31;
            float2 bk0 = *(const float2*)&sm.sBk[2 * c];
            float2 bk1 = *(const float2*)&sm.sBk[2 * c + 64];
            #pragma unroll
            for (int ii = 0; ii < 4; ++ii) {
                int i = 4 * r + ii;
                float bq = sm.sBq[i];
                float2 f0 = *(const float2*)&sm.sLog[i][2 * c];
                float2 f1 = *(const float2*)&sm.sLog[i][2 * c + 64];
                unsigned w0 = sm.sAdj[i][wi];
                unsigned w1 = sm.sAdj[i][wi + 2];
                float p00 = ((w0 >> b0) & 1u)       ? ex2f(f0.x + bq + bk0.x) : 0.f;
                float p01 = ((w0 >> (b0 + 1)) & 1u) ? ex2f(f0.y + bq + bk0.y) : 0.f;
                float p10 = ((w1 >> b0) & 1u)       ? ex2f(f1.x + bq + bk1.x) : 0.f;
                float p11 = ((w1 >> (b0 + 1)) & 1u) ? ex2f(f1.y + bq + bk1.y) : 0.f;
                psum[ii] += (p00 + p01) + (p10 + p11);
                *(__half2*)&sm.sPh[i][2 * c]      = __floats2half2_rn(p00, p01);
                *(__half2*)&sm.sPh[i][2 * c + 64] = __floats2half2_rn(p10, p11);
            }
        }
        __syncthreads();  // P tile complete

        // ---- PV via tensor cores: one m16n8 output tile per warp ----
        #pragma unroll
        for (int ks = 0; ks < 8; ++ks) {
            unsigned a0, a1, a2r, a3, b0r, b1r;
            ldm_x4(a0, a1, a2r, a3, aAddrBase + ks * 32);
            ldm_x2t(b0r, b1r, bAddrBase + ks * 16 * 80);
            mma16816(cacc0, cacc1, cacc2, cacc3, a0, a1, a2r, a3, b0r, b1r);
        }
    }

    // ---- row-sum reduction across lanes ----
    #pragma unroll
    for (int ii = 0; ii < 4; ++ii) {
        float v = psum[ii];
        v += __shfl_xor_sync(0xffffffffu, v, 16);
        v += __shfl_xor_sync(0xffffffffu, v, 8);
        v += __shfl_xor_sync(0xffffffffu, v, 4);
        v += __shfl_xor_sync(0xffffffffu, v, 2);
        v += __shfl_xor_sync(0xffffffffu, v, 1);
        if (c == 0) sm.sL[4 * r + ii] = v;
    }
    __syncthreads();

    // ---- normalize + store (c-fragment layout) ----
    {
        int row0 = mh * 16 + (c >> 2);
        int col0 = nq * 8 + 2 * (c & 3);
        float inv0 = 1.0f / sm.sL[row0];
        float inv1 = 1.0f / sm.sL[row0 + 8];
        *(float2*)&d_ao[(i0 + row0) * F + h * DK + col0] =
            make_float2(cacc0 * inv0, cacc1 * inv0);
        *(float2*)&d_ao[(i0 + row0 + 8) * F + h * DK + col0] =
            make_float2(cacc2 * inv1, cacc3 * inv1);
    }
}

// ---------------- K5: output projection + bias + residual ----------------
__global__ void __launch_bounds__(256) out_gemm(const float* __restrict__ Wo,
                                                const float* __restrict__ bo,
                                                const float* __restrict__ x,
                                                float* __restrict__ out) {
    __shared__ float sAT[32][132];
    __shared__ float sB[32][36];
    int tid = threadIdx.x;
    int bm0 = blockIdx.x * 128;
    int c0 = blockIdx.y * 32;
    int tm = tid >> 3, tn = tid & 7;
    float acc[4][4];
    #pragma unroll
    for (int i = 0; i < 4; ++i)
        #pragma unroll
        for (int j = 0; j < 4; ++j) acc[i][j] = 0.f;

    for (int k0 = 0; k0 < F; k0 += 32) {
        #pragma unroll
        for (int it = 0; it < 4; ++it) {
            int idx = it * 256 + tid;
            int row = idx >> 3, f4 = idx & 7;
            float4 av = *(const float4*)&d_ao[(bm0 + row) * F + k0 + 4 * f4];
            sAT[4 * f4 + 0][row] = av.x;
            sAT[4 * f4 + 1][row] = av.y;
            sAT[4 * f4 + 2][row] = av.z;
            sAT[4 * f4 + 3][row] = av.w;
        }
        {
            int kk = tid >> 3, d4 = tid & 7;
            *(float4*)&sB[kk][4 * d4] = *(const float4*)&Wo[(k0 + kk) * F + c0 + 4 * d4];
        }
        __syncthreads();
        #pragma unroll
        for (int kk = 0; kk < 32; ++kk) {
            float4 a4 = *(const float4*)&sAT[kk][4 * tm];
            float4 b4 = *(const float4*)&sB[kk][4 * tn];
            float av[4] = {a4.x, a4.y, a4.z, a4.w};
            float bv[4] = {b4.x, b4.y, b4.z, b4.w};
            #pragma unroll
            for (int i = 0; i < 4; ++i)
                #pragma unroll
                for (int j = 0; j < 4; ++j) acc[i][j] += av[i] * bv[j];
        }
        __syncthreads();
    }
    float4 bv4 = *(const float4*)&bo[c0 + 4 * tn];
    #pragma unroll
    for (int i = 0; i < 4; ++i) {
        int n = bm0 + 4 * tm + i;
        float4 xv = *(const float4*)&x[n * F + c0 + 4 * tn];
        float4 o = make_float4(acc[i][0] + bv4.x + xv.x, acc[i][1] + bv4.y + xv.y,
                               acc[i][2] + bv4.z + xv.z, acc[i][3] + bv4.w + xv.w);
        *(float4*)&out[n * F + c0 + 4 * tn] = o;
    }
}

// ---------------- launch ----------------
extern "C" void kernel_launch(void* const* d_in, const int* in_sizes, int n_in,
                              void* d_out, int out_size) {
    const float* x     = (const float*)d_in[0];
    const int*   adj   = (const int*)d_in[1];
    const float* Wq    = (const float*)d_in[2];
    const float* Wk    = (const float*)d_in[3];
    const float* Wv    = (const float*)d_in[4];
    const float* a     = (const float*)d_in[5];
    const float* Wo    = (const float*)d_in[6];
    const float* bo    = (const float*)d_in[7];
    const float* gamma = (const float*)d_in[8];
    const float* beta  = (const float*)d_in[9];
    float* out = (float*)d_out;

    cudaFuncSetAttribute(attn_kernel, cudaFuncAttributeMaxDynamicSharedMemorySize,
                         (int)sizeof(AttnSmem));

    pack_adj<<<(N_NODES * N_NODES / 4) / 256, 256>>>(adj, a);
    ln_kernel<<<N_NODES, 256>>>(x, gamma, beta);
    qkv_gemm<<<dim3(N_NODES / 128, 24), 256>>>(Wq, Wk, Wv, a);
    attn_kernel<<<dim3(N_NODES / BI, H), 256, sizeof(AttnSmem)>>>();
    out_gemm<<<dim3(N_NODES / 128, F / 32), 256>>>(Wo, bo, x, out);
}

// round 11
// speedup vs baseline: 1.8465x; 1.1174x over previous
#include <cuda_runtime.h>
#include <cuda_fp16.h>

#define N_NODES 2048
#define F 256
#define H 8
#define DK 32
#define ALPHA 0.2f
#define LN_EPS 1e-5f

typedef unsigned long long ull;

// ---------------- scratch (no allocations allowed) ----------------
__device__ __half d_hbufh[N_NODES * F];             // fp16 LN output
__device__ __half2 d_Qh2[H * N_NODES * (DK / 2)];   // fp16 Q, d-pairs
__device__ __half2 d_Kh2[H * N_NODES * (DK / 2)];   // fp16 K, d-pairs
__device__ __half  d_Vh[H * N_NODES * DK];          // fp16 V, [node][d]
__device__ float d_bq[H * N_NODES];
__device__ float d_bk[H * N_NODES];
__device__ __half2 d_afh2[H * (DK / 2)];            // a' d-pairs, a' = (1-α)·scale·log2e·a
__device__ unsigned d_adjb[N_NODES * (N_NODES / 32)];
__device__ float d_ao[N_NODES * F];

// ---------------- helpers ----------------
__device__ __forceinline__ float ex2f(float x) {
    float r; asm("ex2.approx.f32 %0, %1;" : "=f"(r) : "f"(x)); return r;
}
// fused relu(k + q) on half2 via fma.rn.relu.f16x2 (k*1 + q)
__device__ __forceinline__ unsigned hrelu_add(unsigned k, unsigned q, unsigned one2) {
    unsigned d;
    asm("fma.rn.relu.f16x2 %0, %1, %2, %3;"
        : "=r"(d) : "r"(k), "r"(one2), "r"(q));
    return d;
}
__device__ __forceinline__ void ldm_x2(unsigned& r0, unsigned& r1, unsigned addr) {
    asm volatile("ldmatrix.sync.aligned.m8n8.x2.shared.b16 {%0,%1}, [%2];"
                 : "=r"(r0), "=r"(r1) : "r"(addr));
}
__device__ __forceinline__ void ldm_x4(unsigned& a0, unsigned& a1, unsigned& a2,
                                       unsigned& a3, unsigned addr) {
    asm volatile("ldmatrix.sync.aligned.m8n8.x4.shared.b16 {%0,%1,%2,%3}, [%4];"
                 : "=r"(a0), "=r"(a1), "=r"(a2), "=r"(a3) : "r"(addr));
}
__device__ __forceinline__ void ldm_x2t(unsigned& b0, unsigned& b1, unsigned addr) {
    asm volatile("ldmatrix.sync.aligned.m8n8.x2.trans.shared.b16 {%0,%1}, [%2];"
                 : "=r"(b0), "=r"(b1) : "r"(addr));
}
__device__ __forceinline__ void mma16816(float& c0, float& c1, float& c2, float& c3,
                                         unsigned a0, unsigned a1, unsigned a2,
                                         unsigned a3, unsigned b0, unsigned b1) {
    asm volatile("mma.sync.aligned.m16n8k16.row.col.f32.f16.f16.f32 "
                 "{%0,%1,%2,%3}, {%4,%5,%6,%7}, {%8,%9}, {%0,%1,%2,%3};"
                 : "+f"(c0), "+f"(c1), "+f"(c2), "+f"(c3)
                 : "r"(a0), "r"(a1), "r"(a2), "r"(a3), "r"(b0), "r"(b1));
}

// ---------------- K1: pack adjacency (4 words/warp) + a' fold ----------------
__global__ void __launch_bounds__(256) pack_adj(const int* __restrict__ adj,
                                                const float* __restrict__ a) {
    int t = blockIdx.x * 256 + threadIdx.x;
    int warp = t >> 5, lane = t & 31;
    int base = warp * 128;
    unsigned m0 = __ballot_sync(0xffffffffu, adj[base + lane] != 0);
    unsigned m1 = __ballot_sync(0xffffffffu, adj[base + 32 + lane] != 0);
    unsigned m2 = __ballot_sync(0xffffffffu, adj[base + 64 + lane] != 0);
    unsigned m3 = __ballot_sync(0xffffffffu, adj[base + 96 + lane] != 0);
    if (lane == 0) *(uint4*)&d_adjb[warp * 4] = make_uint4(m0, m1, m2, m3);
    if (blockIdx.x == 0 && threadIdx.x < H * (DK / 2)) {
        const float C = (1.0f - ALPHA) * 0.17677669529663687f * 1.4426950408889634f;
        float2 av = *(const float2*)&a[2 * threadIdx.x];
        d_afh2[threadIdx.x] = __floats2half2_rn(C * av.x, C * av.y);
    }
}

// ---------------- K2: LayerNorm (fp16 output) ----------------
__global__ void __launch_bounds__(256) ln_kernel(const float* __restrict__ x,
                                                 const float* __restrict__ gamma,
                                                 const float* __restrict__ beta) {
    int row = blockIdx.x;
    int t = threadIdx.x;
    float v = x[row * F + t];
    float s = v, s2 = v * v;
    #pragma unroll
    for (int m = 16; m > 0; m >>= 1) {
        s  += __shfl_xor_sync(0xffffffffu, s, m);
        s2 += __shfl_xor_sync(0xffffffffu, s2, m);
    }
    __shared__ float ws[8], ws2[8];
    if ((t & 31) == 0) { ws[t >> 5] = s; ws2[t >> 5] = s2; }
    __syncthreads();
    float tot = 0.f, tot2 = 0.f;
    #pragma unroll
    for (int w = 0; w < 8; ++w) { tot += ws[w]; tot2 += ws2[w]; }
    float mu = tot * (1.0f / F);
    float var = tot2 * (1.0f / F) - mu * mu;
    float inv = rsqrtf(var + LN_EPS);
    d_hbufh[row * F + t] = __float2half((v - mu) * inv * gamma[t] + beta[t]);
}

// ---------------- K3: QKV projection via tensor-core mma ----------------
// grid(16, 24): y = which*8 + head. Block: 128 rows x 32 cols, 8 warps (16 rows each).
__global__ void __launch_bounds__(256) qkv_mma(const float* __restrict__ Wq,
                                               const float* __restrict__ Wk,
                                               const float* __restrict__ Wv,
                                               const float* __restrict__ a) {
    __shared__ __half sA[128][24];   // h tile [m][k16], pitch 24 halves
    __shared__ __half sB[16][40];    // W tile [k16][n32], pitch 40 halves
    int tid = threadIdx.x;
    int warp = tid >> 5, c = tid & 31;
    int bm0 = blockIdx.x * 128;
    int by = blockIdx.y;
    int which = by >> 3, hh = by & 7;
    const float* W = ((which == 0) ? Wq : (which == 1) ? Wk : Wv) + hh * (F * DK);

    float cc[4][4];
    #pragma unroll
    for (int nt = 0; nt < 4; ++nt)
        #pragma unroll
        for (int q = 0; q < 4; ++q) cc[nt][q] = 0.f;

    unsigned aAddr = (unsigned)__cvta_generic_to_shared(
        &sA[warp * 16 + (c & 15)][(c >> 4) * 8]);
    unsigned bAddrBase = (unsigned)__cvta_generic_to_shared(&sB[c & 15][0]);

    int arow = tid >> 1, aoff = (tid & 1) * 8;
    int bk = tid >> 4, bn = (tid & 15) * 2;

    for (int k0 = 0; k0 < F; k0 += 16) {
        __syncthreads();
        *(uint4*)&sA[arow][aoff] =
            *(const uint4*)&d_hbufh[(bm0 + arow) * F + k0 + aoff];
        {
            float2 wv = *(const float2*)&W[(k0 + bk) * DK + bn];
            *(__half2*)&sB[bk][bn] = __floats2half2_rn(wv.x, wv.y);
        }
        __syncthreads();
        unsigned a0, a1, a2, a3;
        ldm_x4(a0, a1, a2, a3, aAddr);
        #pragma unroll
        for (int nt = 0; nt < 4; ++nt) {
            unsigned b0, b1;
            ldm_x2t(b0, b1, bAddrBase + nt * 16);
            mma16816(cc[nt][0], cc[nt][1], cc[nt][2], cc[nt][3],
                     a0, a1, a2, a3, b0, b1);
        }
    }

    int r0 = bm0 + warp * 16 + (c >> 2);
    if (which == 2) {
        __half* dstV = d_Vh + hh * N_NODES * DK;
        #pragma unroll
        for (int nt = 0; nt < 4; ++nt) {
            int col0 = nt * 8 + 2 * (c & 3);
            *(__half2*)&dstV[r0 * DK + col0] = __floats2half2_rn(cc[nt][0], cc[nt][1]);
            *(__half2*)&dstV[(r0 + 8) * DK + col0] = __floats2half2_rn(cc[nt][2], cc[nt][3]);
        }
    } else {
        const float CC = ALPHA * 0.17677669529663687f * 1.4426950408889634f;
        __half2* dstH = ((which == 0) ? d_Qh2 : d_Kh2) + hh * N_NODES * 16;
        float* dstB = ((which == 0) ? d_bq : d_bk) + hh * N_NODES;
        float p0 = 0.f, p1 = 0.f;
        #pragma unroll
        for (int nt = 0; nt < 4; ++nt) {
            int col0 = nt * 8 + 2 * (c & 3);
            float a0v = a[hh * DK + col0];
            float a1v = a[hh * DK + col0 + 1];
            dstH[r0 * 16 + nt * 4 + (c & 3)] = __floats2half2_rn(cc[nt][0], cc[nt][1]);
            dstH[(r0 + 8) * 16 + nt * 4 + (c & 3)] = __floats2half2_rn(cc[nt][2], cc[nt][3]);
            p0 += a0v * cc[nt][0] + a1v * cc[nt][1];
            p1 += a0v * cc[nt][2] + a1v * cc[nt][3];
        }
        p0 += __shfl_xor_sync(0xffffffffu, p0, 1);
        p0 += __shfl_xor_sync(0xffffffffu, p0, 2);
        p1 += __shfl_xor_sync(0xffffffffu, p1, 1);
        p1 += __shfl_xor_sync(0xffffffffu, p1, 2);
        if ((c & 3) == 0) {
            dstB[r0] = CC * p0;
            dstB[r0 + 8] = CC * p1;
        }
    }
}

// ---------------- K4: fused GAT attention (mma logits + mma PV) ----------------
#define BI 32
#define BJ 128
#define NJT (N_NODES / BJ)

struct AttnSmem {
    __half  sPh[BI][136];      // P fp16 - 8.5KB
    __half  sVh[BJ][40];       // V fp16 [j][d] - 10KB
    __half  sKh[BJ][40];       // K fp16 [j][d] - 10KB
    float   sLog[BI][128];     // fp32 logits (pre-bias) - 16KB
    __half2 sQh[BI][17];       // Q [i][d2] - 2.2KB
    unsigned sAdj[BI][64];     // 8KB
    float   sBq[BI];
    float   sBk[BJ];
    float   sL[BI];
};

__global__ void __launch_bounds__(256, 4) attn_kernel() {
    extern __shared__ char smem_raw[];
    AttnSmem& sm = *reinterpret_cast<AttnSmem*>(smem_raw);
    int tid = threadIdx.x;
    int h = blockIdx.y;
    int i0 = blockIdx.x * BI;
    int hN = h * N_NODES;
    const __half2* Qh2 = d_Qh2 + hN * 16;
    const __half2* Kh2 = d_Kh2 + hN * 16;
    const __half*  Vh  = d_Vh + hN * DK;

    // ---- prologue: Q tile, adjacency, bases ----
    if (tid < 128) {
        int i = tid >> 2, q4 = (tid & 3) * 4;
        uint4 qv = *(const uint4*)&Qh2[(i0 + i) * 16 + q4];
        sm.sQh[i][q4 + 0] = *(__half2*)&qv.x;
        sm.sQh[i][q4 + 1] = *(__half2*)&qv.y;
        sm.sQh[i][q4 + 2] = *(__half2*)&qv.z;
        sm.sQh[i][q4 + 3] = *(__half2*)&qv.w;
    }
    if (tid < BI) sm.sBq[tid] = d_bq[hN + i0 + tid];
    for (int idx = tid; idx < BI * 64; idx += 256)
        sm.sAdj[idx >> 6][idx & 63] = d_adjb[(i0 + (idx >> 6)) * 64 + (idx & 63)];
    __syncthreads();

    int r = tid >> 5;           // warp id (owns i-rows 4r..4r+3)
    int c = tid & 31;           // lane
    int mh = r >> 2;            // PV mma: m-half
    int nq = r & 3;             // PV mma: n-quarter
    int l4 = c & 3;             // lane % 4

    // ---- kernel-lifetime register operands for logits mma ----
    unsigned qE[2][2], qEh[2][2], qO[2][2], qOh[2][2];  // [ig][slab]
    #pragma unroll
    for (int ig = 0; ig < 2; ++ig) {
        int iE = 4 * r + 2 * ig, iO = iE + 1;
        #pragma unroll
        for (int s = 0; s < 2; ++s) {
            qE[ig][s]  = *(unsigned*)&sm.sQh[iE][s * 8 + l4];
            qEh[ig][s] = *(unsigned*)&sm.sQh[iE][s * 8 + 4 + l4];
            qO[ig][s]  = *(unsigned*)&sm.sQh[iO][s * 8 + l4];
            qOh[ig][s] = *(unsigned*)&sm.sQh[iO][s * 8 + 4 + l4];
        }
    }
    unsigned bLo[2], bHi[2];
    #pragma unroll
    for (int s = 0; s < 2; ++s) {
        bLo[s] = *(const unsigned*)&d_afh2[h * 16 + s * 8 + l4];
        bHi[s] = *(const unsigned*)&d_afh2[h * 16 + s * 8 + 4 + l4];
    }
    unsigned kBase = (unsigned)__cvta_generic_to_shared(
        &sm.sKh[c & 7][((c & 15) >> 3) * 8]);
    unsigned aAddrBase = (unsigned)__cvta_generic_to_shared(
        &sm.sPh[mh * 16 + (c & 15)][(c >> 4) * 8]);
    unsigned bAddrBase = (unsigned)__cvta_generic_to_shared(
        &sm.sVh[c & 15][nq * 8]);
    const unsigned one2 = 0x3c003c00u;  // (1.0h, 1.0h)

    float psum[4] = {0.f, 0.f, 0.f, 0.f};
    float cacc0 = 0.f, cacc1 = 0.f, cacc2 = 0.f, cacc3 = 0.f;

    for (int jt = 0; jt < NJT; ++jt) {
        int j0 = jt * BJ;
        __syncthreads();  // prev tile fully consumed

        // ---- fill K tile [j][d] fp16 ----
        #pragma unroll
        for (int it = 0; it < 2; ++it) {
            int chunk = it * 256 + tid;
            int j = chunk >> 2, q8 = (chunk & 3) * 8;
            *(uint4*)&sm.sKh[j][q8] = *(const uint4*)&Kh2[(j0 + j) * 16 + (chunk & 3) * 4];
        }
        // ---- fill V tile [j][d] fp16 ----
        #pragma unroll
        for (int it = 0; it < 2; ++it) {
            int chunk = it * 256 + tid;
            int j = chunk >> 2, q8 = (chunk & 3) * 8;
            *(uint4*)&sm.sVh[j][q8] = *(const uint4*)&Vh[(j0 + j) * DK + q8];
        }
        if (tid < BJ) sm.sBk[tid] = d_bk[hN + j0 + tid];
        __syncthreads();

        // ---- logits: r = relu(k+q) fragments -> mma d-reduction (fp32) ----
        #pragma unroll 2
        for (int jg = 0; jg < 16; ++jg) {
            unsigned addr = kBase + jg * 640;
            unsigned kaL0, kaH0, kaL1, kaH1;
            ldm_x2(kaL0, kaH0, addr);
            ldm_x2(kaL1, kaH1, addr + 32);
            #pragma unroll
            for (int ig = 0; ig < 2; ++ig) {
                float c0 = 0.f, c1 = 0.f, c2v = 0.f, c3 = 0.f;
                mma16816(c0, c1, c2v, c3,
                         hrelu_add(kaL0, qE[ig][0], one2),
                         hrelu_add(kaL0, qO[ig][0], one2),
                         hrelu_add(kaH0, qEh[ig][0], one2),
                         hrelu_add(kaH0, qOh[ig][0], one2),
                         bLo[0], bHi[0]);
                mma16816(c0, c1, c2v, c3,
                         hrelu_add(kaL1, qE[ig][1], one2),
                         hrelu_add(kaL1, qO[ig][1], one2),
                         hrelu_add(kaH1, qEh[ig][1], one2),
                         hrelu_add(kaH1, qOh[ig][1], one2),
                         bLo[1], bHi[1]);
                int i0r = 4 * r + 2 * ig;
                int jj = jg * 8 + (c >> 2);
                if (l4 == 0) sm.sLog[i0r][jj] = c0;
                if (l4 == 1) sm.sLog[i0r + 1][jj] = c2v;
            }
        }
        __syncwarp();

        // ---- epilogue: bias, adjacency mask, exp2, fp16 P store, row partials ----
        {
            int wi = jt * 4 + (c >> 4);
            int b0 = (2 * c) & 31;
            float2 bk0 = *(const float2*)&sm.sBk[2 * c];
            float2 bk1 = *(const float2*)&sm.sBk[2 * c + 64];
            #pragma unroll
            for (int ii = 0; ii < 4; ++ii) {
                int i = 4 * r + ii;
                float bq = sm.sBq[i];
                float2 f0 = *(const float2*)&sm.sLog[i][2 * c];
                float2 f1 = *(const float2*)&sm.sLog[i][2 * c + 64];
                unsigned w0 = sm.sAdj[i][wi];
                unsigned w1 = sm.sAdj[i][wi + 2];
                float p00 = ((w0 >> b0) & 1u)       ? ex2f(f0.x + bq + bk0.x) : 0.f;
                float p01 = ((w0 >> (b0 + 1)) & 1u) ? ex2f(f0.y + bq + bk0.y) : 0.f;
                float p10 = ((w1 >> b0) & 1u)       ? ex2f(f1.x + bq + bk1.x) : 0.f;
                float p11 = ((w1 >> (b0 + 1)) & 1u) ? ex2f(f1.y + bq + bk1.y) : 0.f;
                psum[ii] += (p00 + p01) + (p10 + p11);
                *(__half2*)&sm.sPh[i][2 * c]      = __floats2half2_rn(p00, p01);
                *(__half2*)&sm.sPh[i][2 * c + 64] = __floats2half2_rn(p10, p11);
            }
        }
        __syncthreads();  // P tile complete

        // ---- PV via tensor cores: one m16n8 output tile per warp ----
        #pragma unroll
        for (int ks = 0; ks < 8; ++ks) {
            unsigned a0, a1, a2r, a3, b0r, b1r;
            ldm_x4(a0, a1, a2r, a3, aAddrBase + ks * 32);
            ldm_x2t(b0r, b1r, bAddrBase + ks * 16 * 80);
            mma16816(cacc0, cacc1, cacc2, cacc3, a0, a1, a2r, a3, b0r, b1r);
        }
    }

    // ---- row-sum reduction across lanes ----
    #pragma unroll
    for (int ii = 0; ii < 4; ++ii) {
        float v = psum[ii];
        v += __shfl_xor_sync(0xffffffffu, v, 16);
        v += __shfl_xor_sync(0xffffffffu, v, 8);
        v += __shfl_xor_sync(0xffffffffu, v, 4);
        v += __shfl_xor_sync(0xffffffffu, v, 2);
        v += __shfl_xor_sync(0xffffffffu, v, 1);
        if (c == 0) sm.sL[4 * r + ii] = v;
    }
    __syncthreads();

    // ---- normalize + store (c-fragment layout) ----
    {
        int row0 = mh * 16 + (c >> 2);
        int col0 = nq * 8 + 2 * (c & 3);
        float inv0 = 1.0f / sm.sL[row0];
        float inv1 = 1.0f / sm.sL[row0 + 8];
        *(float2*)&d_ao[(i0 + row0) * F + h * DK + col0] =
            make_float2(cacc0 * inv0, cacc1 * inv0);
        *(float2*)&d_ao[(i0 + row0 + 8) * F + h * DK + col0] =
            make_float2(cacc2 * inv1, cacc3 * inv1);
    }
}

// ---------------- K5: output projection + bias + residual (fp32) ----------------
__global__ void __launch_bounds__(256) out_gemm(const float* __restrict__ Wo,
                                                const float* __restrict__ bo,
                                                const float* __restrict__ x,
                                                float* __restrict__ out) {
    __shared__ float sAT[32][132];
    __shared__ float sB[32][36];
    int tid = threadIdx.x;
    int bm0 = blockIdx.x * 128;
    int c0 = blockIdx.y * 32;
    int tm = tid >> 3, tn = tid & 7;
    float acc[4][4];
    #pragma unroll
    for (int i = 0; i < 4; ++i)
        #pragma unroll
        for (int j = 0; j < 4; ++j) acc[i][j] = 0.f;

    for (int k0 = 0; k0 < F; k0 += 32) {
        #pragma unroll
        for (int it = 0; it < 4; ++it) {
            int idx = it * 256 + tid;
            int row = idx >> 3, f4 = idx & 7;
            float4 av = *(const float4*)&d_ao[(bm0 + row) * F + k0 + 4 * f4];
            sAT[4 * f4 + 0][row] = av.x;
            sAT[4 * f4 + 1][row] = av.y;
            sAT[4 * f4 + 2][row] = av.z;
            sAT[4 * f4 + 3][row] = av.w;
        }
        {
            int kk = tid >> 3, d4 = tid & 7;
            *(float4*)&sB[kk][4 * d4] = *(const float4*)&Wo[(k0 + kk) * F + c0 + 4 * d4];
        }
        __syncthreads();
        #pragma unroll
        for (int kk = 0; kk < 32; ++kk) {
            float4 a4 = *(const float4*)&sAT[kk][4 * tm];
            float4 b4 = *(const float4*)&sB[kk][4 * tn];
            float av[4] = {a4.x, a4.y, a4.z, a4.w};
            float bv[4] = {b4.x, b4.y, b4.z, b4.w};
            #pragma unroll
            for (int i = 0; i < 4; ++i)
                #pragma unroll
                for (int j = 0; j < 4; ++j) acc[i][j] += av[i] * bv[j];
        }
        __syncthreads();
    }
    float4 bv4 = *(const float4*)&bo[c0 + 4 * tn];
    #pragma unroll
    for (int i = 0; i < 4; ++i) {
        int n = bm0 + 4 * tm + i;
        float4 xv = *(const float4*)&x[n * F + c0 + 4 * tn];
        float4 o = make_float4(acc[i][0] + bv4.x + xv.x, acc[i][1] + bv4.y + xv.y,
                               acc[i][2] + bv4.z + xv.z, acc[i][3] + bv4.w + xv.w);
        *(float4*)&out[n * F + c0 + 4 * tn] = o;
    }
}

// ---------------- launch ----------------
extern "C" void kernel_launch(void* const* d_in, const int* in_sizes, int n_in,
                              void* d_out, int out_size) {
    const float* x     = (const float*)d_in[0];
    const int*   adj   = (const int*)d_in[1];
    const float* Wq    = (const float*)d_in[2];
    const float* Wk    = (const float*)d_in[3];
    const float* Wv    = (const float*)d_in[4];
    const float* a     = (const float*)d_in[5];
    const float* Wo    = (const float*)d_in[6];
    const float* bo    = (const float*)d_in[7];
    const float* gamma = (const float*)d_in[8];
    const float* beta  = (const float*)d_in[9];
    float* out = (float*)d_out;

    cudaFuncSetAttribute(attn_kernel, cudaFuncAttributeMaxDynamicSharedMemorySize,
                         (int)sizeof(AttnSmem));

    pack_adj<<<(N_NODES * N_NODES / 4) / 256, 256>>>(adj, a);
    ln_kernel<<<N_NODES, 256>>>(x, gamma, beta);
    qkv_mma<<<dim3(N_NODES / 128, 24), 256>>>(Wq, Wk, Wv, a);
    attn_kernel<<<dim3(N_NODES / BI, H), 256, sizeof(AttnSmem)>>>();
    out_gemm<<<dim3(N_NODES / 128, F / 32), 256>>>(Wo, bo, x, out);
}

// round 12
// speedup vs baseline: 1.8682x; 1.0117x over previous
#include <cuda_runtime.h>
#include <cuda_fp16.h>

#define N_NODES 2048
#define F 256
#define H 8
#define DK 32
#define ALPHA 0.2f
#define LN_EPS 1e-5f

typedef unsigned long long ull;

// ---------------- scratch (no allocations allowed) ----------------
__device__ __half d_hbufh[N_NODES * F];             // fp16 LN output
__device__ __half2 d_Qh2[H * N_NODES * (DK / 2)];   // fp16 Q, d-pairs
__device__ __half2 d_Kh2[H * N_NODES * (DK / 2)];   // fp16 K, d-pairs
__device__ __half  d_Vh[H * N_NODES * DK];          // fp16 V, [node][d]
__device__ float d_bq[H * N_NODES];
__device__ float d_bk[H * N_NODES];
__device__ __half2 d_afh2[H * (DK / 2)];            // a' d-pairs, a' = (1-α)·scale·log2e·a
__device__ unsigned d_adjb[N_NODES * (N_NODES / 32)];
__device__ __half d_aoh[N_NODES * F];               // fp16 attention output

// ---------------- helpers ----------------
__device__ __forceinline__ float ex2f(float x) {
    float r; asm("ex2.approx.f32 %0, %1;" : "=f"(r) : "f"(x)); return r;
}
// fused relu(k + q) on half2 via fma.rn.relu.f16x2 (k*1 + q)
__device__ __forceinline__ unsigned hrelu_add(unsigned k, unsigned q, unsigned one2) {
    unsigned d;
    asm("fma.rn.relu.f16x2 %0, %1, %2, %3;"
        : "=r"(d) : "r"(k), "r"(one2), "r"(q));
    return d;
}
__device__ __forceinline__ void ldm_x2(unsigned& r0, unsigned& r1, unsigned addr) {
    asm volatile("ldmatrix.sync.aligned.m8n8.x2.shared.b16 {%0,%1}, [%2];"
                 : "=r"(r0), "=r"(r1) : "r"(addr));
}
__device__ __forceinline__ void ldm_x4(unsigned& a0, unsigned& a1, unsigned& a2,
                                       unsigned& a3, unsigned addr) {
    asm volatile("ldmatrix.sync.aligned.m8n8.x4.shared.b16 {%0,%1,%2,%3}, [%4];"
                 : "=r"(a0), "=r"(a1), "=r"(a2), "=r"(a3) : "r"(addr));
}
__device__ __forceinline__ void ldm_x2t(unsigned& b0, unsigned& b1, unsigned addr) {
    asm volatile("ldmatrix.sync.aligned.m8n8.x2.trans.shared.b16 {%0,%1}, [%2];"
                 : "=r"(b0), "=r"(b1) : "r"(addr));
}
__device__ __forceinline__ void mma16816(float& c0, float& c1, float& c2, float& c3,
                                         unsigned a0, unsigned a1, unsigned a2,
                                         unsigned a3, unsigned b0, unsigned b1) {
    asm volatile("mma.sync.aligned.m16n8k16.row.col.f32.f16.f16.f32 "
                 "{%0,%1,%2,%3}, {%4,%5,%6,%7}, {%8,%9}, {%0,%1,%2,%3};"
                 : "+f"(c0), "+f"(c1), "+f"(c2), "+f"(c3)
                 : "r"(a0), "r"(a1), "r"(a2), "r"(a3), "r"(b0), "r"(b1));
}

// ---------------- K1: pack adjacency (4 words/warp) + a' fold ----------------
__global__ void __launch_bounds__(256) pack_adj(const int* __restrict__ adj,
                                                const float* __restrict__ a) {
    int t = blockIdx.x * 256 + threadIdx.x;
    int warp = t >> 5, lane = t & 31;
    int base = warp * 128;
    unsigned m0 = __ballot_sync(0xffffffffu, adj[base + lane] != 0);
    unsigned m1 = __ballot_sync(0xffffffffu, adj[base + 32 + lane] != 0);
    unsigned m2 = __ballot_sync(0xffffffffu, adj[base + 64 + lane] != 0);
    unsigned m3 = __ballot_sync(0xffffffffu, adj[base + 96 + lane] != 0);
    if (lane == 0) *(uint4*)&d_adjb[warp * 4] = make_uint4(m0, m1, m2, m3);
    if (blockIdx.x == 0 && threadIdx.x < H * (DK / 2)) {
        const float C = (1.0f - ALPHA) * 0.17677669529663687f * 1.4426950408889634f;
        float2 av = *(const float2*)&a[2 * threadIdx.x];
        d_afh2[threadIdx.x] = __floats2half2_rn(C * av.x, C * av.y);
    }
}

// ---------------- K2: LayerNorm (fp16 output) ----------------
__global__ void __launch_bounds__(256) ln_kernel(const float* __restrict__ x,
                                                 const float* __restrict__ gamma,
                                                 const float* __restrict__ beta) {
    int row = blockIdx.x;
    int t = threadIdx.x;
    float v = x[row * F + t];
    float s = v, s2 = v * v;
    #pragma unroll
    for (int m = 16; m > 0; m >>= 1) {
        s  += __shfl_xor_sync(0xffffffffu, s, m);
        s2 += __shfl_xor_sync(0xffffffffu, s2, m);
    }
    __shared__ float ws[8], ws2[8];
    if ((t & 31) == 0) { ws[t >> 5] = s; ws2[t >> 5] = s2; }
    __syncthreads();
    float tot = 0.f, tot2 = 0.f;
    #pragma unroll
    for (int w = 0; w < 8; ++w) { tot += ws[w]; tot2 += ws2[w]; }
    float mu = tot * (1.0f / F);
    float var = tot2 * (1.0f / F) - mu * mu;
    float inv = rsqrtf(var + LN_EPS);
    d_hbufh[row * F + t] = __float2half((v - mu) * inv * gamma[t] + beta[t]);
}

// ---------------- K3: QKV projection via tensor-core mma ----------------
__global__ void __launch_bounds__(256) qkv_mma(const float* __restrict__ Wq,
                                               const float* __restrict__ Wk,
                                               const float* __restrict__ Wv,
                                               const float* __restrict__ a) {
    __shared__ __half sA[128][24];   // h tile [m][k16], pitch 24 halves
    __shared__ __half sB[16][40];    // W tile [k16][n32], pitch 40 halves
    int tid = threadIdx.x;
    int warp = tid >> 5, c = tid & 31;
    int bm0 = blockIdx.x * 128;
    int by = blockIdx.y;
    int which = by >> 3, hh = by & 7;
    const float* W = ((which == 0) ? Wq : (which == 1) ? Wk : Wv) + hh * (F * DK);

    float cc[4][4];
    #pragma unroll
    for (int nt = 0; nt < 4; ++nt)
        #pragma unroll
        for (int q = 0; q < 4; ++q) cc[nt][q] = 0.f;

    unsigned aAddr = (unsigned)__cvta_generic_to_shared(
        &sA[warp * 16 + (c & 15)][(c >> 4) * 8]);
    unsigned bAddrBase = (unsigned)__cvta_generic_to_shared(&sB[c & 15][0]);

    int arow = tid >> 1, aoff = (tid & 1) * 8;
    int bk = tid >> 4, bn = (tid & 15) * 2;

    for (int k0 = 0; k0 < F; k0 += 16) {
        __syncthreads();
        *(uint4*)&sA[arow][aoff] =
            *(const uint4*)&d_hbufh[(bm0 + arow) * F + k0 + aoff];
        {
            float2 wv = *(const float2*)&W[(k0 + bk) * DK + bn];
            *(__half2*)&sB[bk][bn] = __floats2half2_rn(wv.x, wv.y);
        }
        __syncthreads();
        unsigned a0, a1, a2, a3;
        ldm_x4(a0, a1, a2, a3, aAddr);
        #pragma unroll
        for (int nt = 0; nt < 4; ++nt) {
            unsigned b0, b1;
            ldm_x2t(b0, b1, bAddrBase + nt * 16);
            mma16816(cc[nt][0], cc[nt][1], cc[nt][2], cc[nt][3],
                     a0, a1, a2, a3, b0, b1);
        }
    }

    int r0 = bm0 + warp * 16 + (c >> 2);
    if (which == 2) {
        __half* dstV = d_Vh + hh * N_NODES * DK;
        #pragma unroll
        for (int nt = 0; nt < 4; ++nt) {
            int col0 = nt * 8 + 2 * (c & 3);
            *(__half2*)&dstV[r0 * DK + col0] = __floats2half2_rn(cc[nt][0], cc[nt][1]);
            *(__half2*)&dstV[(r0 + 8) * DK + col0] = __floats2half2_rn(cc[nt][2], cc[nt][3]);
        }
    } else {
        const float CC = ALPHA * 0.17677669529663687f * 1.4426950408889634f;
        __half2* dstH = ((which == 0) ? d_Qh2 : d_Kh2) + hh * N_NODES * 16;
        float* dstB = ((which == 0) ? d_bq : d_bk) + hh * N_NODES;
        float p0 = 0.f, p1 = 0.f;
        #pragma unroll
        for (int nt = 0; nt < 4; ++nt) {
            int col0 = nt * 8 + 2 * (c & 3);
            float a0v = a[hh * DK + col0];
            float a1v = a[hh * DK + col0 + 1];
            dstH[r0 * 16 + nt * 4 + (c & 3)] = __floats2half2_rn(cc[nt][0], cc[nt][1]);
            dstH[(r0 + 8) * 16 + nt * 4 + (c & 3)] = __floats2half2_rn(cc[nt][2], cc[nt][3]);
            p0 += a0v * cc[nt][0] + a1v * cc[nt][1];
            p1 += a0v * cc[nt][2] + a1v * cc[nt][3];
        }
        p0 += __shfl_xor_sync(0xffffffffu, p0, 1);
        p0 += __shfl_xor_sync(0xffffffffu, p0, 2);
        p1 += __shfl_xor_sync(0xffffffffu, p1, 1);
        p1 += __shfl_xor_sync(0xffffffffu, p1, 2);
        if ((c & 3) == 0) {
            dstB[r0] = CC * p0;
            dstB[r0 + 8] = CC * p1;
        }
    }
}

// ---------------- K4: fused GAT attention (mma logits + mma PV) ----------------
#define BI 32
#define BJ 128
#define NJT (N_NODES / BJ)

struct AttnSmem {
    __half  sPh[BI][136];      // P fp16 - 8.5KB
    __half  sVh[BJ][40];       // V fp16 [j][d] - 10KB
    __half  sKh[BJ][40];       // K fp16 [j][d] - 10KB
    float   sLog[BI][128];     // fp32 logits (pre-bias) - 16KB
    __half2 sQh[BI][17];       // Q [i][d2] - 2.2KB
    unsigned sAdj[BI][64];     // 8KB
    float   sBq[BI];
    float   sBk[BJ];
    float   sL[BI];
};

__global__ void __launch_bounds__(256, 4) attn_kernel() {
    extern __shared__ char smem_raw[];
    AttnSmem& sm = *reinterpret_cast<AttnSmem*>(smem_raw);
    int tid = threadIdx.x;
    int h = blockIdx.y;
    int i0 = blockIdx.x * BI;
    int hN = h * N_NODES;
    const __half2* Qh2 = d_Qh2 + hN * 16;
    const __half2* Kh2 = d_Kh2 + hN * 16;
    const __half*  Vh  = d_Vh + hN * DK;

    // ---- prologue: Q tile, adjacency, bases ----
    if (tid < 128) {
        int i = tid >> 2, q4 = (tid & 3) * 4;
        uint4 qv = *(const uint4*)&Qh2[(i0 + i) * 16 + q4];
        sm.sQh[i][q4 + 0] = *(__half2*)&qv.x;
        sm.sQh[i][q4 + 1] = *(__half2*)&qv.y;
        sm.sQh[i][q4 + 2] = *(__half2*)&qv.z;
        sm.sQh[i][q4 + 3] = *(__half2*)&qv.w;
    }
    if (tid < BI) sm.sBq[tid] = d_bq[hN + i0 + tid];
    for (int idx = tid; idx < BI * 64; idx += 256)
        sm.sAdj[idx >> 6][idx & 63] = d_adjb[(i0 + (idx >> 6)) * 64 + (idx & 63)];
    __syncthreads();

    int r = tid >> 5;           // warp id (owns i-rows 4r..4r+3)
    int c = tid & 31;           // lane
    int mh = r >> 2;            // PV mma: m-half
    int nq = r & 3;             // PV mma: n-quarter
    int l4 = c & 3;             // lane % 4

    // ---- kernel-lifetime register operands for logits mma ----
    unsigned qE[2][2], qEh[2][2], qO[2][2], qOh[2][2];  // [ig][slab]
    #pragma unroll
    for (int ig = 0; ig < 2; ++ig) {
        int iE = 4 * r + 2 * ig, iO = iE + 1;
        #pragma unroll
        for (int s = 0; s < 2; ++s) {
            qE[ig][s]  = *(unsigned*)&sm.sQh[iE][s * 8 + l4];
            qEh[ig][s] = *(unsigned*)&sm.sQh[iE][s * 8 + 4 + l4];
            qO[ig][s]  = *(unsigned*)&sm.sQh[iO][s * 8 + l4];
            qOh[ig][s] = *(unsigned*)&sm.sQh[iO][s * 8 + 4 + l4];
        }
    }
    unsigned bLo[2], bHi[2];
    #pragma unroll
    for (int s = 0; s < 2; ++s) {
        bLo[s] = *(const unsigned*)&d_afh2[h * 16 + s * 8 + l4];
        bHi[s] = *(const unsigned*)&d_afh2[h * 16 + s * 8 + 4 + l4];
    }
    unsigned kBase = (unsigned)__cvta_generic_to_shared(
        &sm.sKh[c & 7][((c & 15) >> 3) * 8]);
    unsigned aAddrBase = (unsigned)__cvta_generic_to_shared(
        &sm.sPh[mh * 16 + (c & 15)][(c >> 4) * 8]);
    unsigned bAddrBase = (unsigned)__cvta_generic_to_shared(
        &sm.sVh[c & 15][nq * 8]);
    const unsigned one2 = 0x3c003c00u;  // (1.0h, 1.0h)

    float psum[4] = {0.f, 0.f, 0.f, 0.f};
    float cacc0 = 0.f, cacc1 = 0.f, cacc2 = 0.f, cacc3 = 0.f;

    for (int jt = 0; jt < NJT; ++jt) {
        int j0 = jt * BJ;
        __syncthreads();  // prev tile fully consumed

        // ---- fill K tile [j][d] fp16 ----
        #pragma unroll
        for (int it = 0; it < 2; ++it) {
            int chunk = it * 256 + tid;
            int j = chunk >> 2, q8 = (chunk & 3) * 8;
            *(uint4*)&sm.sKh[j][q8] = *(const uint4*)&Kh2[(j0 + j) * 16 + (chunk & 3) * 4];
        }
        // ---- fill V tile [j][d] fp16 ----
        #pragma unroll
        for (int it = 0; it < 2; ++it) {
            int chunk = it * 256 + tid;
            int j = chunk >> 2, q8 = (chunk & 3) * 8;
            *(uint4*)&sm.sVh[j][q8] = *(const uint4*)&Vh[(j0 + j) * DK + q8];
        }
        if (tid < BJ) sm.sBk[tid] = d_bk[hN + j0 + tid];
        __syncthreads();

        // ---- logits: r = relu(k+q) fragments -> mma d-reduction (fp32) ----
        #pragma unroll 2
        for (int jg = 0; jg < 16; ++jg) {
            unsigned addr = kBase + jg * 640;
            unsigned kaL0, kaH0, kaL1, kaH1;
            ldm_x2(kaL0, kaH0, addr);
            ldm_x2(kaL1, kaH1, addr + 32);
            #pragma unroll
            for (int ig = 0; ig < 2; ++ig) {
                float c0 = 0.f, c1 = 0.f, c2v = 0.f, c3 = 0.f;
                mma16816(c0, c1, c2v, c3,
                         hrelu_add(kaL0, qE[ig][0], one2),
                         hrelu_add(kaL0, qO[ig][0], one2),
                         hrelu_add(kaH0, qEh[ig][0], one2),
                         hrelu_add(kaH0, qOh[ig][0], one2),
                         bLo[0], bHi[0]);
                mma16816(c0, c1, c2v, c3,
                         hrelu_add(kaL1, qE[ig][1], one2),
                         hrelu_add(kaL1, qO[ig][1], one2),
                         hrelu_add(kaH1, qEh[ig][1], one2),
                         hrelu_add(kaH1, qOh[ig][1], one2),
                         bLo[1], bHi[1]);
                int i0r = 4 * r + 2 * ig;
                int jj = jg * 8 + (c >> 2);
                if (l4 == 0) sm.sLog[i0r][jj] = c0;
                if (l4 == 1) sm.sLog[i0r + 1][jj] = c2v;
            }
        }
        __syncwarp();

        // ---- epilogue (vectorized): lane owns 4 contiguous cols 4c..4c+3 ----
        {
            int col = 4 * c;
            int wi = jt * 4 + (c >> 3);
            int sh = col & 31;
            float4 bk4 = *(const float4*)&sm.sBk[col];
            #pragma unroll
            for (int ii = 0; ii < 4; ++ii) {
                int i = 4 * r + ii;
                float bq = sm.sBq[i];
                float4 lg = *(const float4*)&sm.sLog[i][col];
                unsigned w = sm.sAdj[i][wi] >> sh;
                float p0 = (w & 1u) ? ex2f(lg.x + bq + bk4.x) : 0.f;
                float p1 = (w & 2u) ? ex2f(lg.y + bq + bk4.y) : 0.f;
                float p2 = (w & 4u) ? ex2f(lg.z + bq + bk4.z) : 0.f;
                float p3 = (w & 8u) ? ex2f(lg.w + bq + bk4.w) : 0.f;
                psum[ii] += (p0 + p1) + (p2 + p3);
                __half2 h0 = __floats2half2_rn(p0, p1);
                __half2 h1 = __floats2half2_rn(p2, p3);
                uint2 pk;
                pk.x = *(unsigned*)&h0;
                pk.y = *(unsigned*)&h1;
                *(uint2*)&sm.sPh[i][col] = pk;
            }
        }
        __syncthreads();  // P tile complete

        // ---- PV via tensor cores: one m16n8 output tile per warp ----
        #pragma unroll
        for (int ks = 0; ks < 8; ++ks) {
            unsigned a0, a1, a2r, a3, b0r, b1r;
            ldm_x4(a0, a1, a2r, a3, aAddrBase + ks * 32);
            ldm_x2t(b0r, b1r, bAddrBase + ks * 16 * 80);
            mma16816(cacc0, cacc1, cacc2, cacc3, a0, a1, a2r, a3, b0r, b1r);
        }
    }

    // ---- row-sum reduction across lanes ----
    #pragma unroll
    for (int ii = 0; ii < 4; ++ii) {
        float v = psum[ii];
        v += __shfl_xor_sync(0xffffffffu, v, 16);
        v += __shfl_xor_sync(0xffffffffu, v, 8);
        v += __shfl_xor_sync(0xffffffffu, v, 4);
        v += __shfl_xor_sync(0xffffffffu, v, 2);
        v += __shfl_xor_sync(0xffffffffu, v, 1);
        if (c == 0) sm.sL[4 * r + ii] = v;
    }
    __syncthreads();

    // ---- normalize + store fp16 (c-fragment layout) ----
    {
        int row0 = mh * 16 + (c >> 2);
        int col0 = nq * 8 + 2 * (c & 3);
        float inv0 = 1.0f / sm.sL[row0];
        float inv1 = 1.0f / sm.sL[row0 + 8];
        *(__half2*)&d_aoh[(i0 + row0) * F + h * DK + col0] =
            __floats2half2_rn(cacc0 * inv0, cacc1 * inv0);
        *(__half2*)&d_aoh[(i0 + row0 + 8) * F + h * DK + col0] =
            __floats2half2_rn(cacc2 * inv1, cacc3 * inv1);
    }
}

// ---------------- K5: output projection via tensor-core mma ----------------
// grid(16, 8): bm0 = bx*128 rows, c0 = by*32 cols. fp32 bias + residual.
__global__ void __launch_bounds__(256) out_mma(const float* __restrict__ Wo,
                                               const float* __restrict__ bo,
                                               const float* __restrict__ x,
                                               float* __restrict__ out) {
    __shared__ __half sA[128][24];
    __shared__ __half sB[16][40];
    int tid = threadIdx.x;
    int warp = tid >> 5, c = tid & 31;
    int bm0 = blockIdx.x * 128;
    int c0 = blockIdx.y * 32;

    float cc[4][4];
    #pragma unroll
    for (int nt = 0; nt < 4; ++nt)
        #pragma unroll
        for (int q = 0; q < 4; ++q) cc[nt][q] = 0.f;

    unsigned aAddr = (unsigned)__cvta_generic_to_shared(
        &sA[warp * 16 + (c & 15)][(c >> 4) * 8]);
    unsigned bAddrBase = (unsigned)__cvta_generic_to_shared(&sB[c & 15][0]);

    int arow = tid >> 1, aoff = (tid & 1) * 8;
    int bk = tid >> 4, bn = (tid & 15) * 2;

    for (int k0 = 0; k0 < F; k0 += 16) {
        __syncthreads();
        *(uint4*)&sA[arow][aoff] =
            *(const uint4*)&d_aoh[(bm0 + arow) * F + k0 + aoff];
        {
            float2 wv = *(const float2*)&Wo[(k0 + bk) * F + c0 + bn];
            *(__half2*)&sB[bk][bn] = __floats2half2_rn(wv.x, wv.y);
        }
        __syncthreads();
        unsigned a0, a1, a2, a3;
        ldm_x4(a0, a1, a2, a3, aAddr);
        #pragma unroll
        for (int nt = 0; nt < 4; ++nt) {
            unsigned b0, b1;
            ldm_x2t(b0, b1, bAddrBase + nt * 16);
            mma16816(cc[nt][0], cc[nt][1], cc[nt][2], cc[nt][3],
                     a0, a1, a2, a3, b0, b1);
        }
    }

    int r0 = bm0 + warp * 16 + (c >> 2);
    #pragma unroll
    for (int nt = 0; nt < 4; ++nt) {
        int col = c0 + nt * 8 + 2 * (c & 3);
        float2 bo2 = *(const float2*)&bo[col];
        float2 x0 = *(const float2*)&x[r0 * F + col];
        float2 x1 = *(const float2*)&x[(r0 + 8) * F + col];
        *(float2*)&out[r0 * F + col] =
            make_float2(cc[nt][0] + bo2.x + x0.x, cc[nt][1] + bo2.y + x0.y);
        *(float2*)&out[(r0 + 8) * F + col] =
            make_float2(cc[nt][2] + bo2.x + x1.x, cc[nt][3] + bo2.y + x1.y);
    }
}

// ---------------- launch ----------------
extern "C" void kernel_launch(void* const* d_in, const int* in_sizes, int n_in,
                              void* d_out, int out_size) {
    const float* x     = (const float*)d_in[0];
    const int*   adj   = (const int*)d_in[1];
    const float* Wq    = (const float*)d_in[2];
    const float* Wk    = (const float*)d_in[3];
    const float* Wv    = (const float*)d_in[4];
    const float* a     = (const float*)d_in[5];
    const float* Wo    = (const float*)d_in[6];
    const float* bo    = (const float*)d_in[7];
    const float* gamma = (const float*)d_in[8];
    const float* beta  = (const float*)d_in[9];
    float* out = (float*)d_out;

    cudaFuncSetAttribute(attn_kernel, cudaFuncAttributeMaxDynamicSharedMemorySize,
                         (int)sizeof(AttnSmem));

    pack_adj<<<(N_NODES * N_NODES / 4) / 256, 256>>>(adj, a);
    ln_kernel<<<N_NODES, 256>>>(x, gamma, beta);
    qkv_mma<<<dim3(N_NODES / 128, 24), 256>>>(Wq, Wk, Wv, a);
    attn_kernel<<<dim3(N_NODES / BI, H), 256, sizeof(AttnSmem)>>>();
    out_mma<<<dim3(N_NODES / 128, F / 32), 256>>>(Wo, bo, x, out);
}

// round 13
// speedup vs baseline: 1.9501x; 1.0439x over previous
#include <cuda_runtime.h>
#include <cuda_fp16.h>

#define N_NODES 2048
#define F 256
#define H 8
#define DK 32
#define ALPHA 0.2f
#define LN_EPS 1e-5f

typedef unsigned long long ull;

// ---------------- scratch (no allocations allowed) ----------------
__device__ __half d_hbufh[N_NODES * F];             // fp16 LN output
__device__ __half2 d_Qh2[H * N_NODES * (DK / 2)];   // fp16 Q, d-pairs
__device__ __half2 d_Kh2[H * N_NODES * (DK / 2)];   // fp16 K, d-pairs
__device__ __half  d_Vh[H * N_NODES * DK];          // fp16 V, [node][d]
__device__ float d_bq[H * N_NODES];
__device__ float d_bk[H * N_NODES];
__device__ __half2 d_afh2[H * (DK / 2)];            // a' d-pairs, a' = (1-α)·scale·log2e·a
__device__ unsigned d_adjb[N_NODES * (N_NODES / 32)];
__device__ __half d_aoh[N_NODES * F];               // fp16 attention output

// ---------------- helpers ----------------
__device__ __forceinline__ float ex2f(float x) {
    float r; asm("ex2.approx.f32 %0, %1;" : "=f"(r) : "f"(x)); return r;
}
// fused relu(k + q) on half2 via fma.rn.relu.f16x2 (k*1 + q)
__device__ __forceinline__ unsigned hrelu_add(unsigned k, unsigned q, unsigned one2) {
    unsigned d;
    asm("fma.rn.relu.f16x2 %0, %1, %2, %3;"
        : "=r"(d) : "r"(k), "r"(one2), "r"(q));
    return d;
}
__device__ __forceinline__ void ldm_x4(unsigned& a0, unsigned& a1, unsigned& a2,
                                       unsigned& a3, unsigned addr) {
    asm volatile("ldmatrix.sync.aligned.m8n8.x4.shared.b16 {%0,%1,%2,%3}, [%4];"
                 : "=r"(a0), "=r"(a1), "=r"(a2), "=r"(a3) : "r"(addr));
}
__device__ __forceinline__ void ldm_x2t(unsigned& b0, unsigned& b1, unsigned addr) {
    asm volatile("ldmatrix.sync.aligned.m8n8.x2.trans.shared.b16 {%0,%1}, [%2];"
                 : "=r"(b0), "=r"(b1) : "r"(addr));
}
__device__ __forceinline__ void mma16816(float& c0, float& c1, float& c2, float& c3,
                                         unsigned a0, unsigned a1, unsigned a2,
                                         unsigned a3, unsigned b0, unsigned b1) {
    asm volatile("mma.sync.aligned.m16n8k16.row.col.f32.f16.f16.f32 "
                 "{%0,%1,%2,%3}, {%4,%5,%6,%7}, {%8,%9}, {%0,%1,%2,%3};"
                 : "+f"(c0), "+f"(c1), "+f"(c2), "+f"(c3)
                 : "r"(a0), "r"(a1), "r"(a2), "r"(a3), "r"(b0), "r"(b1));
}

// ---------------- K1: adjacency pack + a' fold + LayerNorm (merged) ----------------
#define PACK_BLOCKS (N_NODES * N_NODES / 4 / 256)   // 4096

__global__ void __launch_bounds__(256) prep_kernel(const int* __restrict__ adj,
                                                   const float* __restrict__ a,
                                                   const float* __restrict__ x,
                                                   const float* __restrict__ gamma,
                                                   const float* __restrict__ beta) {
    int bx = blockIdx.x;
    if (bx < PACK_BLOCKS) {
        int t = bx * 256 + threadIdx.x;
        int warp = t >> 5, lane = t & 31;
        int base = warp * 128;
        unsigned m0 = __ballot_sync(0xffffffffu, adj[base + lane] != 0);
        unsigned m1 = __ballot_sync(0xffffffffu, adj[base + 32 + lane] != 0);
        unsigned m2 = __ballot_sync(0xffffffffu, adj[base + 64 + lane] != 0);
        unsigned m3 = __ballot_sync(0xffffffffu, adj[base + 96 + lane] != 0);
        if (lane == 0) *(uint4*)&d_adjb[warp * 4] = make_uint4(m0, m1, m2, m3);
        if (bx == 0 && threadIdx.x < H * (DK / 2)) {
            const float C = (1.0f - ALPHA) * 0.17677669529663687f * 1.4426950408889634f;
            float2 av = *(const float2*)&a[2 * threadIdx.x];
            d_afh2[threadIdx.x] = __floats2half2_rn(C * av.x, C * av.y);
        }
    } else {
        int row = bx - PACK_BLOCKS;
        int t = threadIdx.x;
        float v = x[row * F + t];
        float s = v, s2 = v * v;
        #pragma unroll
        for (int m = 16; m > 0; m >>= 1) {
            s  += __shfl_xor_sync(0xffffffffu, s, m);
            s2 += __shfl_xor_sync(0xffffffffu, s2, m);
        }
        __shared__ float ws[8], ws2[8];
        if ((t & 31) == 0) { ws[t >> 5] = s; ws2[t >> 5] = s2; }
        __syncthreads();
        float tot = 0.f, tot2 = 0.f;
        #pragma unroll
        for (int w = 0; w < 8; ++w) { tot += ws[w]; tot2 += ws2[w]; }
        float mu = tot * (1.0f / F);
        float var = tot2 * (1.0f / F) - mu * mu;
        float inv = rsqrtf(var + LN_EPS);
        d_hbufh[row * F + t] = __float2half((v - mu) * inv * gamma[t] + beta[t]);
    }
}

// ---------------- K3: QKV projection via tensor-core mma ----------------
__global__ void __launch_bounds__(256) qkv_mma(const float* __restrict__ Wq,
                                               const float* __restrict__ Wk,
                                               const float* __restrict__ Wv,
                                               const float* __restrict__ a) {
    __shared__ __half sA[128][24];   // h tile [m][k16], pitch 24 halves
    __shared__ __half sB[16][40];    // W tile [k16][n32], pitch 40 halves
    int tid = threadIdx.x;
    int warp = tid >> 5, c = tid & 31;
    int bm0 = blockIdx.x * 128;
    int by = blockIdx.y;
    int which = by >> 3, hh = by & 7;
    const float* W = ((which == 0) ? Wq : (which == 1) ? Wk : Wv) + hh * (F * DK);

    float cc[4][4];
    #pragma unroll
    for (int nt = 0; nt < 4; ++nt)
        #pragma unroll
        for (int q = 0; q < 4; ++q) cc[nt][q] = 0.f;

    unsigned aAddr = (unsigned)__cvta_generic_to_shared(
        &sA[warp * 16 + (c & 15)][(c >> 4) * 8]);
    unsigned bAddrBase = (unsigned)__cvta_generic_to_shared(&sB[c & 15][0]);

    int arow = tid >> 1, aoff = (tid & 1) * 8;
    int bk = tid >> 4, bn = (tid & 15) * 2;

    for (int k0 = 0; k0 < F; k0 += 16) {
        __syncthreads();
        *(uint4*)&sA[arow][aoff] =
            *(const uint4*)&d_hbufh[(bm0 + arow) * F + k0 + aoff];
        {
            float2 wv = *(const float2*)&W[(k0 + bk) * DK + bn];
            *(__half2*)&sB[bk][bn] = __floats2half2_rn(wv.x, wv.y);
        }
        __syncthreads();
        unsigned a0, a1, a2, a3;
        ldm_x4(a0, a1, a2, a3, aAddr);
        #pragma unroll
        for (int nt = 0; nt < 4; ++nt) {
            unsigned b0, b1;
            ldm_x2t(b0, b1, bAddrBase + nt * 16);
            mma16816(cc[nt][0], cc[nt][1], cc[nt][2], cc[nt][3],
                     a0, a1, a2, a3, b0, b1);
        }
    }

    int r0 = bm0 + warp * 16 + (c >> 2);
    if (which == 2) {
        __half* dstV = d_Vh + hh * N_NODES * DK;
        #pragma unroll
        for (int nt = 0; nt < 4; ++nt) {
            int col0 = nt * 8 + 2 * (c & 3);
            *(__half2*)&dstV[r0 * DK + col0] = __floats2half2_rn(cc[nt][0], cc[nt][1]);
            *(__half2*)&dstV[(r0 + 8) * DK + col0] = __floats2half2_rn(cc[nt][2], cc[nt][3]);
        }
    } else {
        const float CC = ALPHA * 0.17677669529663687f * 1.4426950408889634f;
        __half2* dstH = ((which == 0) ? d_Qh2 : d_Kh2) + hh * N_NODES * 16;
        float* dstB = ((which == 0) ? d_bq : d_bk) + hh * N_NODES;
        float p0 = 0.f, p1 = 0.f;
        #pragma unroll
        for (int nt = 0; nt < 4; ++nt) {
            int col0 = nt * 8 + 2 * (c & 3);
            float a0v = a[hh * DK + col0];
            float a1v = a[hh * DK + col0 + 1];
            dstH[r0 * 16 + nt * 4 + (c & 3)] = __floats2half2_rn(cc[nt][0], cc[nt][1]);
            dstH[(r0 + 8) * 16 + nt * 4 + (c & 3)] = __floats2half2_rn(cc[nt][2], cc[nt][3]);
            p0 += a0v * cc[nt][0] + a1v * cc[nt][1];
            p1 += a0v * cc[nt][2] + a1v * cc[nt][3];
        }
        p0 += __shfl_xor_sync(0xffffffffu, p0, 1);
        p0 += __shfl_xor_sync(0xffffffffu, p0, 2);
        p1 += __shfl_xor_sync(0xffffffffu, p1, 1);
        p1 += __shfl_xor_sync(0xffffffffu, p1, 2);
        if ((c & 3) == 0) {
            dstB[r0] = CC * p0;
            dstB[r0 + 8] = CC * p1;
        }
    }
}

// ---------------- K4: fused GAT attention (mma logits + mma PV) ----------------
#define BI 32
#define BJ 128
#define NJT (N_NODES / BJ)

struct AttnSmem {
    __half  sPh[BI][136];      // P fp16 - 8.5KB
    __half  sVh[BJ][40];       // V fp16 [j][d] - 10KB
    __half  sKh[BJ][40];       // K fp16 [j][d] - 10KB
    float   sLog[BI][128];     // fp32 logits (pre-bias) - 16KB
    __half2 sQh[BI][17];       // Q [i][d2] - 2.2KB
    unsigned sAdj[BI][64];     // 8KB
    float   sBq[BI];
    float   sBk[BJ];
    float   sL[BI];
};

__global__ void __launch_bounds__(256, 4) attn_kernel() {
    extern __shared__ char smem_raw[];
    AttnSmem& sm = *reinterpret_cast<AttnSmem*>(smem_raw);
    int tid = threadIdx.x;
    int h = blockIdx.y;
    int i0 = blockIdx.x * BI;
    int hN = h * N_NODES;
    const __half2* Qh2 = d_Qh2 + hN * 16;
    const __half2* Kh2 = d_Kh2 + hN * 16;
    const __half*  Vh  = d_Vh + hN * DK;

    // ---- prologue: Q tile, adjacency, bases ----
    if (tid < 128) {
        int i = tid >> 2, q4 = (tid & 3) * 4;
        uint4 qv = *(const uint4*)&Qh2[(i0 + i) * 16 + q4];
        sm.sQh[i][q4 + 0] = *(__half2*)&qv.x;
        sm.sQh[i][q4 + 1] = *(__half2*)&qv.y;
        sm.sQh[i][q4 + 2] = *(__half2*)&qv.z;
        sm.sQh[i][q4 + 3] = *(__half2*)&qv.w;
    }
    if (tid < BI) sm.sBq[tid] = d_bq[hN + i0 + tid];
    for (int idx = tid; idx < BI * 64; idx += 256)
        sm.sAdj[idx >> 6][idx & 63] = d_adjb[(i0 + (idx >> 6)) * 64 + (idx & 63)];
    __syncthreads();

    int r = tid >> 5;           // warp id (owns i-rows 4r..4r+3)
    int c = tid & 31;           // lane
    int mh = r >> 2;            // PV mma: m-half
    int nq = r & 3;             // PV mma: n-quarter
    int l4 = c & 3;             // lane % 4

    // ---- kernel-lifetime register operands for logits mma ----
    unsigned qE[2][2], qEh[2][2], qO[2][2], qOh[2][2];  // [ig][slab]
    #pragma unroll
    for (int ig = 0; ig < 2; ++ig) {
        int iE = 4 * r + 2 * ig, iO = iE + 1;
        #pragma unroll
        for (int s = 0; s < 2; ++s) {
            qE[ig][s]  = *(unsigned*)&sm.sQh[iE][s * 8 + l4];
            qEh[ig][s] = *(unsigned*)&sm.sQh[iE][s * 8 + 4 + l4];
            qO[ig][s]  = *(unsigned*)&sm.sQh[iO][s * 8 + l4];
            qOh[ig][s] = *(unsigned*)&sm.sQh[iO][s * 8 + 4 + l4];
        }
    }
    unsigned bLo[2], bHi[2];
    #pragma unroll
    for (int s = 0; s < 2; ++s) {
        bLo[s] = *(const unsigned*)&d_afh2[h * 16 + s * 8 + l4];
        bHi[s] = *(const unsigned*)&d_afh2[h * 16 + s * 8 + 4 + l4];
    }
    // ldmatrix x4 lane mapping: lanes 0-7 -> d0-7 rows, 8-15 -> d8-15, etc.
    unsigned kBase4 = (unsigned)__cvta_generic_to_shared(
        &sm.sKh[c & 7][(c >> 3) * 8]);
    unsigned aAddrBase = (unsigned)__cvta_generic_to_shared(
        &sm.sPh[mh * 16 + (c & 15)][(c >> 4) * 8]);
    unsigned bAddrBase = (unsigned)__cvta_generic_to_shared(
        &sm.sVh[c & 15][nq * 8]);
    const unsigned one2 = 0x3c003c00u;  // (1.0h, 1.0h)

    float psum[4] = {0.f, 0.f, 0.f, 0.f};
    float cacc0 = 0.f, cacc1 = 0.f, cacc2 = 0.f, cacc3 = 0.f;

    for (int jt = 0; jt < NJT; ++jt) {
        int j0 = jt * BJ;
        __syncthreads();  // prev tile fully consumed

        // ---- fill K tile [j][d] fp16 ----
        #pragma unroll
        for (int it = 0; it < 2; ++it) {
            int chunk = it * 256 + tid;
            int j = chunk >> 2, q8 = (chunk & 3) * 8;
            *(uint4*)&sm.sKh[j][q8] = *(const uint4*)&Kh2[(j0 + j) * 16 + (chunk & 3) * 4];
        }
        // ---- fill V tile [j][d] fp16 ----
        #pragma unroll
        for (int it = 0; it < 2; ++it) {
            int chunk = it * 256 + tid;
            int j = chunk >> 2, q8 = (chunk & 3) * 8;
            *(uint4*)&sm.sVh[j][q8] = *(const uint4*)&Vh[(j0 + j) * DK + q8];
        }
        if (tid < BJ) sm.sBk[tid] = d_bk[hN + j0 + tid];
        __syncthreads();

        // ---- logits: relu(k+q) fragments -> mma d-reduction (fp32) ----
        #pragma unroll
        for (int jg = 0; jg < 16; ++jg) {
            unsigned kaL0, kaH0, kaL1, kaH1;
            ldm_x4(kaL0, kaH0, kaL1, kaH1, kBase4 + jg * 640);
            #pragma unroll
            for (int ig = 0; ig < 2; ++ig) {
                float c0 = 0.f, c1 = 0.f, c2v = 0.f, c3 = 0.f;
                mma16816(c0, c1, c2v, c3,
                         hrelu_add(kaL0, qE[ig][0], one2),
                         hrelu_add(kaL0, qO[ig][0], one2),
                         hrelu_add(kaH0, qEh[ig][0], one2),
                         hrelu_add(kaH0, qOh[ig][0], one2),
                         bLo[0], bHi[0]);
                mma16816(c0, c1, c2v, c3,
                         hrelu_add(kaL1, qE[ig][1], one2),
                         hrelu_add(kaL1, qO[ig][1], one2),
                         hrelu_add(kaH1, qEh[ig][1], one2),
                         hrelu_add(kaH1, qOh[ig][1], one2),
                         bLo[1], bHi[1]);
                int i0r = 4 * r + 2 * ig;
                int jj = jg * 8 + (c >> 2);
                if (l4 == 0) sm.sLog[i0r][jj] = c0;
                if (l4 == 1) sm.sLog[i0r + 1][jj] = c2v;
            }
        }
        __syncwarp();

        // ---- epilogue (vectorized): lane owns 4 contiguous cols 4c..4c+3 ----
        {
            int col = 4 * c;
            int wi = jt * 4 + (c >> 3);
            int sh = col & 31;
            float4 bk4 = *(const float4*)&sm.sBk[col];
            #pragma unroll
            for (int ii = 0; ii < 4; ++ii) {
                int i = 4 * r + ii;
                float bq = sm.sBq[i];
                float4 lg = *(const float4*)&sm.sLog[i][col];
                unsigned w = sm.sAdj[i][wi] >> sh;
                float p0 = (w & 1u) ? ex2f(lg.x + bq + bk4.x) : 0.f;
                float p1 = (w & 2u) ? ex2f(lg.y + bq + bk4.y) : 0.f;
                float p2 = (w & 4u) ? ex2f(lg.z + bq + bk4.z) : 0.f;
                float p3 = (w & 8u) ? ex2f(lg.w + bq + bk4.w) : 0.f;
                psum[ii] += (p0 + p1) + (p2 + p3);
                __half2 h0 = __floats2half2_rn(p0, p1);
                __half2 h1 = __floats2half2_rn(p2, p3);
                uint2 pk;
                pk.x = *(unsigned*)&h0;
                pk.y = *(unsigned*)&h1;
                *(uint2*)&sm.sPh[i][col] = pk;
            }
        }
        __syncthreads();  // P tile complete

        // ---- PV via tensor cores: one m16n8 output tile per warp ----
        #pragma unroll
        for (int ks = 0; ks < 8; ++ks) {
            unsigned a0, a1, a2r, a3, b0r, b1r;
            ldm_x4(a0, a1, a2r, a3, aAddrBase + ks * 32);
            ldm_x2t(b0r, b1r, bAddrBase + ks * 16 * 80);
            mma16816(cacc0, cacc1, cacc2, cacc3, a0, a1, a2r, a3, b0r, b1r);
        }
    }

    // ---- row-sum reduction across lanes ----
    #pragma unroll
    for (int ii = 0; ii < 4; ++ii) {
        float v = psum[ii];
        v += __shfl_xor_sync(0xffffffffu, v, 16);
        v += __shfl_xor_sync(0xffffffffu, v, 8);
        v += __shfl_xor_sync(0xffffffffu, v, 4);
        v += __shfl_xor_sync(0xffffffffu, v, 2);
        v += __shfl_xor_sync(0xffffffffu, v, 1);
        if (c == 0) sm.sL[4 * r + ii] = v;
    }
    __syncthreads();

    // ---- normalize + store fp16 (c-fragment layout) ----
    {
        int row0 = mh * 16 + (c >> 2);
        int col0 = nq * 8 + 2 * (c & 3);
        float inv0 = 1.0f / sm.sL[row0];
        float inv1 = 1.0f / sm.sL[row0 + 8];
        *(__half2*)&d_aoh[(i0 + row0) * F + h * DK + col0] =
            __floats2half2_rn(cacc0 * inv0, cacc1 * inv0);
        *(__half2*)&d_aoh[(i0 + row0 + 8) * F + h * DK + col0] =
            __floats2half2_rn(cacc2 * inv1, cacc3 * inv1);
    }
}

// ---------------- K5: output projection via tensor-core mma ----------------
__global__ void __launch_bounds__(256) out_mma(const float* __restrict__ Wo,
                                               const float* __restrict__ bo,
                                               const float* __restrict__ x,
                                               float* __restrict__ out) {
    __shared__ __half sA[128][24];
    __shared__ __half sB[16][40];
    int tid = threadIdx.x;
    int warp = tid >> 5, c = tid & 31;
    int bm0 = blockIdx.x * 128;
    int c0 = blockIdx.y * 32;

    float cc[4][4];
    #pragma unroll
    for (int nt = 0; nt < 4; ++nt)
        #pragma unroll
        for (int q = 0; q < 4; ++q) cc[nt][q] = 0.f;

    unsigned aAddr = (unsigned)__cvta_generic_to_shared(
        &sA[warp * 16 + (c & 15)][(c >> 4) * 8]);
    unsigned bAddrBase = (unsigned)__cvta_generic_to_shared(&sB[c & 15][0]);

    int arow = tid >> 1, aoff = (tid & 1) * 8;
    int bk = tid >> 4, bn = (tid & 15) * 2;

    for (int k0 = 0; k0 < F; k0 += 16) {
        __syncthreads();
        *(uint4*)&sA[arow][aoff] =
            *(const uint4*)&d_aoh[(bm0 + arow) * F + k0 + aoff];
        {
            float2 wv = *(const float2*)&Wo[(k0 + bk) * F + c0 + bn];
            *(__half2*)&sB[bk][bn] = __floats2half2_rn(wv.x, wv.y);
        }
        __syncthreads();
        unsigned a0, a1, a2, a3;
        ldm_x4(a0, a1, a2, a3, aAddr);
        #pragma unroll
        for (int nt = 0; nt < 4; ++nt) {
            unsigned b0, b1;
            ldm_x2t(b0, b1, bAddrBase + nt * 16);
            mma16816(cc[nt][0], cc[nt][1], cc[nt][2], cc[nt][3],
                     a0, a1, a2, a3, b0, b1);
        }
    }

    int r0 = bm0 + warp * 16 + (c >> 2);
    #pragma unroll
    for (int nt = 0; nt < 4; ++nt) {
        int col = c0 + nt * 8 + 2 * (c & 3);
        float2 bo2 = *(const float2*)&bo[col];
        float2 x0 = *(const float2*)&x[r0 * F + col];
        float2 x1 = *(const float2*)&x[(r0 + 8) * F + col];
        *(float2*)&out[r0 * F + col] =
            make_float2(cc[nt][0] + bo2.x + x0.x, cc[nt][1] + bo2.y + x0.y);
        *(float2*)&out[(r0 + 8) * F + col] =
            make_float2(cc[nt][2] + bo2.x + x1.x, cc[nt][3] + bo2.y + x1.y);
    }
}

// ---------------- launch ----------------
extern "C" void kernel_launch(void* const* d_in, const int* in_sizes, int n_in,
                              void* d_out, int out_size) {
    const float* x     = (const float*)d_in[0];
    const int*   adj   = (const int*)d_in[1];
    const float* Wq    = (const float*)d_in[2];
    const float* Wk    = (const float*)d_in[3];
    const float* Wv    = (const float*)d_in[4];
    const float* a     = (const float*)d_in[5];
    const float* Wo    = (const float*)d_in[6];
    const float* bo    = (const float*)d_in[7];
    const float* gamma = (const float*)d_in[8];
    const float* beta  = (const float*)d_in[9];
    float* out = (float*)d_out;

    cudaFuncSetAttribute(attn_kernel, cudaFuncAttributeMaxDynamicSharedMemorySize,
                         (int)sizeof(AttnSmem));

    prep_kernel<<<PACK_BLOCKS + N_NODES, 256>>>(adj, a, x, gamma, beta);
    qkv_mma<<<dim3(N_NODES / 128, 24), 256>>>(Wq, Wk, Wv, a);
    attn_kernel<<<dim3(N_NODES / BI, H), 256, sizeof(AttnSmem)>>>();
    out_mma<<<dim3(N_NODES / 128, F / 32), 256>>>(Wo, bo, x, out);
}

// round 14
// speedup vs baseline: 2.0388x; 1.0455x over previous
#include <cuda_runtime.h>
#include <cuda_fp16.h>

#define N_NODES 2048
#define F 256
#define H 8
#define DK 32
#define ALPHA 0.2f
#define LN_EPS 1e-5f

typedef unsigned long long ull;

// ---------------- scratch (no allocations allowed) ----------------
__device__ __half d_hbufh[N_NODES * F];             // fp16 LN output
__device__ __half2 d_Qh2[H * N_NODES * (DK / 2)];   // fp16 Q, d-pairs
__device__ __half2 d_Kh2[H * N_NODES * (DK / 2)];   // fp16 K, d-pairs
__device__ __half  d_Vh[H * N_NODES * DK];          // fp16 V, [node][d]
__device__ float d_bq[H * N_NODES];
__device__ float d_bk[H * N_NODES];
__device__ __half2 d_afh2[H * (DK / 2)];            // a' d-pairs
__device__ unsigned d_adjb[N_NODES * (N_NODES / 32)];
__device__ __half d_aoh[N_NODES * F];               // fp16 attention output

// ---------------- helpers ----------------
__device__ __forceinline__ float ex2f(float x) {
    float r; asm("ex2.approx.f32 %0, %1;" : "=f"(r) : "f"(x)); return r;
}
__device__ __forceinline__ unsigned hrelu_add(unsigned k, unsigned q, unsigned one2) {
    unsigned d;
    asm("fma.rn.relu.f16x2 %0, %1, %2, %3;"
        : "=r"(d) : "r"(k), "r"(one2), "r"(q));
    return d;
}
__device__ __forceinline__ void ldm_x4(unsigned& a0, unsigned& a1, unsigned& a2,
                                       unsigned& a3, unsigned addr) {
    asm volatile("ldmatrix.sync.aligned.m8n8.x4.shared.b16 {%0,%1,%2,%3}, [%4];"
                 : "=r"(a0), "=r"(a1), "=r"(a2), "=r"(a3) : "r"(addr));
}
__device__ __forceinline__ void ldm_x2t(unsigned& b0, unsigned& b1, unsigned addr) {
    asm volatile("ldmatrix.sync.aligned.m8n8.x2.trans.shared.b16 {%0,%1}, [%2];"
                 : "=r"(b0), "=r"(b1) : "r"(addr));
}
__device__ __forceinline__ void mma16816(float& c0, float& c1, float& c2, float& c3,
                                         unsigned a0, unsigned a1, unsigned a2,
                                         unsigned a3, unsigned b0, unsigned b1) {
    asm volatile("mma.sync.aligned.m16n8k16.row.col.f32.f16.f16.f32 "
                 "{%0,%1,%2,%3}, {%4,%5,%6,%7}, {%8,%9}, {%0,%1,%2,%3};"
                 : "+f"(c0), "+f"(c1), "+f"(c2), "+f"(c3)
                 : "r"(a0), "r"(a1), "r"(a2), "r"(a3), "r"(b0), "r"(b1));
}

// ---------------- K1: adjacency pack + a' fold + LayerNorm (merged) ----------------
#define PACK_BLOCKS (N_NODES * N_NODES / 4 / 256)   // 4096

__global__ void __launch_bounds__(256) prep_kernel(const int* __restrict__ adj,
                                                   const float* __restrict__ a,
                                                   const float* __restrict__ x,
                                                   const float* __restrict__ gamma,
                                                   const float* __restrict__ beta) {
    int bx = blockIdx.x;
    if (bx < PACK_BLOCKS) {
        int t = bx * 256 + threadIdx.x;
        int warp = t >> 5, lane = t & 31;
        int base = warp * 128;
        unsigned m0 = __ballot_sync(0xffffffffu, adj[base + lane] != 0);
        unsigned m1 = __ballot_sync(0xffffffffu, adj[base + 32 + lane] != 0);
        unsigned m2 = __ballot_sync(0xffffffffu, adj[base + 64 + lane] != 0);
        unsigned m3 = __ballot_sync(0xffffffffu, adj[base + 96 + lane] != 0);
        if (lane == 0) *(uint4*)&d_adjb[warp * 4] = make_uint4(m0, m1, m2, m3);
        if (bx == 0 && threadIdx.x < H * (DK / 2)) {
            const float C = (1.0f - ALPHA) * 0.17677669529663687f * 1.4426950408889634f;
            float2 av = *(const float2*)&a[2 * threadIdx.x];
            d_afh2[threadIdx.x] = __floats2half2_rn(C * av.x, C * av.y);
        }
    } else {
        int row = bx - PACK_BLOCKS;
        int t = threadIdx.x;
        float v = x[row * F + t];
        float s = v, s2 = v * v;
        #pragma unroll
        for (int m = 16; m > 0; m >>= 1) {
            s  += __shfl_xor_sync(0xffffffffu, s, m);
            s2 += __shfl_xor_sync(0xffffffffu, s2, m);
        }
        __shared__ float ws[8], ws2[8];
        if ((t & 31) == 0) { ws[t >> 5] = s; ws2[t >> 5] = s2; }
        __syncthreads();
        float tot = 0.f, tot2 = 0.f;
        #pragma unroll
        for (int w = 0; w < 8; ++w) { tot += ws[w]; tot2 += ws2[w]; }
        float mu = tot * (1.0f / F);
        float var = tot2 * (1.0f / F) - mu * mu;
        float inv = rsqrtf(var + LN_EPS);
        d_hbufh[row * F + t] = __float2half((v - mu) * inv * gamma[t] + beta[t]);
    }
}

// ---------------- pipelined GEMM mainloop (shared by qkv/out) ----------------
// A: fp16 gmem [128 rows x 256 k], B: fp32 gmem [k x n] (row ld), 8 stages of k=32.
// Result: cc[4][4] per thread (warp -> 16 rows, 4 n-tiles of 8).
#define GSTAGE_A (128 * 40)         // halves per A stage
#define GSTAGE_B (32 * 40)          // halves per B stage

struct GemmSmem {
    __half sA[2][128][40];
    __half sB[2][32][40];
};

__device__ __forceinline__ void gemm_mainloop(
    GemmSmem& gs, const __half* __restrict__ Asrc, int bm0,
    const float* __restrict__ Bsrc, int ldB, int cb,
    int tid, int warp, int c, float cc[4][4]) {

    int arow = tid >> 1, aq = (tid & 1) * 16;
    int bk = tid >> 3, bn = (tid & 7) * 4;

    unsigned aAddr0 = (unsigned)__cvta_generic_to_shared(
        &gs.sA[0][warp * 16 + (c & 15)][(c >> 4) * 8]);
    unsigned bAddr0 = (unsigned)__cvta_generic_to_shared(
        &gs.sB[0][c & 15][0]);

    // prefetch stage 0
    uint4 aR0 = *(const uint4*)&Asrc[(bm0 + arow) * F + aq];
    uint4 aR1 = *(const uint4*)&Asrc[(bm0 + arow) * F + aq + 8];
    float4 wv = *(const float4*)&Bsrc[bk * ldB + cb + bn];
    *(uint4*)&gs.sA[0][arow][aq] = aR0;
    *(uint4*)&gs.sA[0][arow][aq + 8] = aR1;
    {
        __half2 b0 = __floats2half2_rn(wv.x, wv.y);
        __half2 b1 = __floats2half2_rn(wv.z, wv.w);
        uint2 pk; pk.x = *(unsigned*)&b0; pk.y = *(unsigned*)&b1;
        *(uint2*)&gs.sB[0][bk][bn] = pk;
    }
    __syncthreads();

    #pragma unroll
    for (int it = 0; it < 8; ++it) {
        int cur = it & 1;
        // prefetch next stage into registers
        if (it < 7) {
            int k0 = (it + 1) * 32;
            aR0 = *(const uint4*)&Asrc[(bm0 + arow) * F + k0 + aq];
            aR1 = *(const uint4*)&Asrc[(bm0 + arow) * F + k0 + aq + 8];
            wv = *(const float4*)&Bsrc[(k0 + bk) * ldB + cb + bn];
        }
        // consume current stage: 2 k16 substeps
        unsigned aBase = aAddr0 + cur * (GSTAGE_A * 2);
        unsigned bBase = bAddr0 + cur * (GSTAGE_B * 2);
        #pragma unroll
        for (int ks = 0; ks < 2; ++ks) {
            unsigned a0, a1, a2, a3;
            ldm_x4(a0, a1, a2, a3, aBase + ks * 32);
            #pragma unroll
            for (int nt = 0; nt < 4; ++nt) {
                unsigned b0, b1;
                ldm_x2t(b0, b1, bBase + ks * 16 * 80 + nt * 16);
                mma16816(cc[nt][0], cc[nt][1], cc[nt][2], cc[nt][3],
                         a0, a1, a2, a3, b0, b1);
            }
        }
        // store prefetched regs into the other buffer
        if (it < 7) {
            int nxt = 1 - cur;
            *(uint4*)&gs.sA[nxt][arow][aq] = aR0;
            *(uint4*)&gs.sA[nxt][arow][aq + 8] = aR1;
            __half2 b0 = __floats2half2_rn(wv.x, wv.y);
            __half2 b1 = __floats2half2_rn(wv.z, wv.w);
            uint2 pk; pk.x = *(unsigned*)&b0; pk.y = *(unsigned*)&b1;
            *(uint2*)&gs.sB[nxt][bk][bn] = pk;
        }
        __syncthreads();
    }
}

// ---------------- K3: QKV projection (pipelined mma) ----------------
__global__ void __launch_bounds__(256) qkv_mma(const float* __restrict__ Wq,
                                               const float* __restrict__ Wk,
                                               const float* __restrict__ Wv,
                                               const float* __restrict__ a) {
    __shared__ GemmSmem gs;
    int tid = threadIdx.x;
    int warp = tid >> 5, c = tid & 31;
    int bm0 = blockIdx.x * 128;
    int by = blockIdx.y;
    int which = by >> 3, hh = by & 7;
    const float* W = ((which == 0) ? Wq : (which == 1) ? Wk : Wv) + hh * (F * DK);

    float cc[4][4];
    #pragma unroll
    for (int nt = 0; nt < 4; ++nt)
        #pragma unroll
        for (int q = 0; q < 4; ++q) cc[nt][q] = 0.f;

    gemm_mainloop(gs, d_hbufh, bm0, W, DK, 0, tid, warp, c, cc);

    int r0 = bm0 + warp * 16 + (c >> 2);
    if (which == 2) {
        __half* dstV = d_Vh + hh * N_NODES * DK;
        #pragma unroll
        for (int nt = 0; nt < 4; ++nt) {
            int col0 = nt * 8 + 2 * (c & 3);
            *(__half2*)&dstV[r0 * DK + col0] = __floats2half2_rn(cc[nt][0], cc[nt][1]);
            *(__half2*)&dstV[(r0 + 8) * DK + col0] = __floats2half2_rn(cc[nt][2], cc[nt][3]);
        }
    } else {
        const float CC = ALPHA * 0.17677669529663687f * 1.4426950408889634f;
        __half2* dstH = ((which == 0) ? d_Qh2 : d_Kh2) + hh * N_NODES * 16;
        float* dstB = ((which == 0) ? d_bq : d_bk) + hh * N_NODES;
        float p0 = 0.f, p1 = 0.f;
        #pragma unroll
        for (int nt = 0; nt < 4; ++nt) {
            int col0 = nt * 8 + 2 * (c & 3);
            float a0v = a[hh * DK + col0];
            float a1v = a[hh * DK + col0 + 1];
            dstH[r0 * 16 + nt * 4 + (c & 3)] = __floats2half2_rn(cc[nt][0], cc[nt][1]);
            dstH[(r0 + 8) * 16 + nt * 4 + (c & 3)] = __floats2half2_rn(cc[nt][2], cc[nt][3]);
            p0 += a0v * cc[nt][0] + a1v * cc[nt][1];
            p1 += a0v * cc[nt][2] + a1v * cc[nt][3];
        }
        p0 += __shfl_xor_sync(0xffffffffu, p0, 1);
        p0 += __shfl_xor_sync(0xffffffffu, p0, 2);
        p1 += __shfl_xor_sync(0xffffffffu, p1, 1);
        p1 += __shfl_xor_sync(0xffffffffu, p1, 2);
        if ((c & 3) == 0) {
            dstB[r0] = CC * p0;
            dstB[r0 + 8] = CC * p1;
        }
    }
}

// ---------------- K4: fused GAT attention (mma logits + mma PV) ----------------
#define BI 32
#define BJ 128
#define NJT (N_NODES / BJ)

struct AttnSmem {
    __half  sPh[BI][136];
    __half  sVh[BJ][40];
    __half  sKh[BJ][40];
    float   sLog[BI][128];
    __half2 sQh[BI][17];
    unsigned sAdj[BI][64];
    float   sBq[BI];
    float   sBk[BJ];
    float   sL[BI];
};

__global__ void __launch_bounds__(256, 4) attn_kernel() {
    extern __shared__ char smem_raw[];
    AttnSmem& sm = *reinterpret_cast<AttnSmem*>(smem_raw);
    int tid = threadIdx.x;
    int h = blockIdx.y;
    int i0 = blockIdx.x * BI;
    int hN = h * N_NODES;
    const __half2* Qh2 = d_Qh2 + hN * 16;
    const __half2* Kh2 = d_Kh2 + hN * 16;
    const __half*  Vh  = d_Vh + hN * DK;

    if (tid < 128) {
        int i = tid >> 2, q4 = (tid & 3) * 4;
        uint4 qv = *(const uint4*)&Qh2[(i0 + i) * 16 + q4];
        sm.sQh[i][q4 + 0] = *(__half2*)&qv.x;
        sm.sQh[i][q4 + 1] = *(__half2*)&qv.y;
        sm.sQh[i][q4 + 2] = *(__half2*)&qv.z;
        sm.sQh[i][q4 + 3] = *(__half2*)&qv.w;
    }
    if (tid < BI) sm.sBq[tid] = d_bq[hN + i0 + tid];
    for (int idx = tid; idx < BI * 64; idx += 256)
        sm.sAdj[idx >> 6][idx & 63] = d_adjb[(i0 + (idx >> 6)) * 64 + (idx & 63)];
    __syncthreads();

    int r = tid >> 5;
    int c = tid & 31;
    int mh = r >> 2;
    int nq = r & 3;
    int l4 = c & 3;

    unsigned qE[2][2], qEh[2][2], qO[2][2], qOh[2][2];
    #pragma unroll
    for (int ig = 0; ig < 2; ++ig) {
        int iE = 4 * r + 2 * ig, iO = iE + 1;
        #pragma unroll
        for (int s = 0; s < 2; ++s) {
            qE[ig][s]  = *(unsigned*)&sm.sQh[iE][s * 8 + l4];
            qEh[ig][s] = *(unsigned*)&sm.sQh[iE][s * 8 + 4 + l4];
            qO[ig][s]  = *(unsigned*)&sm.sQh[iO][s * 8 + l4];
            qOh[ig][s] = *(unsigned*)&sm.sQh[iO][s * 8 + 4 + l4];
        }
    }
    unsigned bLo[2], bHi[2];
    #pragma unroll
    for (int s = 0; s < 2; ++s) {
        bLo[s] = *(const unsigned*)&d_afh2[h * 16 + s * 8 + l4];
        bHi[s] = *(const unsigned*)&d_afh2[h * 16 + s * 8 + 4 + l4];
    }
    unsigned kBase4 = (unsigned)__cvta_generic_to_shared(
        &sm.sKh[c & 7][(c >> 3) * 8]);
    unsigned aAddrBase = (unsigned)__cvta_generic_to_shared(
        &sm.sPh[mh * 16 + (c & 15)][(c >> 4) * 8]);
    unsigned bAddrBase = (unsigned)__cvta_generic_to_shared(
        &sm.sVh[c & 15][nq * 8]);
    const unsigned one2 = 0x3c003c00u;

    float psum[4] = {0.f, 0.f, 0.f, 0.f};
    float cacc0 = 0.f, cacc1 = 0.f, cacc2 = 0.f, cacc3 = 0.f;

    for (int jt = 0; jt < NJT; ++jt) {
        int j0 = jt * BJ;
        __syncthreads();

        #pragma unroll
        for (int it = 0; it < 2; ++it) {
            int chunk = it * 256 + tid;
            int j = chunk >> 2, q8 = (chunk & 3) * 8;
            *(uint4*)&sm.sKh[j][q8] = *(const uint4*)&Kh2[(j0 + j) * 16 + (chunk & 3) * 4];
        }
        #pragma unroll
        for (int it = 0; it < 2; ++it) {
            int chunk = it * 256 + tid;
            int j = chunk >> 2, q8 = (chunk & 3) * 8;
            *(uint4*)&sm.sVh[j][q8] = *(const uint4*)&Vh[(j0 + j) * DK + q8];
        }
        if (tid < BJ) sm.sBk[tid] = d_bk[hN + j0 + tid];
        __syncthreads();

        #pragma unroll
        for (int jg = 0; jg < 16; ++jg) {
            unsigned kaL0, kaH0, kaL1, kaH1;
            ldm_x4(kaL0, kaH0, kaL1, kaH1, kBase4 + jg * 640);
            #pragma unroll
            for (int ig = 0; ig < 2; ++ig) {
                float c0 = 0.f, c1 = 0.f, c2v = 0.f, c3 = 0.f;
                mma16816(c0, c1, c2v, c3,
                         hrelu_add(kaL0, qE[ig][0], one2),
                         hrelu_add(kaL0, qO[ig][0], one2),
                         hrelu_add(kaH0, qEh[ig][0], one2),
                         hrelu_add(kaH0, qOh[ig][0], one2),
                         bLo[0], bHi[0]);
                mma16816(c0, c1, c2v, c3,
                         hrelu_add(kaL1, qE[ig][1], one2),
                         hrelu_add(kaL1, qO[ig][1], one2),
                         hrelu_add(kaH1, qEh[ig][1], one2),
                         hrelu_add(kaH1, qOh[ig][1], one2),
                         bLo[1], bHi[1]);
                int i0r = 4 * r + 2 * ig;
                int jj = jg * 8 + (c >> 2);
                if (l4 == 0) sm.sLog[i0r][jj] = c0;
                if (l4 == 1) sm.sLog[i0r + 1][jj] = c2v;
            }
        }
        __syncwarp();

        {
            int col = 4 * c;
            int wi = jt * 4 + (c >> 3);
            int sh = col & 31;
            float4 bk4 = *(const float4*)&sm.sBk[col];
            #pragma unroll
            for (int ii = 0; ii < 4; ++ii) {
                int i = 4 * r + ii;
                float bq = sm.sBq[i];
                float4 lg = *(const float4*)&sm.sLog[i][col];
                unsigned w = sm.sAdj[i][wi] >> sh;
                float p0 = (w & 1u) ? ex2f(lg.x + bq + bk4.x) : 0.f;
                float p1 = (w & 2u) ? ex2f(lg.y + bq + bk4.y) : 0.f;
                float p2 = (w & 4u) ? ex2f(lg.z + bq + bk4.z) : 0.f;
                float p3 = (w & 8u) ? ex2f(lg.w + bq + bk4.w) : 0.f;
                psum[ii] += (p0 + p1) + (p2 + p3);
                __half2 h0 = __floats2half2_rn(p0, p1);
                __half2 h1 = __floats2half2_rn(p2, p3);
                uint2 pk;
                pk.x = *(unsigned*)&h0;
                pk.y = *(unsigned*)&h1;
                *(uint2*)&sm.sPh[i][col] = pk;
            }
        }
        __syncthreads();

        #pragma unroll
        for (int ks = 0; ks < 8; ++ks) {
            unsigned a0, a1, a2r, a3, b0r, b1r;
            ldm_x4(a0, a1, a2r, a3, aAddrBase + ks * 32);
            ldm_x2t(b0r, b1r, bAddrBase + ks * 16 * 80);
            mma16816(cacc0, cacc1, cacc2, cacc3, a0, a1, a2r, a3, b0r, b1r);
        }
    }

    #pragma unroll
    for (int ii = 0; ii < 4; ++ii) {
        float v = psum[ii];
        v += __shfl_xor_sync(0xffffffffu, v, 16);
        v += __shfl_xor_sync(0xffffffffu, v, 8);
        v += __shfl_xor_sync(0xffffffffu, v, 4);
        v += __shfl_xor_sync(0xffffffffu, v, 2);
        v += __shfl_xor_sync(0xffffffffu, v, 1);
        if (c == 0) sm.sL[4 * r + ii] = v;
    }
    __syncthreads();

    {
        int row0 = mh * 16 + (c >> 2);
        int col0 = nq * 8 + 2 * (c & 3);
        float inv0 = 1.0f / sm.sL[row0];
        float inv1 = 1.0f / sm.sL[row0 + 8];
        *(__half2*)&d_aoh[(i0 + row0) * F + h * DK + col0] =
            __floats2half2_rn(cacc0 * inv0, cacc1 * inv0);
        *(__half2*)&d_aoh[(i0 + row0 + 8) * F + h * DK + col0] =
            __floats2half2_rn(cacc2 * inv1, cacc3 * inv1);
    }
}

// ---------------- K5: output projection (pipelined mma) ----------------
__global__ void __launch_bounds__(256) out_mma(const float* __restrict__ Wo,
                                               const float* __restrict__ bo,
                                               const float* __restrict__ x,
                                               float* __restrict__ out) {
    __shared__ GemmSmem gs;
    int tid = threadIdx.x;
    int warp = tid >> 5, c = tid & 31;
    int bm0 = blockIdx.x * 128;
    int c0 = blockIdx.y * 32;

    float cc[4][4];
    #pragma unroll
    for (int nt = 0; nt < 4; ++nt)
        #pragma unroll
        for (int q = 0; q < 4; ++q) cc[nt][q] = 0.f;

    gemm_mainloop(gs, d_aoh, bm0, Wo, F, c0, tid, warp, c, cc);

    int r0 = bm0 + warp * 16 + (c >> 2);
    #pragma unroll
    for (int nt = 0; nt < 4; ++nt) {
        int col = c0 + nt * 8 + 2 * (c & 3);
        float2 bo2 = *(const float2*)&bo[col];
        float2 x0 = *(const float2*)&x[r0 * F + col];
        float2 x1 = *(const float2*)&x[(r0 + 8) * F + col];
        *(float2*)&out[r0 * F + col] =
            make_float2(cc[nt][0] + bo2.x + x0.x, cc[nt][1] + bo2.y + x0.y);
        *(float2*)&out[(r0 + 8) * F + col] =
            make_float2(cc[nt][2] + bo2.x + x1.x, cc[nt][3] + bo2.y + x1.y);
    }
}

// ---------------- launch ----------------
extern "C" void kernel_launch(void* const* d_in, const int* in_sizes, int n_in,
                              void* d_out, int out_size) {
    const float* x     = (const float*)d_in[0];
    const int*   adj   = (const int*)d_in[1];
    const float* Wq    = (const float*)d_in[2];
    const float* Wk    = (const float*)d_in[3];
    const float* Wv    = (const float*)d_in[4];
    const float* a     = (const float*)d_in[5];
    const float* Wo    = (const float*)d_in[6];
    const float* bo    = (const float*)d_in[7];
    const float* gamma = (const float*)d_in[8];
    const float* beta  = (const float*)d_in[9];
    float* out = (float*)d_out;

    cudaFuncSetAttribute(attn_kernel, cudaFuncAttributeMaxDynamicSharedMemorySize,
                         (int)sizeof(AttnSmem));

    prep_kernel<<<PACK_BLOCKS + N_NODES, 256>>>(adj, a, x, gamma, beta);
    qkv_mma<<<dim3(N_NODES / 128, 24), 256>>>(Wq, Wk, Wv, a);
    attn_kernel<<<dim3(N_NODES / BI, H), 256, sizeof(AttnSmem)>>>();
    out_mma<<<dim3(N_NODES / 128, F / 32), 256>>>(Wo, bo, x, out);
}

// round 15
// speedup vs baseline: 2.0567x; 1.0088x over previous
#include <cuda_runtime.h>
#include <cuda_fp16.h>

#define N_NODES 2048
#define F 256
#define H 8
#define DK 32
#define ALPHA 0.2f
#define LN_EPS 1e-5f

typedef unsigned long long ull;

// ---------------- scratch (no allocations allowed) ----------------
__device__ __half d_hbufh[N_NODES * F];             // fp16 LN output
__device__ __half2 d_Qh2[H * N_NODES * (DK / 2)];   // fp16 Q, d-pairs
__device__ __half2 d_Kh2[H * N_NODES * (DK / 2)];   // fp16 K, d-pairs
__device__ __half  d_Vh[H * N_NODES * DK];          // fp16 V, [node][d]
__device__ float d_bq[H * N_NODES];
__device__ float d_bk[H * N_NODES];
__device__ __half2 d_afh2[H * (DK / 2)];            // a' d-pairs
__device__ unsigned d_adjb[N_NODES * (N_NODES / 32)];
__device__ __half d_aoh[N_NODES * F];               // fp16 attention output

// ---------------- helpers ----------------
__device__ __forceinline__ float ex2f(float x) {
    float r; asm("ex2.approx.f32 %0, %1;" : "=f"(r) : "f"(x)); return r;
}
__device__ __forceinline__ unsigned hrelu_add(unsigned k, unsigned q, unsigned one2) {
    unsigned d;
    asm("fma.rn.relu.f16x2 %0, %1, %2, %3;"
        : "=r"(d) : "r"(k), "r"(one2), "r"(q));
    return d;
}
__device__ __forceinline__ void ldm_x4(unsigned& a0, unsigned& a1, unsigned& a2,
                                       unsigned& a3, unsigned addr) {
    asm volatile("ldmatrix.sync.aligned.m8n8.x4.shared.b16 {%0,%1,%2,%3}, [%4];"
                 : "=r"(a0), "=r"(a1), "=r"(a2), "=r"(a3) : "r"(addr));
}
__device__ __forceinline__ void ldm_x2t(unsigned& b0, unsigned& b1, unsigned addr) {
    asm volatile("ldmatrix.sync.aligned.m8n8.x2.trans.shared.b16 {%0,%1}, [%2];"
                 : "=r"(b0), "=r"(b1) : "r"(addr));
}
__device__ __forceinline__ void mma16816(float& c0, float& c1, float& c2, float& c3,
                                         unsigned a0, unsigned a1, unsigned a2,
                                         unsigned a3, unsigned b0, unsigned b1) {
    asm volatile("mma.sync.aligned.m16n8k16.row.col.f32.f16.f16.f32 "
                 "{%0,%1,%2,%3}, {%4,%5,%6,%7}, {%8,%9}, {%0,%1,%2,%3};"
                 : "+f"(c0), "+f"(c1), "+f"(c2), "+f"(c3)
                 : "r"(a0), "r"(a1), "r"(a2), "r"(a3), "r"(b0), "r"(b1));
}

// ---------------- K1: adjacency pack + a' fold + LayerNorm (merged) ----------------
#define PACK_BLOCKS (N_NODES * N_NODES / 4 / 256)   // 4096

__global__ void __launch_bounds__(256) prep_kernel(const int* __restrict__ adj,
                                                   const float* __restrict__ a,
                                                   const float* __restrict__ x,
                                                   const float* __restrict__ gamma,
                                                   const float* __restrict__ beta) {
    int bx = blockIdx.x;
    if (bx < PACK_BLOCKS) {
        int t = bx * 256 + threadIdx.x;
        int warp = t >> 5, lane = t & 31;
        int base = warp * 128;
        unsigned m0 = __ballot_sync(0xffffffffu, adj[base + lane] != 0);
        unsigned m1 = __ballot_sync(0xffffffffu, adj[base + 32 + lane] != 0);
        unsigned m2 = __ballot_sync(0xffffffffu, adj[base + 64 + lane] != 0);
        unsigned m3 = __ballot_sync(0xffffffffu, adj[base + 96 + lane] != 0);
        if (lane == 0) *(uint4*)&d_adjb[warp * 4] = make_uint4(m0, m1, m2, m3);
        if (bx == 0 && threadIdx.x < H * (DK / 2)) {
            const float C = (1.0f - ALPHA) * 0.17677669529663687f * 1.4426950408889634f;
            float2 av = *(const float2*)&a[2 * threadIdx.x];
            d_afh2[threadIdx.x] = __floats2half2_rn(C * av.x, C * av.y);
        }
    } else {
        int row = bx - PACK_BLOCKS;
        int t = threadIdx.x;
        float v = x[row * F + t];
        float s = v, s2 = v * v;
        #pragma unroll
        for (int m = 16; m > 0; m >>= 1) {
            s  += __shfl_xor_sync(0xffffffffu, s, m);
            s2 += __shfl_xor_sync(0xffffffffu, s2, m);
        }
        __shared__ float ws[8], ws2[8];
        if ((t & 31) == 0) { ws[t >> 5] = s; ws2[t >> 5] = s2; }
        __syncthreads();
        float tot = 0.f, tot2 = 0.f;
        #pragma unroll
        for (int w = 0; w < 8; ++w) { tot += ws[w]; tot2 += ws2[w]; }
        float mu = tot * (1.0f / F);
        float var = tot2 * (1.0f / F) - mu * mu;
        float inv = rsqrtf(var + LN_EPS);
        d_hbufh[row * F + t] = __float2half((v - mu) * inv * gamma[t] + beta[t]);
    }
}

// ---------------- pipelined 64-row GEMM mainloop (shared by qkv/out) ----------------
// A: fp16 gmem [64 rows x 256 k], B: fp32 gmem [k x n], 8 double-buffered k32 stages.
// Warp (wr, wn): rows wr*16, n-half wn*16. Result cc[2][4] per thread.
struct GemmSmem64 {
    __half sA[2][64][40];   // 10.2KB
    __half sB[2][32][40];   // 5.1KB
};

__device__ __forceinline__ void gemm_mainloop64(
    GemmSmem64& gs, const __half* __restrict__ Asrc, int bm0,
    const float* __restrict__ Bsrc, int ldB, int cb,
    int tid, int wr, int wn, int c, float cc[2][4]) {

    int arow = tid >> 2, aq = (tid & 3) * 8;
    int bk = tid >> 3, bn = (tid & 7) * 4;

    unsigned aAddr0 = (unsigned)__cvta_generic_to_shared(
        &gs.sA[0][wr * 16 + (c & 15)][(c >> 4) * 8]);
    unsigned bAddr0 = (unsigned)__cvta_generic_to_shared(
        &gs.sB[0][c & 15][wn * 16]);

    // prefetch stage 0
    uint4 aR = *(const uint4*)&Asrc[(bm0 + arow) * F + aq];
    float4 wv = *(const float4*)&Bsrc[bk * ldB + cb + bn];
    *(uint4*)&gs.sA[0][arow][aq] = aR;
    {
        __half2 b0 = __floats2half2_rn(wv.x, wv.y);
        __half2 b1 = __floats2half2_rn(wv.z, wv.w);
        uint2 pk; pk.x = *(unsigned*)&b0; pk.y = *(unsigned*)&b1;
        *(uint2*)&gs.sB[0][bk][bn] = pk;
    }
    __syncthreads();

    #pragma unroll
    for (int it = 0; it < 8; ++it) {
        int cur = it & 1;
        if (it < 7) {
            int k0 = (it + 1) * 32;
            aR = *(const uint4*)&Asrc[(bm0 + arow) * F + k0 + aq];
            wv = *(const float4*)&Bsrc[(k0 + bk) * ldB + cb + bn];
        }
        unsigned aBase = aAddr0 + cur * (64 * 40 * 2);
        unsigned bBase = bAddr0 + cur * (32 * 40 * 2);
        #pragma unroll
        for (int ks = 0; ks < 2; ++ks) {
            unsigned a0, a1, a2, a3;
            ldm_x4(a0, a1, a2, a3, aBase + ks * 32);
            #pragma unroll
            for (int nt = 0; nt < 2; ++nt) {
                unsigned b0, b1;
                ldm_x2t(b0, b1, bBase + ks * 16 * 80 + nt * 16);
                mma16816(cc[nt][0], cc[nt][1], cc[nt][2], cc[nt][3],
                         a0, a1, a2, a3, b0, b1);
            }
        }
        if (it < 7) {
            int nxt = 1 - cur;
            *(uint4*)&gs.sA[nxt][arow][aq] = aR;
            __half2 b0 = __floats2half2_rn(wv.x, wv.y);
            __half2 b1 = __floats2half2_rn(wv.z, wv.w);
            uint2 pk; pk.x = *(unsigned*)&b0; pk.y = *(unsigned*)&b1;
            *(uint2*)&gs.sB[nxt][bk][bn] = pk;
        }
        __syncthreads();
    }
}

// ---------------- K3: QKV projection (pipelined 64-row mma) ----------------
// grid(32, 24): y = which*8 + head.
__global__ void __launch_bounds__(256) qkv_mma(const float* __restrict__ Wq,
                                               const float* __restrict__ Wk,
                                               const float* __restrict__ Wv,
                                               const float* __restrict__ a) {
    __shared__ GemmSmem64 gs;
    __shared__ float sPart[64][2];
    int tid = threadIdx.x;
    int warp = tid >> 5, c = tid & 31;
    int wr = warp & 3, wn = warp >> 2;
    int bm0 = blockIdx.x * 64;
    int by = blockIdx.y;
    int which = by >> 3, hh = by & 7;
    const float* W = ((which == 0) ? Wq : (which == 1) ? Wk : Wv) + hh * (F * DK);

    float cc[2][4];
    #pragma unroll
    for (int nt = 0; nt < 2; ++nt)
        #pragma unroll
        for (int q = 0; q < 4; ++q) cc[nt][q] = 0.f;

    gemm_mainloop64(gs, d_hbufh, bm0, W, DK, 0, tid, wr, wn, c, cc);

    int r0 = bm0 + wr * 16 + (c >> 2);
    if (which == 2) {
        __half* dstV = d_Vh + hh * N_NODES * DK;
        #pragma unroll
        for (int nt = 0; nt < 2; ++nt) {
            int col0 = wn * 16 + nt * 8 + 2 * (c & 3);
            *(__half2*)&dstV[r0 * DK + col0] = __floats2half2_rn(cc[nt][0], cc[nt][1]);
            *(__half2*)&dstV[(r0 + 8) * DK + col0] = __floats2half2_rn(cc[nt][2], cc[nt][3]);
        }
    } else {
        const float CC = ALPHA * 0.17677669529663687f * 1.4426950408889634f;
        __half2* dstH = ((which == 0) ? d_Qh2 : d_Kh2) + hh * N_NODES * 16;
        float* dstB = ((which == 0) ? d_bq : d_bk) + hh * N_NODES;
        float p0 = 0.f, p1 = 0.f;
        #pragma unroll
        for (int nt = 0; nt < 2; ++nt) {
            int col0 = wn * 16 + nt * 8 + 2 * (c & 3);
            float a0v = a[hh * DK + col0];
            float a1v = a[hh * DK + col0 + 1];
            dstH[r0 * 16 + (col0 >> 1)] = __floats2half2_rn(cc[nt][0], cc[nt][1]);
            dstH[(r0 + 8) * 16 + (col0 >> 1)] = __floats2half2_rn(cc[nt][2], cc[nt][3]);
            p0 += a0v * cc[nt][0] + a1v * cc[nt][1];
            p1 += a0v * cc[nt][2] + a1v * cc[nt][3];
        }
        p0 += __shfl_xor_sync(0xffffffffu, p0, 1);
        p0 += __shfl_xor_sync(0xffffffffu, p0, 2);
        p1 += __shfl_xor_sync(0xffffffffu, p1, 1);
        p1 += __shfl_xor_sync(0xffffffffu, p1, 2);
        if ((c & 3) == 0) {
            int lr = wr * 16 + (c >> 2);
            sPart[lr][wn] = p0;
            sPart[lr + 8][wn] = p1;
        }
        __syncthreads();
        if (tid < 64)
            dstB[bm0 + tid] = CC * (sPart[tid][0] + sPart[tid][1]);
    }
}

// ---------------- K4: fused GAT attention (mma logits + mma PV) ----------------
#define BI 32
#define BJ 128
#define NJT (N_NODES / BJ)

struct AttnSmem {
    __half  sPh[BI][136];
    __half  sVh[BJ][40];
    __half  sKh[BJ][40];
    float   sLog[BI][128];
    __half2 sQh[BI][17];
    unsigned sAdj[BI][64];
    float   sBq[BI];
    float   sBk[BJ];
    float   sL[BI];
};

__global__ void __launch_bounds__(256, 4) attn_kernel() {
    extern __shared__ char smem_raw[];
    AttnSmem& sm = *reinterpret_cast<AttnSmem*>(smem_raw);
    int tid = threadIdx.x;
    int h = blockIdx.y;
    int i0 = blockIdx.x * BI;
    int hN = h * N_NODES;
    const __half2* Qh2 = d_Qh2 + hN * 16;
    const __half2* Kh2 = d_Kh2 + hN * 16;
    const __half*  Vh  = d_Vh + hN * DK;

    if (tid < 128) {
        int i = tid >> 2, q4 = (tid & 3) * 4;
        uint4 qv = *(const uint4*)&Qh2[(i0 + i) * 16 + q4];
        sm.sQh[i][q4 + 0] = *(__half2*)&qv.x;
        sm.sQh[i][q4 + 1] = *(__half2*)&qv.y;
        sm.sQh[i][q4 + 2] = *(__half2*)&qv.z;
        sm.sQh[i][q4 + 3] = *(__half2*)&qv.w;
    }
    if (tid < BI) sm.sBq[tid] = d_bq[hN + i0 + tid];
    for (int idx = tid; idx < BI * 64; idx += 256)
        sm.sAdj[idx >> 6][idx & 63] = d_adjb[(i0 + (idx >> 6)) * 64 + (idx & 63)];
    __syncthreads();

    int r = tid >> 5;
    int c = tid & 31;
    int mh = r >> 2;
    int nq = r & 3;
    int l4 = c & 3;

    unsigned qE[2][2], qEh[2][2], qO[2][2], qOh[2][2];
    #pragma unroll
    for (int ig = 0; ig < 2; ++ig) {
        int iE = 4 * r + 2 * ig, iO = iE + 1;
        #pragma unroll
        for (int s = 0; s < 2; ++s) {
            qE[ig][s]  = *(unsigned*)&sm.sQh[iE][s * 8 + l4];
            qEh[ig][s] = *(unsigned*)&sm.sQh[iE][s * 8 + 4 + l4];
            qO[ig][s]  = *(unsigned*)&sm.sQh[iO][s * 8 + l4];
            qOh[ig][s] = *(unsigned*)&sm.sQh[iO][s * 8 + 4 + l4];
        }
    }
    unsigned bLo[2], bHi[2];
    #pragma unroll
    for (int s = 0; s < 2; ++s) {
        bLo[s] = *(const unsigned*)&d_afh2[h * 16 + s * 8 + l4];
        bHi[s] = *(const unsigned*)&d_afh2[h * 16 + s * 8 + 4 + l4];
    }
    unsigned kBase4 = (unsigned)__cvta_generic_to_shared(
        &sm.sKh[c & 7][(c >> 3) * 8]);
    unsigned aAddrBase = (unsigned)__cvta_generic_to_shared(
        &sm.sPh[mh * 16 + (c & 15)][(c >> 4) * 8]);
    unsigned bAddrBase = (unsigned)__cvta_generic_to_shared(
        &sm.sVh[c & 15][nq * 8]);
    const unsigned one2 = 0x3c003c00u;

    float psum[4] = {0.f, 0.f, 0.f, 0.f};
    float cacc0 = 0.f, cacc1 = 0.f, cacc2 = 0.f, cacc3 = 0.f;

    for (int jt = 0; jt < NJT; ++jt) {
        int j0 = jt * BJ;
        __syncthreads();

        #pragma unroll
        for (int it = 0; it < 2; ++it) {
            int chunk = it * 256 + tid;
            int j = chunk >> 2, q8 = (chunk & 3) * 8;
            *(uint4*)&sm.sKh[j][q8] = *(const uint4*)&Kh2[(j0 + j) * 16 + (chunk & 3) * 4];
        }
        #pragma unroll
        for (int it = 0; it < 2; ++it) {
            int chunk = it * 256 + tid;
            int j = chunk >> 2, q8 = (chunk & 3) * 8;
            *(uint4*)&sm.sVh[j][q8] = *(const uint4*)&Vh[(j0 + j) * DK + q8];
        }
        if (tid < BJ) sm.sBk[tid] = d_bk[hN + j0 + tid];
        __syncthreads();

        #pragma unroll
        for (int jg = 0; jg < 16; ++jg) {
            unsigned kaL0, kaH0, kaL1, kaH1;
            ldm_x4(kaL0, kaH0, kaL1, kaH1, kBase4 + jg * 640);
            #pragma unroll
            for (int ig = 0; ig < 2; ++ig) {
                float c0 = 0.f, c1 = 0.f, c2v = 0.f, c3 = 0.f;
                mma16816(c0, c1, c2v, c3,
                         hrelu_add(kaL0, qE[ig][0], one2),
                         hrelu_add(kaL0, qO[ig][0], one2),
                         hrelu_add(kaH0, qEh[ig][0], one2),
                         hrelu_add(kaH0, qOh[ig][0], one2),
                         bLo[0], bHi[0]);
                mma16816(c0, c1, c2v, c3,
                         hrelu_add(kaL1, qE[ig][1], one2),
                         hrelu_add(kaL1, qO[ig][1], one2),
                         hrelu_add(kaH1, qEh[ig][1], one2),
                         hrelu_add(kaH1, qOh[ig][1], one2),
                         bLo[1], bHi[1]);
                int i0r = 4 * r + 2 * ig;
                int jj = jg * 8 + (c >> 2);
                if (l4 == 0) sm.sLog[i0r][jj] = c0;
                if (l4 == 1) sm.sLog[i0r + 1][jj] = c2v;
            }
        }
        __syncwarp();

        {
            int col = 4 * c;
            int wi = jt * 4 + (c >> 3);
            int sh = col & 31;
            float4 bk4 = *(const float4*)&sm.sBk[col];
            #pragma unroll
            for (int ii = 0; ii < 4; ++ii) {
                int i = 4 * r + ii;
                float bq = sm.sBq[i];
                float4 lg = *(const float4*)&sm.sLog[i][col];
                unsigned w = sm.sAdj[i][wi] >> sh;
                float p0 = (w & 1u) ? ex2f(lg.x + bq + bk4.x) : 0.f;
                float p1 = (w & 2u) ? ex2f(lg.y + bq + bk4.y) : 0.f;
                float p2 = (w & 4u) ? ex2f(lg.z + bq + bk4.z) : 0.f;
                float p3 = (w & 8u) ? ex2f(lg.w + bq + bk4.w) : 0.f;
                psum[ii] += (p0 + p1) + (p2 + p3);
                __half2 h0 = __floats2half2_rn(p0, p1);
                __half2 h1 = __floats2half2_rn(p2, p3);
                uint2 pk;
                pk.x = *(unsigned*)&h0;
                pk.y = *(unsigned*)&h1;
                *(uint2*)&sm.sPh[i][col] = pk;
            }
        }
        __syncthreads();

        #pragma unroll
        for (int ks = 0; ks < 8; ++ks) {
            unsigned a0, a1, a2r, a3, b0r, b1r;
            ldm_x4(a0, a1, a2r, a3, aAddrBase + ks * 32);
            ldm_x2t(b0r, b1r, bAddrBase + ks * 16 * 80);
            mma16816(cacc0, cacc1, cacc2, cacc3, a0, a1, a2r, a3, b0r, b1r);
        }
    }

    #pragma unroll
    for (int ii = 0; ii < 4; ++ii) {
        float v = psum[ii];
        v += __shfl_xor_sync(0xffffffffu, v, 16);
        v += __shfl_xor_sync(0xffffffffu, v, 8);
        v += __shfl_xor_sync(0xffffffffu, v, 4);
        v += __shfl_xor_sync(0xffffffffu, v, 2);
        v += __shfl_xor_sync(0xffffffffu, v, 1);
        if (c == 0) sm.sL[4 * r + ii] = v;
    }
    __syncthreads();

    {
        int row0 = mh * 16 + (c >> 2);
        int col0 = nq * 8 + 2 * (c & 3);
        float inv0 = 1.0f / sm.sL[row0];
        float inv1 = 1.0f / sm.sL[row0 + 8];
        *(__half2*)&d_aoh[(i0 + row0) * F + h * DK + col0] =
            __floats2half2_rn(cacc0 * inv0, cacc1 * inv0);
        *(__half2*)&d_aoh[(i0 + row0 + 8) * F + h * DK + col0] =
            __floats2half2_rn(cacc2 * inv1, cacc3 * inv1);
    }
}

// ---------------- K5: output projection (pipelined 64-row mma) ----------------
// grid(32, 8): bm0 = bx*64 rows, c0 = by*32 cols. fp32 bias + residual.
__global__ void __launch_bounds__(256) out_mma(const float* __restrict__ Wo,
                                               const float* __restrict__ bo,
                                               const float* __restrict__ x,
                                               float* __restrict__ out) {
    __shared__ GemmSmem64 gs;
    int tid = threadIdx.x;
    int warp = tid >> 5, c = tid & 31;
    int wr = warp & 3, wn = warp >> 2;
    int bm0 = blockIdx.x * 64;
    int c0 = blockIdx.y * 32;

    float cc[2][4];
    #pragma unroll
    for (int nt = 0; nt < 2; ++nt)
        #pragma unroll
        for (int q = 0; q < 4; ++q) cc[nt][q] = 0.f;

    gemm_mainloop64(gs, d_aoh, bm0, Wo, F, c0, tid, wr, wn, c, cc);

    int r0 = bm0 + wr * 16 + (c >> 2);
    #pragma unroll
    for (int nt = 0; nt < 2; ++nt) {
        int col = c0 + wn * 16 + nt * 8 + 2 * (c & 3);
        float2 bo2 = *(const float2*)&bo[col];
        float2 x0 = *(const float2*)&x[r0 * F + col];
        float2 x1 = *(const float2*)&x[(r0 + 8) * F + col];
        *(float2*)&out[r0 * F + col] =
            make_float2(cc[nt][0] + bo2.x + x0.x, cc[nt][1] + bo2.y + x0.y);
        *(float2*)&out[(r0 + 8) * F + col] =
            make_float2(cc[nt][2] + bo2.x + x1.x, cc[nt][3] + bo2.y + x1.y);
    }
}

// ---------------- launch ----------------
extern "C" void kernel_launch(void* const* d_in, const int* in_sizes, int n_in,
                              void* d_out, int out_size) {
    const float* x     = (const float*)d_in[0];
    const int*   adj   = (const int*)d_in[1];
    const float* Wq    = (const float*)d_in[2];
    const float* Wk    = (const float*)d_in[3];
    const float* Wv    = (const float*)d_in[4];
    const float* a     = (const float*)d_in[5];
    const float* Wo    = (const float*)d_in[6];
    const float* bo    = (const float*)d_in[7];
    const float* gamma = (const float*)d_in[8];
    const float* beta  = (const float*)d_in[9];
    float* out = (float*)d_out;

    cudaFuncSetAttribute(attn_kernel, cudaFuncAttributeMaxDynamicSharedMemorySize,
                         (int)sizeof(AttnSmem));

    prep_kernel<<<PACK_BLOCKS + N_NODES, 256>>>(adj, a, x, gamma, beta);
    qkv_mma<<<dim3(N_NODES / 64, 24), 256>>>(Wq, Wk, Wv, a);
    attn_kernel<<<dim3(N_NODES / BI, H), 256, sizeof(AttnSmem)>>>();
    out_mma<<<dim3(N_NODES / 64, F / 32), 256>>>(Wo, bo, x, out);
}

// round 16
// speedup vs baseline: 2.0703x; 1.0066x over previous
#include <cuda_runtime.h>
#include <cuda_fp16.h>

#define N_NODES 2048
#define F 256
#define H 8
#define DK 32
#define ALPHA 0.2f
#define LN_EPS 1e-5f

typedef unsigned long long ull;

// ---------------- scratch (no allocations allowed) ----------------
__device__ __half d_hbufh[N_NODES * F];             // fp16 LN output
__device__ __half d_Wh[4 * 65536];                  // fp16 weights [Wq|Wk|Wv|Wo]
__device__ __half2 d_Qh2[H * N_NODES * (DK / 2)];   // fp16 Q, d-pairs
__device__ __half2 d_Kh2[H * N_NODES * (DK / 2)];   // fp16 K, d-pairs
__device__ __half  d_Vh[H * N_NODES * DK];          // fp16 V, [node][d]
__device__ float d_bq[H * N_NODES];
__device__ float d_bk[H * N_NODES];
__device__ __half2 d_afh2[H * (DK / 2)];            // a' d-pairs
__device__ unsigned d_adjb[N_NODES * (N_NODES / 32)];
__device__ __half d_aoh[N_NODES * F];               // fp16 attention output

// ---------------- helpers ----------------
__device__ __forceinline__ float ex2f(float x) {
    float r; asm("ex2.approx.f32 %0, %1;" : "=f"(r) : "f"(x)); return r;
}
__device__ __forceinline__ unsigned hrelu_add(unsigned k, unsigned q, unsigned one2) {
    unsigned d;
    asm("fma.rn.relu.f16x2 %0, %1, %2, %3;"
        : "=r"(d) : "r"(k), "r"(one2), "r"(q));
    return d;
}
__device__ __forceinline__ void ldm_x4(unsigned& a0, unsigned& a1, unsigned& a2,
                                       unsigned& a3, unsigned addr) {
    asm volatile("ldmatrix.sync.aligned.m8n8.x4.shared.b16 {%0,%1,%2,%3}, [%4];"
                 : "=r"(a0), "=r"(a1), "=r"(a2), "=r"(a3) : "r"(addr));
}
__device__ __forceinline__ void ldm_x2t(unsigned& b0, unsigned& b1, unsigned addr) {
    asm volatile("ldmatrix.sync.aligned.m8n8.x2.trans.shared.b16 {%0,%1}, [%2];"
                 : "=r"(b0), "=r"(b1) : "r"(addr));
}
__device__ __forceinline__ void mma16816(float& c0, float& c1, float& c2, float& c3,
                                         unsigned a0, unsigned a1, unsigned a2,
                                         unsigned a3, unsigned b0, unsigned b1) {
    asm volatile("mma.sync.aligned.m16n8k16.row.col.f32.f16.f16.f32 "
                 "{%0,%1,%2,%3}, {%4,%5,%6,%7}, {%8,%9}, {%0,%1,%2,%3};"
                 : "+f"(c0), "+f"(c1), "+f"(c2), "+f"(c3)
                 : "r"(a0), "r"(a1), "r"(a2), "r"(a3), "r"(b0), "r"(b1));
}
__device__ __forceinline__ void cpa16(unsigned s, const void* g) {
    asm volatile("cp.async.ca.shared.global [%0], [%1], 16;" :: "r"(s), "l"(g));
}
__device__ __forceinline__ void cpa_commit() {
    asm volatile("cp.async.commit_group;" ::: "memory");
}
template <int N>
__device__ __forceinline__ void cpa_wait() {
    asm volatile("cp.async.wait_group %0;" :: "n"(N) : "memory");
}

// ---------------- K1: adj pack + a' fold + LayerNorm + weight fp16 convert ----------------
#define PACK_BLOCKS (N_NODES * N_NODES / 4 / 256)   // 4096
#define LN_BLOCKS N_NODES
#define WCONV_BLOCKS 128                             // 4*65536 halves / 8 / 256

__global__ void __launch_bounds__(256) prep_kernel(const int* __restrict__ adj,
                                                   const float* __restrict__ a,
                                                   const float* __restrict__ x,
                                                   const float* __restrict__ gamma,
                                                   const float* __restrict__ beta,
                                                   const float* __restrict__ Wq,
                                                   const float* __restrict__ Wk,
                                                   const float* __restrict__ Wv,
                                                   const float* __restrict__ Wo) {
    int bx = blockIdx.x;
    if (bx < PACK_BLOCKS) {
        int t = bx * 256 + threadIdx.x;
        int warp = t >> 5, lane = t & 31;
        int base = warp * 128;
        unsigned m0 = __ballot_sync(0xffffffffu, adj[base + lane] != 0);
        unsigned m1 = __ballot_sync(0xffffffffu, adj[base + 32 + lane] != 0);
        unsigned m2 = __ballot_sync(0xffffffffu, adj[base + 64 + lane] != 0);
        unsigned m3 = __ballot_sync(0xffffffffu, adj[base + 96 + lane] != 0);
        if (lane == 0) *(uint4*)&d_adjb[warp * 4] = make_uint4(m0, m1, m2, m3);
        if (bx == 0 && threadIdx.x < H * (DK / 2)) {
            const float C = (1.0f - ALPHA) * 0.17677669529663687f * 1.4426950408889634f;
            float2 av = *(const float2*)&a[2 * threadIdx.x];
            d_afh2[threadIdx.x] = __floats2half2_rn(C * av.x, C * av.y);
        }
    } else if (bx < PACK_BLOCKS + LN_BLOCKS) {
        int row = bx - PACK_BLOCKS;
        int t = threadIdx.x;
        float v = x[row * F + t];
        float s = v, s2 = v * v;
        #pragma unroll
        for (int m = 16; m > 0; m >>= 1) {
            s  += __shfl_xor_sync(0xffffffffu, s, m);
            s2 += __shfl_xor_sync(0xffffffffu, s2, m);
        }
        __shared__ float ws[8], ws2[8];
        if ((t & 31) == 0) { ws[t >> 5] = s; ws2[t >> 5] = s2; }
        __syncthreads();
        float tot = 0.f, tot2 = 0.f;
        #pragma unroll
        for (int w = 0; w < 8; ++w) { tot += ws[w]; tot2 += ws2[w]; }
        float mu = tot * (1.0f / F);
        float var = tot2 * (1.0f / F) - mu * mu;
        float inv = rsqrtf(var + LN_EPS);
        d_hbufh[row * F + t] = __float2half((v - mu) * inv * gamma[t] + beta[t]);
    } else {
        int gi = (bx - PACK_BLOCKS - LN_BLOCKS) * 256 + threadIdx.x;  // 8 halves each
        int m = gi >> 13;
        int off = (gi & 8191) * 8;
        const float* src = (m == 0) ? Wq : (m == 1) ? Wk : (m == 2) ? Wv : Wo;
        float4 f0 = *(const float4*)&src[off];
        float4 f1 = *(const float4*)&src[off + 4];
        __half2 h0 = __floats2half2_rn(f0.x, f0.y);
        __half2 h1 = __floats2half2_rn(f0.z, f0.w);
        __half2 h2 = __floats2half2_rn(f1.x, f1.y);
        __half2 h3 = __floats2half2_rn(f1.z, f1.w);
        uint4 pk;
        pk.x = *(unsigned*)&h0; pk.y = *(unsigned*)&h1;
        pk.z = *(unsigned*)&h2; pk.w = *(unsigned*)&h3;
        *(uint4*)&d_Wh[m * 65536 + off] = pk;
    }
}

// ---------------- 4-stage cp.async 64-row GEMM mainloop ----------------
#define STAGES 4

struct GemmSmem64 {
    __align__(16) __half sA[STAGES][64][40];   // 20.5KB
    __align__(16) __half sB[STAGES][32][40];   // 10.2KB
};

__device__ __forceinline__ void gemm_mainloop64(
    GemmSmem64& gs, const __half* __restrict__ Asrc, int bm0,
    const __half* __restrict__ Bsrc, int ldB, int cb,
    int tid, int wr, int wn, int c, float cc[2][4]) {

    int arow = tid >> 2, aq = (tid & 3) * 8;            // A: 256 thr x 16B
    int bk = (tid & 127) >> 2, bq_ = (tid & 3) * 8;     // B: 128 thr x 16B
    bool doB = tid < 128;

    const __half* aG = Asrc + (bm0 + arow) * F + aq;
    const __half* bG = Bsrc + bk * ldB + cb + bq_;

    unsigned aS[STAGES], bS[STAGES];
    #pragma unroll
    for (int st = 0; st < STAGES; ++st) {
        aS[st] = (unsigned)__cvta_generic_to_shared(&gs.sA[st][arow][aq]);
        bS[st] = (unsigned)__cvta_generic_to_shared(&gs.sB[st][bk][bq_]);
    }
    unsigned aAddr0 = (unsigned)__cvta_generic_to_shared(
        &gs.sA[0][wr * 16 + (c & 15)][(c >> 4) * 8]);
    unsigned bAddr0 = (unsigned)__cvta_generic_to_shared(
        &gs.sB[0][c & 15][wn * 16]);

    // prologue: stages 0..2
    #pragma unroll
    for (int st = 0; st < 3; ++st) {
        cpa16(aS[st], aG + st * 32);
        if (doB) cpa16(bS[st], bG + st * 32 * ldB);
        cpa_commit();
    }

    #pragma unroll
    for (int it = 0; it < 8; ++it) {
        int st = it & 3;
        cpa_wait<2>();
        __syncthreads();
        unsigned aBase = aAddr0 + st * (64 * 40 * 2);
        unsigned bBase = bAddr0 + st * (32 * 40 * 2);
        #pragma unroll
        for (int ks = 0; ks < 2; ++ks) {
            unsigned a0, a1, a2, a3;
            ldm_x4(a0, a1, a2, a3, aBase + ks * 32);
            #pragma unroll
            for (int nt = 0; nt < 2; ++nt) {
                unsigned b0, b1;
                ldm_x2t(b0, b1, bBase + ks * 16 * 80 + nt * 16);
                mma16816(cc[nt][0], cc[nt][1], cc[nt][2], cc[nt][3],
                         a0, a1, a2, a3, b0, b1);
            }
        }
        if (it < 5) {
            int ns = (it + 3) & 3;
            int k0 = (it + 3) * 32;
            cpa16(aS[ns], aG + k0);
            if (doB) cpa16(bS[ns], bG + k0 * ldB);
        }
        cpa_commit();
    }
}

// ---------------- K3: QKV projection (cp.async mma) ----------------
// grid(32, 24): y = which*8 + head.
__global__ void __launch_bounds__(256) qkv_mma(const float* __restrict__ a) {
    __shared__ GemmSmem64 gs;
    __shared__ float sPart[64][2];
    int tid = threadIdx.x;
    int warp = tid >> 5, c = tid & 31;
    int wr = warp & 3, wn = warp >> 2;
    int bm0 = blockIdx.x * 64;
    int by = blockIdx.y;
    int which = by >> 3, hh = by & 7;
    const __half* W = d_Wh + which * 65536 + hh * (F * DK);

    float cc[2][4];
    #pragma unroll
    for (int nt = 0; nt < 2; ++nt)
        #pragma unroll
        for (int q = 0; q < 4; ++q) cc[nt][q] = 0.f;

    gemm_mainloop64(gs, d_hbufh, bm0, W, DK, 0, tid, wr, wn, c, cc);

    int r0 = bm0 + wr * 16 + (c >> 2);
    if (which == 2) {
        __half* dstV = d_Vh + hh * N_NODES * DK;
        #pragma unroll
        for (int nt = 0; nt < 2; ++nt) {
            int col0 = wn * 16 + nt * 8 + 2 * (c & 3);
            *(__half2*)&dstV[r0 * DK + col0] = __floats2half2_rn(cc[nt][0], cc[nt][1]);
            *(__half2*)&dstV[(r0 + 8) * DK + col0] = __floats2half2_rn(cc[nt][2], cc[nt][3]);
        }
    } else {
        const float CC = ALPHA * 0.17677669529663687f * 1.4426950408889634f;
        __half2* dstH = ((which == 0) ? d_Qh2 : d_Kh2) + hh * N_NODES * 16;
        float* dstB = ((which == 0) ? d_bq : d_bk) + hh * N_NODES;
        float p0 = 0.f, p1 = 0.f;
        #pragma unroll
        for (int nt = 0; nt < 2; ++nt) {
            int col0 = wn * 16 + nt * 8 + 2 * (c & 3);
            float a0v = a[hh * DK + col0];
            float a1v = a[hh * DK + col0 + 1];
            dstH[r0 * 16 + (col0 >> 1)] = __floats2half2_rn(cc[nt][0], cc[nt][1]);
            dstH[(r0 + 8) * 16 + (col0 >> 1)] = __floats2half2_rn(cc[nt][2], cc[nt][3]);
            p0 += a0v * cc[nt][0] + a1v * cc[nt][1];
            p1 += a0v * cc[nt][2] + a1v * cc[nt][3];
        }
        p0 += __shfl_xor_sync(0xffffffffu, p0, 1);
        p0 += __shfl_xor_sync(0xffffffffu, p0, 2);
        p1 += __shfl_xor_sync(0xffffffffu, p1, 1);
        p1 += __shfl_xor_sync(0xffffffffu, p1, 2);
        if ((c & 3) == 0) {
            int lr = wr * 16 + (c >> 2);
            sPart[lr][wn] = p0;
            sPart[lr + 8][wn] = p1;
        }
        __syncthreads();
        if (tid < 64)
            dstB[bm0 + tid] = CC * (sPart[tid][0] + sPart[tid][1]);
    }
}

// ---------------- K4: fused GAT attention (mma logits + mma PV) ----------------
#define BI 32
#define BJ 128
#define NJT (N_NODES / BJ)

struct AttnSmem {
    __half  sPh[BI][136];
    __half  sVh[BJ][40];
    __half  sKh[BJ][40];
    float   sLog[BI][128];
    __half2 sQh[BI][17];
    unsigned sAdj[BI][64];
    float   sBq[BI];
    float   sBk[BJ];
    float   sL[BI];
};

__global__ void __launch_bounds__(256, 4) attn_kernel() {
    extern __shared__ char smem_raw[];
    AttnSmem& sm = *reinterpret_cast<AttnSmem*>(smem_raw);
    int tid = threadIdx.x;
    int h = blockIdx.y;
    int i0 = blockIdx.x * BI;
    int hN = h * N_NODES;
    const __half2* Qh2 = d_Qh2 + hN * 16;
    const __half2* Kh2 = d_Kh2 + hN * 16;
    const __half*  Vh  = d_Vh + hN * DK;

    if (tid < 128) {
        int i = tid >> 2, q4 = (tid & 3) * 4;
        uint4 qv = *(const uint4*)&Qh2[(i0 + i) * 16 + q4];
        sm.sQh[i][q4 + 0] = *(__half2*)&qv.x;
        sm.sQh[i][q4 + 1] = *(__half2*)&qv.y;
        sm.sQh[i][q4 + 2] = *(__half2*)&qv.z;
        sm.sQh[i][q4 + 3] = *(__half2*)&qv.w;
    }
    if (tid < BI) sm.sBq[tid] = d_bq[hN + i0 + tid];
    for (int idx = tid; idx < BI * 64; idx += 256)
        sm.sAdj[idx >> 6][idx & 63] = d_adjb[(i0 + (idx >> 6)) * 64 + (idx & 63)];
    __syncthreads();

    int r = tid >> 5;
    int c = tid & 31;
    int mh = r >> 2;
    int nq = r & 3;
    int l4 = c & 3;

    unsigned qE[2][2], qEh[2][2], qO[2][2], qOh[2][2];
    #pragma unroll
    for (int ig = 0; ig < 2; ++ig) {
        int iE = 4 * r + 2 * ig, iO = iE + 1;
        #pragma unroll
        for (int s = 0; s < 2; ++s) {
            qE[ig][s]  = *(unsigned*)&sm.sQh[iE][s * 8 + l4];
            qEh[ig][s] = *(unsigned*)&sm.sQh[iE][s * 8 + 4 + l4];
            qO[ig][s]  = *(unsigned*)&sm.sQh[iO][s * 8 + l4];
            qOh[ig][s] = *(unsigned*)&sm.sQh[iO][s * 8 + 4 + l4];
        }
    }
    unsigned bLo[2], bHi[2];
    #pragma unroll
    for (int s = 0; s < 2; ++s) {
        bLo[s] = *(const unsigned*)&d_afh2[h * 16 + s * 8 + l4];
        bHi[s] = *(const unsigned*)&d_afh2[h * 16 + s * 8 + 4 + l4];
    }
    unsigned kBase4 = (unsigned)__cvta_generic_to_shared(
        &sm.sKh[c & 7][(c >> 3) * 8]);
    unsigned aAddrBase = (unsigned)__cvta_generic_to_shared(
        &sm.sPh[mh * 16 + (c & 15)][(c >> 4) * 8]);
    unsigned bAddrBase = (unsigned)__cvta_generic_to_shared(
        &sm.sVh[c & 15][nq * 8]);
    const unsigned one2 = 0x3c003c00u;

    float psum[4] = {0.f, 0.f, 0.f, 0.f};
    float cacc0 = 0.f, cacc1 = 0.f, cacc2 = 0.f, cacc3 = 0.f;

    for (int jt = 0; jt < NJT; ++jt) {
        int j0 = jt * BJ;
        __syncthreads();

        #pragma unroll
        for (int it = 0; it < 2; ++it) {
            int chunk = it * 256 + tid;
            int j = chunk >> 2, q8 = (chunk & 3) * 8;
            *(uint4*)&sm.sKh[j][q8] = *(const uint4*)&Kh2[(j0 + j) * 16 + (chunk & 3) * 4];
        }
        #pragma unroll
        for (int it = 0; it < 2; ++it) {
            int chunk = it * 256 + tid;
            int j = chunk >> 2, q8 = (chunk & 3) * 8;
            *(uint4*)&sm.sVh[j][q8] = *(const uint4*)&Vh[(j0 + j) * DK + q8];
        }
        if (tid < BJ) sm.sBk[tid] = d_bk[hN + j0 + tid];
        __syncthreads();

        #pragma unroll
        for (int jg = 0; jg < 16; ++jg) {
            unsigned kaL0, kaH0, kaL1, kaH1;
            ldm_x4(kaL0, kaH0, kaL1, kaH1, kBase4 + jg * 640);
            #pragma unroll
            for (int ig = 0; ig < 2; ++ig) {
                float c0 = 0.f, c1 = 0.f, c2v = 0.f, c3 = 0.f;
                mma16816(c0, c1, c2v, c3,
                         hrelu_add(kaL0, qE[ig][0], one2),
                         hrelu_add(kaL0, qO[ig][0], one2),
                         hrelu_add(kaH0, qEh[ig][0], one2),
                         hrelu_add(kaH0, qOh[ig][0], one2),
                         bLo[0], bHi[0]);
                mma16816(c0, c1, c2v, c3,
                         hrelu_add(kaL1, qE[ig][1], one2),
                         hrelu_add(kaL1, qO[ig][1], one2),
                         hrelu_add(kaH1, qEh[ig][1], one2),
                         hrelu_add(kaH1, qOh[ig][1], one2),
                         bLo[1], bHi[1]);
                int i0r = 4 * r + 2 * ig;
                int jj = jg * 8 + (c >> 2);
                if (l4 == 0) sm.sLog[i0r][jj] = c0;
                if (l4 == 1) sm.sLog[i0r + 1][jj] = c2v;
            }
        }
        __syncwarp();

        {
            int col = 4 * c;
            int wi = jt * 4 + (c >> 3);
            int sh = col & 31;
            float4 bk4 = *(const float4*)&sm.sBk[col];
            #pragma unroll
            for (int ii = 0; ii < 4; ++ii) {
                int i = 4 * r + ii;
                float bq = sm.sBq[i];
                float4 lg = *(const float4*)&sm.sLog[i][col];
                unsigned w = sm.sAdj[i][wi] >> sh;
                float p0 = (w & 1u) ? ex2f(lg.x + bq + bk4.x) : 0.f;
                float p1 = (w & 2u) ? ex2f(lg.y + bq + bk4.y) : 0.f;
                float p2 = (w & 4u) ? ex2f(lg.z + bq + bk4.z) : 0.f;
                float p3 = (w & 8u) ? ex2f(lg.w + bq + bk4.w) : 0.f;
                psum[ii] += (p0 + p1) + (p2 + p3);
                __half2 h0 = __floats2half2_rn(p0, p1);
                __half2 h1 = __floats2half2_rn(p2, p3);
                uint2 pk;
                pk.x = *(unsigned*)&h0;
                pk.y = *(unsigned*)&h1;
                *(uint2*)&sm.sPh[i][col] = pk;
            }
        }
        __syncthreads();

        #pragma unroll
        for (int ks = 0; ks < 8; ++ks) {
            unsigned a0, a1, a2r, a3, b0r, b1r;
            ldm_x4(a0, a1, a2r, a3, aAddrBase + ks * 32);
            ldm_x2t(b0r, b1r, bAddrBase + ks * 16 * 80);
            mma16816(cacc0, cacc1, cacc2, cacc3, a0, a1, a2r, a3, b0r, b1r);
        }
    }

    #pragma unroll
    for (int ii = 0; ii < 4; ++ii) {
        float v = psum[ii];
        v += __shfl_xor_sync(0xffffffffu, v, 16);
        v += __shfl_xor_sync(0xffffffffu, v, 8);
        v += __shfl_xor_sync(0xffffffffu, v, 4);
        v += __shfl_xor_sync(0xffffffffu, v, 2);
        v += __shfl_xor_sync(0xffffffffu, v, 1);
        if (c == 0) sm.sL[4 * r + ii] = v;
    }
    __syncthreads();

    {
        int row0 = mh * 16 + (c >> 2);
        int col0 = nq * 8 + 2 * (c & 3);
        float inv0 = 1.0f / sm.sL[row0];
        float inv1 = 1.0f / sm.sL[row0 + 8];
        *(__half2*)&d_aoh[(i0 + row0) * F + h * DK + col0] =
            __floats2half2_rn(cacc0 * inv0, cacc1 * inv0);
        *(__half2*)&d_aoh[(i0 + row0 + 8) * F + h * DK + col0] =
            __floats2half2_rn(cacc2 * inv1, cacc3 * inv1);
    }
}

// ---------------- K5: output projection (cp.async mma) ----------------
// grid(32, 8): bm0 = bx*64 rows, c0 = by*32 cols. fp32 bias + residual.
__global__ void __launch_bounds__(256) out_mma(const float* __restrict__ bo,
                                               const float* __restrict__ x,
                                               float* __restrict__ out) {
    __shared__ GemmSmem64 gs;
    int tid = threadIdx.x;
    int warp = tid >> 5, c = tid & 31;
    int wr = warp & 3, wn = warp >> 2;
    int bm0 = blockIdx.x * 64;
    int c0 = blockIdx.y * 32;

    float cc[2][4];
    #pragma unroll
    for (int nt = 0; nt < 2; ++nt)
        #pragma unroll
        for (int q = 0; q < 4; ++q) cc[nt][q] = 0.f;

    gemm_mainloop64(gs, d_aoh, bm0, d_Wh + 3 * 65536, F, c0, tid, wr, wn, c, cc);

    int r0 = bm0 + wr * 16 + (c >> 2);
    #pragma unroll
    for (int nt = 0; nt < 2; ++nt) {
        int col = c0 + wn * 16 + nt * 8 + 2 * (c & 3);
        float2 bo2 = *(const float2*)&bo[col];
        float2 x0 = *(const float2*)&x[r0 * F + col];
        float2 x1 = *(const float2*)&x[(r0 + 8) * F + col];
        *(float2*)&out[r0 * F + col] =
            make_float2(cc[nt][0] + bo2.x + x0.x, cc[nt][1] + bo2.y + x0.y);
        *(float2*)&out[(r0 + 8) * F + col] =
            make_float2(cc[nt][2] + bo2.x + x1.x, cc[nt][3] + bo2.y + x1.y);
    }
}

// ---------------- launch ----------------
extern "C" void kernel_launch(void* const* d_in, const int* in_sizes, int n_in,
                              void* d_out, int out_size) {
    const float* x     = (const float*)d_in[0];
    const int*   adj   = (const int*)d_in[1];
    const float* Wq    = (const float*)d_in[2];
    const float* Wk    = (const float*)d_in[3];
    const float* Wv    = (const float*)d_in[4];
    const float* a     = (const float*)d_in[5];
    const float* Wo    = (const float*)d_in[6];
    const float* bo    = (const float*)d_in[7];
    const float* gamma = (const float*)d_in[8];
    const float* beta  = (const float*)d_in[9];
    float* out = (float*)d_out;

    cudaFuncSetAttribute(attn_kernel, cudaFuncAttributeMaxDynamicSharedMemorySize,
                         (int)sizeof(AttnSmem));

    prep_kernel<<<PACK_BLOCKS + LN_BLOCKS + WCONV_BLOCKS, 256>>>(
        adj, a, x, gamma, beta, Wq, Wk, Wv, Wo);
    qkv_mma<<<dim3(N_NODES / 64, 24), 256>>>(a);
    attn_kernel<<<dim3(N_NODES / BI, H), 256, sizeof(AttnSmem)>>>();
    out_mma<<<dim3(N_NODES / 64, F / 32), 256>>>(bo, x, out);
}